// round 5
// baseline (speedup 1.0000x reference)
#include <cuda_runtime.h>
#include <cstdint>

#define NPTS 32768
#define DH 32
#define NH 8
#define NC 3
#define BSZ 128
#define NBK 256
#define CHN 24          // NC*NH
#define QSTR 36         // padded row stride for 35-dim hat vectors

typedef unsigned long long ull;

// ---------------- scratch (static device globals; no allocations) ----------------
__device__ float g_qhat[(size_t)NH * NPTS * QSTR];
__device__ float g_khat[(size_t)NH * NPTS * QSTR];
__device__ float g_v[(size_t)NH * NPTS * DH];
__device__ float g_qh[(size_t)CHN * NPTS];
__device__ float g_kh[(size_t)CHN * NPTS];
__device__ ull   g_keys[(size_t)2 * CHN * NPTS];
__device__ ull   g_keys2[(size_t)2 * CHN * NPTS];
__device__ unsigned g_mn[CHN], g_mx[CHN];
__device__ float g_sqrtw[NH * 3];
__device__ float g_oscr[(size_t)CHN * NPTS * DH];
__device__ float g_dscr[(size_t)CHN * NPTS];

// ---------------- f32x2 packed helpers ----------------
__device__ __forceinline__ ull pk2(float a, float b) {
    ull r; asm("mov.b64 %0, {%1, %2};" : "=l"(r) : "f"(a), "f"(b)); return r;
}
__device__ __forceinline__ void upk(ull p, float& a, float& b) {
    asm("mov.b64 {%0, %1}, %2;" : "=f"(a), "=f"(b) : "l"(p));
}
__device__ __forceinline__ ull f2fma(ull a, ull b, ull c) {
    ull d; asm("fma.rn.f32x2 %0, %1, %2, %3;" : "=l"(d) : "l"(a), "l"(b), "l"(c)); return d;
}
__device__ __forceinline__ ull f2add(ull a, ull b) {
    ull d; asm("add.rn.f32x2 %0, %1, %2;" : "=l"(d) : "l"(a), "l"(b)); return d;
}
__device__ __forceinline__ ull lo2(float4 v) { return pk2(v.x, v.y); }
__device__ __forceinline__ ull hi2(float4 v) { return pk2(v.z, v.w); }

// ---------------- sort helpers ----------------
__device__ __forceinline__ unsigned encf(float f) {
    unsigned u = __float_as_uint(f);
    return (u & 0x80000000u) ? ~u : (u | 0x80000000u);
}
__device__ __forceinline__ float decf(unsigned u) {
    return (u & 0x80000000u) ? __uint_as_float(u ^ 0x80000000u)
                             : __uint_as_float(~u);
}

// scalar fast exp; clamped, rel err ~1e-7
__device__ __forceinline__ float fexp(float x) {
    x = fminf(fmaxf(x, -87.0f), 87.0f);
    float t = fmaf(x, 1.4426950408889634f, 12582912.0f);
    float j = t - 12582912.0f;
    float f = fmaf(j, -0.693145751953125f, x);
    f = fmaf(j, -1.4286067653301938e-6f, f);
    float p = 1.3888889e-3f;
    p = fmaf(p, f, 8.3333333e-3f);
    p = fmaf(p, f, 4.1666667e-2f);
    p = fmaf(p, f, 1.6666667e-1f);
    p = fmaf(p, f, 0.5f);
    p = fmaf(p, f, 1.0f);
    p = fmaf(p, f, 1.0f);
    return __int_as_float(__float_as_int(p) + (__float_as_int(t) << 23));
}

// packed exp for x <= ~0; underflow-guarded
__device__ __forceinline__ void fexp2p(ull x2, float& e0, float& e1) {
    const ull L2E = pk2(1.4426950408889634f, 1.4426950408889634f);
    const ull MAG = pk2(12582912.0f, 12582912.0f);
    const ull NMAG = pk2(-12582912.0f, -12582912.0f);
    ull t2 = f2fma(x2, L2E, MAG);
    ull j2 = f2add(t2, NMAG);
    ull f2 = f2fma(j2, pk2(-0.693145751953125f, -0.693145751953125f), x2);
    f2 = f2fma(j2, pk2(-1.4286067653301938e-6f, -1.4286067653301938e-6f), f2);
    ull p = pk2(1.3888889e-3f, 1.3888889e-3f);
    p = f2fma(p, f2, pk2(8.3333333e-3f, 8.3333333e-3f));
    p = f2fma(p, f2, pk2(4.1666667e-2f, 4.1666667e-2f));
    p = f2fma(p, f2, pk2(1.6666667e-1f, 1.6666667e-1f));
    p = f2fma(p, f2, pk2(0.5f, 0.5f));
    p = f2fma(p, f2, pk2(1.0f, 1.0f));
    p = f2fma(p, f2, pk2(1.0f, 1.0f));
    float p0, p1, t0, t1;
    upk(p, p0, p1); upk(t2, t0, t1);
    float r0 = __int_as_float(__float_as_int(p0) + (__float_as_int(t0) << 23));
    float r1 = __int_as_float(__float_as_int(p1) + (__float_as_int(t1) << 23));
    e0 = (t0 < 12582792.0f) ? 0.0f : r0;
    e1 = (t1 < 12582792.0f) ? 0.0f : r1;
}

// ---------------- kernel 1: LayerNorm + QKV projection (+prep fold) ----------------
__global__ void __launch_bounds__(768) k_ln_qkv(
    const float* __restrict__ x, const float* __restrict__ n1w,
    const float* __restrict__ n1b, const float* __restrict__ wq,
    const float* __restrict__ wk, const float* __restrict__ wv,
    const float* __restrict__ wr) {
    __shared__ float xs[128 * QSTR];
    int base = blockIdx.x * 128;
    int tid = threadIdx.x;
    if (blockIdx.x == 0 && tid < CHN) {        // folded k_prep
        g_mn[tid] = 0xFFFFFFFFu;
        g_mx[tid] = 0u;
        int h = tid / 3, r = tid % 3;
        float qw = 0.f;
        for (int k = 0; k < 8; k++) {
            float s = 0.f;
            for (int d = 0; d < 32; d++) s += wr[(h * 32 + d) * 24 + r * 8 + k];
            qw += expf(fminf(s, 50.f));
        }
        g_sqrtw[tid] = sqrtf(2.f * qw);
    }
    if (tid < 128) {
        int n = base + tid;
        float r[32];
        const float4* xr = (const float4*)(x + (size_t)n * 32);
#pragma unroll
        for (int u = 0; u < 8; u++) {
            float4 v4 = xr[u];
            r[4 * u] = v4.x; r[4 * u + 1] = v4.y; r[4 * u + 2] = v4.z; r[4 * u + 3] = v4.w;
        }
        float mu = 0.f;
#pragma unroll
        for (int d = 0; d < 32; d++) mu += r[d];
        mu *= (1.0f / 32.0f);
        float var = 0.f;
#pragma unroll
        for (int d = 0; d < 32; d++) { float dd = r[d] - mu; var += dd * dd; }
        var *= (1.0f / 32.0f);
        float rs = rsqrtf(var + 1e-5f);
#pragma unroll
        for (int d = 0; d < 32; d++)
            xs[tid * QSTR + d] = (r[d] - mu) * rs * n1w[d] + n1b[d];
    }
    __syncthreads();
    int j = tid;
    int proj = j >> 8, jj = j & 255;
    const float* W = (proj == 0) ? wq : (proj == 1) ? wk : wv;
    ull wpk[16];
#pragma unroll
    for (int d = 0; d < 16; d++)
        wpk[d] = pk2(W[(2 * d) * 256 + jj], W[(2 * d + 1) * 256 + jj]);
    int h = jj >> 5, d0 = jj & 31;
    float* dst;
    int stride;
    if (proj == 0) { dst = g_qhat; stride = QSTR; }
    else if (proj == 1) { dst = g_khat; stride = QSTR; }
    else { dst = g_v; stride = DH; }
    for (int r = 0; r < 128; r++) {
        const float4* xr = (const float4*)(xs + r * QSTR);
        ull a0 = 0, a1 = 0;
#pragma unroll
        for (int u = 0; u < 8; u++) {
            float4 v4 = xr[u];
            a0 = f2fma(lo2(v4), wpk[2 * u], a0);
            a1 = f2fma(hi2(v4), wpk[2 * u + 1], a1);
        }
        float s0, s1;
        upk(f2add(a0, a1), s0, s1);
        dst[((size_t)h * NPTS + (base + r)) * stride + d0] = s0 + s1;
    }
}

// ---------------- kernel 2: hat tails + LSH hashes + min/max ----------------
__global__ void k_hash(const float* __restrict__ coords, const float* __restrict__ alpha) {
    int h = blockIdx.y;
    int n = blockIdx.x * 256 + threadIdx.x;
    float q[36], kk[36];
    float* qrow = g_qhat + ((size_t)h * NPTS + n) * QSTR;
    float* krow = g_khat + ((size_t)h * NPTS + n) * QSTR;
#pragma unroll
    for (int u = 0; u < 8; u++) {
        ((float4*)q)[u] = ((const float4*)qrow)[u];
        ((float4*)kk)[u] = ((const float4*)krow)[u];
    }
#pragma unroll
    for (int r = 0; r < 3; r++) {
        float sr = g_sqrtw[h * 3 + r] * coords[n * 3 + r];
        q[32 + r] = sr; kk[32 + r] = sr;
        qrow[32 + r] = sr; krow[32 + r] = sr;
    }
    qrow[35] = 0.f; krow[35] = 0.f;               // zero pad element
    float qh[3] = {0.f, 0.f, 0.f}, kh[3] = {0.f, 0.f, 0.f};
    const float* al = alpha + h * 105;
#pragma unroll 5
    for (int d = 0; d < 35; d++) {
        float a0 = al[d * 3 + 0], a1 = al[d * 3 + 1], a2 = al[d * 3 + 2];
        qh[0] += q[d] * a0; qh[1] += q[d] * a1; qh[2] += q[d] * a2;
        kh[0] += kk[d] * a0; kh[1] += kk[d] * a1; kh[2] += kk[d] * a2;
    }
#pragma unroll
    for (int c = 0; c < 3; c++) {
        g_qh[(size_t)(c * 8 + h) * NPTS + n] = qh[c];
        g_kh[(size_t)(c * 8 + h) * NPTS + n] = kh[c];
        float mn = fminf(qh[c], kh[c]);
        float mx = fmaxf(qh[c], kh[c]);
#pragma unroll
        for (int o = 16; o > 0; o >>= 1) {
            mn = fminf(mn, __shfl_xor_sync(0xFFFFFFFFu, mn, o));
            mx = fmaxf(mx, __shfl_xor_sync(0xFFFFFFFFu, mx, o));
        }
        if ((threadIdx.x & 31) == 0) {
            atomicMin(&g_mn[c * 8 + h], encf(mn));
            atomicMax(&g_mx[c * 8 + h], encf(mx));
        }
    }
}

// ---------------- local bitonic sort of 4096-elem chunks + fused key build ----------------
template<int J>
__device__ __forceinline__ void shflp8(ull* r, int ibase, int l, int k_) {
#pragma unroll
    for (int s = 0; s < 8; s++) {
        int i = ibase + s * 32;
        bool up = ((i & k_) == 0);
        ull o = __shfl_xor_sync(0xFFFFFFFFu, r[s], J);
        bool kmin = (((l & J) == 0) == up);
        ull lo_ = (r[s] < o) ? r[s] : o;
        ull hi_ = (r[s] < o) ? o : r[s];
        r[s] = kmin ? lo_ : hi_;
    }
}
template<int JS>   // slot-pair pass, J = JS*32
__device__ __forceinline__ void slotp8(ull* r, int ibase, int k_) {
#pragma unroll
    for (int s = 0; s < 8; s++) {
        if (!(s & JS)) {
            int sp = s | JS;
            int i = ibase + s * 32;
            bool up = ((i & k_) == 0);
            if ((r[s] > r[sp]) == up) { ull t2 = r[s]; r[s] = r[sp]; r[sp] = t2; }
        }
    }
}
__device__ __forceinline__ void regpasses8(ull* r, int ibase, int l, int k_) {
    int half = k_ >> 1;
    if (half >= 128) slotp8<4>(r, ibase, k_);
    if (half >= 64)  slotp8<2>(r, ibase, k_);
    if (half >= 32)  slotp8<1>(r, ibase, k_);
    if (half >= 16)  shflp8<16>(r, ibase, l, k_);
    if (half >= 8)   shflp8<8>(r, ibase, l, k_);
    if (half >= 4)   shflp8<4>(r, ibase, l, k_);
    if (half >= 2)   shflp8<2>(r, ibase, l, k_);
    shflp8<1>(r, ibase, l, k_);
}
__device__ __forceinline__ void smem_pass4k(ull* s, int k_, int j_, int tid) {
#pragma unroll
    for (int p = 0; p < 4; p++) {
        int t = tid + p * 512;
        int i = ((t & ~(j_ - 1)) << 1) | (t & (j_ - 1));
        bool up = ((i & k_) == 0);
        ull a = s[i], b = s[i + j_];
        if ((a > b) == up) { s[i] = b; s[i + j_] = a; }
    }
}

__global__ void __launch_bounds__(512) k_sort_local4k(const int* __restrict__ shifts) {
    __shared__ ull s[4096];
    size_t base = (size_t)blockIdx.x * 4096;
    int tid = threadIdx.x;
    int w = tid >> 5, l = tid & 31;
    int ibase = w * 256 + l;

    // fused key build: chunk lies in one (half, segment)
    bool isQ = (base < (size_t)CHN * NPTS);
    size_t hoff = isQ ? base : base - (size_t)CHN * NPTS;
    int seg = (int)(hoff >> 15);
    float hsv = decf(g_mx[seg]) - decf(g_mn[seg]);
    const float* hsrc = isQ ? g_qh : g_kh;
    ull r[8];
#pragma unroll
    for (int s_ = 0; s_ < 8; s_++) {
        size_t t = hoff + ibase + s_ * 32;
        float off = __fmul_rn((float)shifts[t], hsv);
        r[s_] = ((ull)encf(__fadd_rn(hsrc[t], off)) << 32) | (unsigned)(t & (NPTS - 1));
    }

    for (int k_ = 2; k_ <= 256; k_ <<= 1) regpasses8(r, ibase, l, k_);

    for (int k_ = 512; k_ <= 4096; k_ <<= 1) {
#pragma unroll
        for (int s_ = 0; s_ < 8; s_++) s[ibase + s_ * 32] = r[s_];
        __syncthreads();
        for (int j_ = k_ >> 1; j_ >= 256; j_ >>= 1) {
            smem_pass4k(s, k_, j_, tid);
            __syncthreads();
        }
#pragma unroll
        for (int s_ = 0; s_ < 8; s_++) r[s_] = s[ibase + s_ * 32];
        __syncthreads();
        regpasses8(r, ibase, l, k_);
    }
#pragma unroll
    for (int s_ = 0; s_ < 8; s_++) g_keys[base + ibase + s_ * 32] = r[s_];
}

// ---------------- merge-path merge pass: runs of L -> 2L ----------------
__global__ void __launch_bounds__(256) k_mergepath(int L, int dir) {
    const ull* __restrict__ src = dir ? g_keys2 : g_keys;
    ull* __restrict__ dst = dir ? g_keys : g_keys2;
    size_t outbase = (size_t)blockIdx.x * 4096 + (size_t)threadIdx.x * 16;
    size_t pairBase = outbase & ~((size_t)(2 * L) - 1);
    const ull* A = src + pairBase;
    const ull* B = A + L;
    int p0 = (int)(outbase - pairBase);
    int lo = p0 > L ? p0 - L : 0;
    int hi = p0 < L ? p0 : L;
    while (lo < hi) {
        int m = (lo + hi) >> 1;
        if (A[m] <= B[p0 - 1 - m]) lo = m + 1; else hi = m;
    }
    int i = lo, j = p0 - lo;
    ull* d = dst + pairBase + p0;
    ull a = (i < L) ? A[i] : ~0ull;
    ull b = (j < L) ? B[j] : ~0ull;
#pragma unroll
    for (int t = 0; t < 16; t++) {
        bool takeA = (a <= b);
        d[t] = takeA ? a : b;
        if (takeA) { i++; a = (i < L) ? A[i] : ~0ull; }
        else       { j++; b = (j < L) ? B[j] : ~0ull; }
    }
}

// ---------------- kernel 5: bucketed attention (2 buckets/block, 2 q/thread) ----------------
// reads final sorted keys from g_keys2; streams K/V rows (low reg pressure)
__global__ void __launch_bounds__(128, 3) k_attn() {
    extern __shared__ float sm[];
    float* ks = sm;                    // [2][128][36]
    float* vs = sm + 9216;             // [2][128][32]
    float* ksq = sm + 9216 + 8192;     // [2][128]
    int seg = blockIdx.y;
    int h = seg & 7;
    int t = threadIdx.x;
    int tb = t >> 6, tq = t & 63;
    int bucket = blockIdx.x * 2 + tb;

    const ull* kkey = g_keys2 + ((size_t)(CHN + seg)) * NPTS + bucket * BSZ;
    const ull* qkey = g_keys2 + (size_t)seg * NPTS + bucket * BSZ;

#pragma unroll
    for (int rr = 0; rr < 2; rr++) {
        int row = tq + rr * 64;
        unsigned kidx = (unsigned)kkey[row];
        const float4* kr = (const float4*)(g_khat + ((size_t)h * NPTS + kidx) * QSTR);
        float tmp[36];
#pragma unroll
        for (int u = 0; u < 9; u++) ((float4*)tmp)[u] = kr[u];
        float s2 = 0.f;
#pragma unroll
        for (int d = 0; d < 35; d++) s2 += tmp[d] * tmp[d];
        ksq[tb * 128 + row] = -0.5f * s2;
        float* kd = ks + (tb * 128 + row) * 36;
#pragma unroll
        for (int u = 0; u < 9; u++) ((float4*)kd)[u] = ((float4*)tmp)[u];
        const float4* vr = (const float4*)(g_v + ((size_t)h * NPTS + kidx) * DH);
        float* vd = vs + (tb * 128 + row) * 32;
#pragma unroll
        for (int u = 0; u < 8; u++) ((float4*)vd)[u] = vr[u];
    }

    unsigned qidxA = (unsigned)qkey[tq];
    unsigned qidxB = (unsigned)qkey[tq + 64];
    ull qAp[18], qBp[18];
    {
        const float4* qr = (const float4*)(g_qhat + ((size_t)h * NPTS + qidxA) * QSTR);
#pragma unroll
        for (int u = 0; u < 9; u++) ((float4*)qAp)[u] = qr[u];
        const float4* qr2 = (const float4*)(g_qhat + ((size_t)h * NPTS + qidxB) * QSTR);
#pragma unroll
        for (int u = 0; u < 9; u++) ((float4*)qBp)[u] = qr2[u];
    }
    float qsqA = 0.f, qsqB = 0.f;
#pragma unroll
    for (int d = 0; d < 35; d++) {
        qsqA += ((float*)qAp)[d] * ((float*)qAp)[d];
        qsqB += ((float*)qBp)[d] * ((float*)qBp)[d];
    }
    qsqA *= -0.5f; qsqB *= -0.5f;

    ull accA[16], accB[16];
#pragma unroll
    for (int p = 0; p < 16; p++) { accA[p] = 0ull; accB[p] = 0ull; }
    float denA = 0.f, denB = 0.f;
    __syncthreads();

    const float* ksb = ks + tb * 128 * 36;
    const float* vsb = vs + tb * 128 * 32;
    const float* ksqb = ksq + tb * 128;
    for (int j = 0; j < BSZ; j++) {
        const float4* krow = (const float4*)(ksb + j * 36);
        ull dA0 = 0ull, dA1 = 0ull, dB0 = 0ull, dB1 = 0ull;
#pragma unroll
        for (int u = 0; u < 9; u++) {
            float4 cc = krow[u];                 // streamed, 4-reg temp
            ull cl = lo2(cc), ch = hi2(cc);
            dA0 = f2fma(qAp[2 * u], cl, dA0);
            dA1 = f2fma(qAp[2 * u + 1], ch, dA1);
            dB0 = f2fma(qBp[2 * u], cl, dB0);
            dB1 = f2fma(qBp[2 * u + 1], ch, dB1);
        }
        float ksqv = ksqb[j];
        float a0, a1, b0, b1;
        upk(f2add(dA0, dA1), a0, a1);
        upk(f2add(dB0, dB1), b0, b1);
        float sA = a0 + a1 + qsqA + ksqv;
        float sB = b0 + b1 + qsqB + ksqv;
        float eA, eB;
        fexp2p(pk2(sA, sB), eA, eB);
        denA += eA; denB += eB;
        ull eAd = pk2(eA, eA), eBd = pk2(eB, eB);
        const float4* vrow = (const float4*)(vsb + j * 32);
#pragma unroll
        for (int p = 0; p < 8; p++) {
            float4 vv = vrow[p];                 // streamed, shared by A and B
            ull vl = lo2(vv), vh = hi2(vv);
            accA[2 * p] = f2fma(eAd, vl, accA[2 * p]);
            accA[2 * p + 1] = f2fma(eAd, vh, accA[2 * p + 1]);
            accB[2 * p] = f2fma(eBd, vl, accB[2 * p]);
            accB[2 * p + 1] = f2fma(eBd, vh, accB[2 * p + 1]);
        }
    }
    float* odA = g_oscr + ((size_t)seg * NPTS + qidxA) * DH;
    float* odB = g_oscr + ((size_t)seg * NPTS + qidxB) * DH;
#pragma unroll
    for (int p = 0; p < 8; p++) {
        float o0, o1, o2, o3;
        upk(accA[2 * p], o0, o1); upk(accA[2 * p + 1], o2, o3);
        ((float4*)odA)[p] = make_float4(o0, o1, o2, o3);
    }
#pragma unroll
    for (int p = 0; p < 8; p++) {
        float o0, o1, o2, o3;
        upk(accB[2 * p], o0, o1); upk(accB[2 * p + 1], o2, o3);
        ((float4*)odB)[p] = make_float4(o0, o1, o2, o3);
    }
    g_dscr[(size_t)seg * NPTS + qidxA] = denA;
    g_dscr[(size_t)seg * NPTS + qidxB] = denB;
}

// ---------------- kernel 7: combine + out-proj + residual + LN2 + FF + residual ----------------
__global__ void __launch_bounds__(128) k_epilogue(
    const float* __restrict__ x, const float* __restrict__ ow,
    const float* __restrict__ ob, const float* __restrict__ n2w,
    const float* __restrict__ n2b, const float* __restrict__ f1w,
    const float* __restrict__ f1b, const float* __restrict__ f2w,
    const float* __restrict__ f2b, float* __restrict__ out) {
    __shared__ float ws[256 * 32];
    __shared__ float f1sT[32 * 32];
    __shared__ float f2s[32 * 32];
    __shared__ float cs[32 * 5];
    int tid = threadIdx.x;
    for (int i = tid; i < 8192; i += 128) ws[i] = ow[i];
    for (int i = tid; i < 1024; i += 128) {
        f1sT[(i & 31) * 32 + (i >> 5)] = f1w[i];
        f2s[i] = f2w[i];
    }
    if (tid < 32) {
        cs[tid] = ob[tid]; cs[32 + tid] = n2w[tid]; cs[64 + tid] = n2b[tid];
        cs[96 + tid] = f1b[tid]; cs[128 + tid] = f2b[tid];
    }
    __syncthreads();
    int n = blockIdx.x * 128 + tid;

    ull acc2[16];
#pragma unroll
    for (int p = 0; p < 16; p++) acc2[p] = pk2(cs[2 * p], cs[2 * p + 1]);

    // fused combine: per head, normalize 3-hash partials then feed out-proj
#pragma unroll 1
    for (int h = 0; h < 8; h++) {
        float den = g_dscr[(size_t)h * NPTS + n] +
                    g_dscr[(size_t)(8 + h) * NPTS + n] +
                    g_dscr[(size_t)(16 + h) * NPTS + n] + 3e-20f;
        float inv = 1.0f / den;
        const float4* oa = (const float4*)(g_oscr + ((size_t)h * NPTS + n) * DH);
        const float4* obp = (const float4*)(g_oscr + ((size_t)(8 + h) * NPTS + n) * DH);
        const float4* oc = (const float4*)(g_oscr + ((size_t)(16 + h) * NPTS + n) * DH);
#pragma unroll
        for (int p4 = 0; p4 < 8; p4++) {
            float4 a4 = oa[p4], b4 = obp[p4], c4 = oc[p4];
            float av[4];
            av[0] = (a4.x + b4.x + c4.x) * inv;
            av[1] = (a4.y + b4.y + c4.y) * inv;
            av[2] = (a4.z + b4.z + c4.z) * inv;
            av[3] = (a4.w + b4.w + c4.w) * inv;
            int j0 = h * 32 + p4 * 4;
#pragma unroll
            for (int u = 0; u < 4; u++) {
                ull ad = pk2(av[u], av[u]);
                const float4* wr2 = (const float4*)(ws + (j0 + u) * 32);
#pragma unroll
                for (int p = 0; p < 8; p++) {
                    float4 w4 = wr2[p];
                    acc2[2 * p] = f2fma(ad, lo2(w4), acc2[2 * p]);
                    acc2[2 * p + 1] = f2fma(ad, hi2(w4), acc2[2 * p + 1]);
                }
            }
        }
    }
    float acc[32];
#pragma unroll
    for (int p = 0; p < 16; p++) upk(acc2[p], acc[2 * p], acc[2 * p + 1]);

    float x2[32];
    const float4* xr = (const float4*)(x + (size_t)n * 32);
#pragma unroll
    for (int u = 0; u < 8; u++) {
        float4 xv = xr[u];
        x2[4 * u] = xv.x + acc[4 * u];
        x2[4 * u + 1] = xv.y + acc[4 * u + 1];
        x2[4 * u + 2] = xv.z + acc[4 * u + 2];
        x2[4 * u + 3] = xv.w + acc[4 * u + 3];
    }
    float mu = 0.f;
#pragma unroll
    for (int d = 0; d < 32; d++) mu += x2[d];
    mu *= (1.0f / 32.0f);
    float var = 0.f;
#pragma unroll
    for (int d = 0; d < 32; d++) { float dd = x2[d] - mu; var += dd * dd; }
    var *= (1.0f / 32.0f);
    float rs = rsqrtf(var + 1e-5f);
    float xn2[32];
#pragma unroll
    for (int d = 0; d < 32; d++)
        xn2[d] = (x2[d] - mu) * rs * cs[32 + d] + cs[64 + d];
    ull xp[16];
#pragma unroll
    for (int u = 0; u < 16; u++) xp[u] = pk2(xn2[2 * u], xn2[2 * u + 1]);
    float h1[32];
#pragma unroll 4
    for (int jj = 0; jj < 32; jj++) {
        const float4* fr = (const float4*)(f1sT + jj * 32);
        ull a0 = 0ull, a1 = 0ull;
#pragma unroll
        for (int u = 0; u < 8; u++) {
            float4 v4 = fr[u];
            a0 = f2fma(lo2(v4), xp[2 * u], a0);
            a1 = f2fma(hi2(v4), xp[2 * u + 1], a1);
        }
        float s0, s1;
        upk(f2add(a0, a1), s0, s1);
        float t2 = cs[96 + jj] + s0 + s1;
        h1[jj] = t2 / (1.0f + fexp(-t2));
    }
    ull o2[16];
#pragma unroll
    for (int p = 0; p < 16; p++) o2[p] = pk2(cs[128 + 2 * p], cs[128 + 2 * p + 1]);
#pragma unroll 4
    for (int jj = 0; jj < 32; jj++) {
        ull hd = pk2(h1[jj], h1[jj]);
        const float4* fr = (const float4*)(f2s + jj * 32);
#pragma unroll
        for (int p = 0; p < 8; p++) {
            float4 v4 = fr[p];
            o2[2 * p] = f2fma(hd, lo2(v4), o2[2 * p]);
            o2[2 * p + 1] = f2fma(hd, hi2(v4), o2[2 * p + 1]);
        }
    }
    float o[32];
#pragma unroll
    for (int p = 0; p < 16; p++) upk(o2[p], o[2 * p], o[2 * p + 1]);
    float4* orow = (float4*)(out + (size_t)n * 32);
#pragma unroll
    for (int u = 0; u < 8; u++)
        orow[u] = make_float4(x2[4 * u] + o[4 * u], x2[4 * u + 1] + o[4 * u + 1],
                              x2[4 * u + 2] + o[4 * u + 2], x2[4 * u + 3] + o[4 * u + 3]);
}

// ---------------- launcher ----------------
extern "C" void kernel_launch(void* const* d_in, const int* in_sizes, int n_in,
                              void* d_out, int out_size) {
    const float* x = (const float*)d_in[0];
    const float* coords = (const float*)d_in[1];
    const int* shifts = (const int*)d_in[2];
    const float* n1w = (const float*)d_in[3];
    const float* n1b = (const float*)d_in[4];
    const float* wq = (const float*)d_in[5];
    const float* wk = (const float*)d_in[6];
    const float* wv = (const float*)d_in[7];
    const float* wr = (const float*)d_in[8];
    const float* alpha = (const float*)d_in[9];
    const float* ow = (const float*)d_in[10];
    const float* ob = (const float*)d_in[11];
    const float* n2w = (const float*)d_in[12];
    const float* n2b = (const float*)d_in[13];
    const float* f1w = (const float*)d_in[14];
    const float* f1b = (const float*)d_in[15];
    const float* f2w = (const float*)d_in[16];
    const float* f2b = (const float*)d_in[17];
    float* out = (float*)d_out;

    cudaFuncSetAttribute(k_attn, cudaFuncAttributeMaxDynamicSharedMemorySize, 71680);

    k_ln_qkv<<<NPTS / 128, 768>>>(x, n1w, n1b, wq, wk, wv, wr);
    k_hash<<<dim3(NPTS / 256, NH), 256>>>(coords, alpha);

    const int TOT = 2 * CHN * NPTS;
    k_sort_local4k<<<TOT / 4096, 512>>>(shifts);   // keys fused in
    k_mergepath<<<TOT / 4096, 256>>>(4096, 0);
    k_mergepath<<<TOT / 4096, 256>>>(8192, 1);
    k_mergepath<<<TOT / 4096, 256>>>(16384, 0);

    k_attn<<<dim3(NBK / 2, CHN), 128, 71680>>>();
    k_epilogue<<<NPTS / 128, 128>>>(x, ow, ob, n2w, n2b, f1w, f1b, f2w, f2b, out);
}

// round 6
// speedup vs baseline: 1.1146x; 1.1146x over previous
#include <cuda_runtime.h>
#include <cstdint>

#define NPTS 32768
#define DH 32
#define NH 8
#define NC 3
#define BSZ 128
#define NBK 256
#define CHN 24          // NC*NH
#define QSTR 36         // padded row stride for 35-dim hat vectors

typedef unsigned long long ull;

// ---------------- scratch (static device globals; no allocations) ----------------
__device__ float g_qhat[(size_t)NH * NPTS * QSTR];
__device__ float g_khat[(size_t)NH * NPTS * QSTR];
__device__ float g_v[(size_t)NH * NPTS * DH];
__device__ float g_qh[(size_t)CHN * NPTS];
__device__ float g_kh[(size_t)CHN * NPTS];
__device__ ull   g_keys[(size_t)2 * CHN * NPTS];
__device__ ull   g_keys2[(size_t)2 * CHN * NPTS];
__device__ unsigned g_mn[CHN], g_mx[CHN];
__device__ float g_sqrtw[NH * 3];
__device__ float g_oscr[(size_t)CHN * NPTS * DH];
__device__ float g_dscr[(size_t)CHN * NPTS];

// ---------------- f32x2 packed helpers ----------------
__device__ __forceinline__ ull pk2(float a, float b) {
    ull r; asm("mov.b64 %0, {%1, %2};" : "=l"(r) : "f"(a), "f"(b)); return r;
}
__device__ __forceinline__ void upk(ull p, float& a, float& b) {
    asm("mov.b64 {%0, %1}, %2;" : "=f"(a), "=f"(b) : "l"(p));
}
__device__ __forceinline__ ull f2fma(ull a, ull b, ull c) {
    ull d; asm("fma.rn.f32x2 %0, %1, %2, %3;" : "=l"(d) : "l"(a), "l"(b), "l"(c)); return d;
}
__device__ __forceinline__ ull f2add(ull a, ull b) {
    ull d; asm("add.rn.f32x2 %0, %1, %2;" : "=l"(d) : "l"(a), "l"(b)); return d;
}
__device__ __forceinline__ ull lo2(float4 v) { return pk2(v.x, v.y); }
__device__ __forceinline__ ull hi2(float4 v) { return pk2(v.z, v.w); }

// ---------------- sort helpers ----------------
__device__ __forceinline__ unsigned encf(float f) {
    unsigned u = __float_as_uint(f);
    return (u & 0x80000000u) ? ~u : (u | 0x80000000u);
}
__device__ __forceinline__ float decf(unsigned u) {
    return (u & 0x80000000u) ? __uint_as_float(u ^ 0x80000000u)
                             : __uint_as_float(~u);
}

// scalar fast exp; clamped, rel err ~1e-7
__device__ __forceinline__ float fexp(float x) {
    x = fminf(fmaxf(x, -87.0f), 87.0f);
    float t = fmaf(x, 1.4426950408889634f, 12582912.0f);
    float j = t - 12582912.0f;
    float f = fmaf(j, -0.693145751953125f, x);
    f = fmaf(j, -1.4286067653301938e-6f, f);
    float p = 1.3888889e-3f;
    p = fmaf(p, f, 8.3333333e-3f);
    p = fmaf(p, f, 4.1666667e-2f);
    p = fmaf(p, f, 1.6666667e-1f);
    p = fmaf(p, f, 0.5f);
    p = fmaf(p, f, 1.0f);
    p = fmaf(p, f, 1.0f);
    return __int_as_float(__float_as_int(p) + (__float_as_int(t) << 23));
}

// packed exp for x <= ~0; underflow-guarded
__device__ __forceinline__ void fexp2p(ull x2, float& e0, float& e1) {
    const ull L2E = pk2(1.4426950408889634f, 1.4426950408889634f);
    const ull MAG = pk2(12582912.0f, 12582912.0f);
    const ull NMAG = pk2(-12582912.0f, -12582912.0f);
    ull t2 = f2fma(x2, L2E, MAG);
    ull j2 = f2add(t2, NMAG);
    ull f2 = f2fma(j2, pk2(-0.693145751953125f, -0.693145751953125f), x2);
    f2 = f2fma(j2, pk2(-1.4286067653301938e-6f, -1.4286067653301938e-6f), f2);
    ull p = pk2(1.3888889e-3f, 1.3888889e-3f);
    p = f2fma(p, f2, pk2(8.3333333e-3f, 8.3333333e-3f));
    p = f2fma(p, f2, pk2(4.1666667e-2f, 4.1666667e-2f));
    p = f2fma(p, f2, pk2(1.6666667e-1f, 1.6666667e-1f));
    p = f2fma(p, f2, pk2(0.5f, 0.5f));
    p = f2fma(p, f2, pk2(1.0f, 1.0f));
    p = f2fma(p, f2, pk2(1.0f, 1.0f));
    float p0, p1, t0, t1;
    upk(p, p0, p1); upk(t2, t0, t1);
    float r0 = __int_as_float(__float_as_int(p0) + (__float_as_int(t0) << 23));
    float r1 = __int_as_float(__float_as_int(p1) + (__float_as_int(t1) << 23));
    e0 = (t0 < 12582792.0f) ? 0.0f : r0;
    e1 = (t1 < 12582792.0f) ? 0.0f : r1;
}

// ---------------- kernel 1: LayerNorm + QKV projection (+prep fold) ----------------
__global__ void __launch_bounds__(768) k_ln_qkv(
    const float* __restrict__ x, const float* __restrict__ n1w,
    const float* __restrict__ n1b, const float* __restrict__ wq,
    const float* __restrict__ wk, const float* __restrict__ wv,
    const float* __restrict__ wr) {
    __shared__ float xs[128 * QSTR];
    int base = blockIdx.x * 128;
    int tid = threadIdx.x;
    if (blockIdx.x == 0 && tid < CHN) {        // folded k_prep
        g_mn[tid] = 0xFFFFFFFFu;
        g_mx[tid] = 0u;
        int h = tid / 3, r = tid % 3;
        float qw = 0.f;
        for (int k = 0; k < 8; k++) {
            float s = 0.f;
            for (int d = 0; d < 32; d++) s += wr[(h * 32 + d) * 24 + r * 8 + k];
            qw += expf(fminf(s, 50.f));
        }
        g_sqrtw[tid] = sqrtf(2.f * qw);
    }
    if (tid < 128) {
        int n = base + tid;
        float r[32];
        const float4* xr = (const float4*)(x + (size_t)n * 32);
#pragma unroll
        for (int u = 0; u < 8; u++) {
            float4 v4 = xr[u];
            r[4 * u] = v4.x; r[4 * u + 1] = v4.y; r[4 * u + 2] = v4.z; r[4 * u + 3] = v4.w;
        }
        float mu = 0.f;
#pragma unroll
        for (int d = 0; d < 32; d++) mu += r[d];
        mu *= (1.0f / 32.0f);
        float var = 0.f;
#pragma unroll
        for (int d = 0; d < 32; d++) { float dd = r[d] - mu; var += dd * dd; }
        var *= (1.0f / 32.0f);
        float rs = rsqrtf(var + 1e-5f);
#pragma unroll
        for (int d = 0; d < 32; d++)
            xs[tid * QSTR + d] = (r[d] - mu) * rs * n1w[d] + n1b[d];
    }
    __syncthreads();
    int j = tid;
    int proj = j >> 8, jj = j & 255;
    const float* W = (proj == 0) ? wq : (proj == 1) ? wk : wv;
    ull wpk[16];
#pragma unroll
    for (int d = 0; d < 16; d++)
        wpk[d] = pk2(W[(2 * d) * 256 + jj], W[(2 * d + 1) * 256 + jj]);
    int h = jj >> 5, d0 = jj & 31;
    float* dst;
    int stride;
    if (proj == 0) { dst = g_qhat; stride = QSTR; }
    else if (proj == 1) { dst = g_khat; stride = QSTR; }
    else { dst = g_v; stride = DH; }
    for (int r = 0; r < 128; r++) {
        const float4* xr = (const float4*)(xs + r * QSTR);
        ull a0 = 0, a1 = 0;
#pragma unroll
        for (int u = 0; u < 8; u++) {
            float4 v4 = xr[u];
            a0 = f2fma(lo2(v4), wpk[2 * u], a0);
            a1 = f2fma(hi2(v4), wpk[2 * u + 1], a1);
        }
        float s0, s1;
        upk(f2add(a0, a1), s0, s1);
        dst[((size_t)h * NPTS + (base + r)) * stride + d0] = s0 + s1;
    }
}

// ---------------- kernel 2: hat tails + LSH hashes + min/max ----------------
__global__ void k_hash(const float* __restrict__ coords, const float* __restrict__ alpha) {
    int h = blockIdx.y;
    int n = blockIdx.x * 256 + threadIdx.x;
    float q[36], kk[36];
    float* qrow = g_qhat + ((size_t)h * NPTS + n) * QSTR;
    float* krow = g_khat + ((size_t)h * NPTS + n) * QSTR;
#pragma unroll
    for (int u = 0; u < 8; u++) {
        ((float4*)q)[u] = ((const float4*)qrow)[u];
        ((float4*)kk)[u] = ((const float4*)krow)[u];
    }
#pragma unroll
    for (int r = 0; r < 3; r++) {
        float sr = g_sqrtw[h * 3 + r] * coords[n * 3 + r];
        q[32 + r] = sr; kk[32 + r] = sr;
        qrow[32 + r] = sr; krow[32 + r] = sr;
    }
    qrow[35] = 0.f; krow[35] = 0.f;               // zero pad element
    float qh[3] = {0.f, 0.f, 0.f}, kh[3] = {0.f, 0.f, 0.f};
    const float* al = alpha + h * 105;
#pragma unroll 5
    for (int d = 0; d < 35; d++) {
        float a0 = al[d * 3 + 0], a1 = al[d * 3 + 1], a2 = al[d * 3 + 2];
        qh[0] += q[d] * a0; qh[1] += q[d] * a1; qh[2] += q[d] * a2;
        kh[0] += kk[d] * a0; kh[1] += kk[d] * a1; kh[2] += kk[d] * a2;
    }
#pragma unroll
    for (int c = 0; c < 3; c++) {
        g_qh[(size_t)(c * 8 + h) * NPTS + n] = qh[c];
        g_kh[(size_t)(c * 8 + h) * NPTS + n] = kh[c];
        float mn = fminf(qh[c], kh[c]);
        float mx = fmaxf(qh[c], kh[c]);
#pragma unroll
        for (int o = 16; o > 0; o >>= 1) {
            mn = fminf(mn, __shfl_xor_sync(0xFFFFFFFFu, mn, o));
            mx = fmaxf(mx, __shfl_xor_sync(0xFFFFFFFFu, mx, o));
        }
        if ((threadIdx.x & 31) == 0) {
            atomicMin(&g_mn[c * 8 + h], encf(mn));
            atomicMax(&g_mx[c * 8 + h], encf(mx));
        }
    }
}

// ---------------- local bitonic sort of 4096-elem chunks + fused key build ----------------
template<int J>
__device__ __forceinline__ void shflp8(ull* r, int ibase, int l, int k_) {
#pragma unroll
    for (int s = 0; s < 8; s++) {
        int i = ibase + s * 32;
        bool up = ((i & k_) == 0);
        ull o = __shfl_xor_sync(0xFFFFFFFFu, r[s], J);
        bool kmin = (((l & J) == 0) == up);
        ull lo_ = (r[s] < o) ? r[s] : o;
        ull hi_ = (r[s] < o) ? o : r[s];
        r[s] = kmin ? lo_ : hi_;
    }
}
template<int JS>   // slot-pair pass, J = JS*32
__device__ __forceinline__ void slotp8(ull* r, int ibase, int k_) {
#pragma unroll
    for (int s = 0; s < 8; s++) {
        if (!(s & JS)) {
            int sp = s | JS;
            int i = ibase + s * 32;
            bool up = ((i & k_) == 0);
            if ((r[s] > r[sp]) == up) { ull t2 = r[s]; r[s] = r[sp]; r[sp] = t2; }
        }
    }
}
__device__ __forceinline__ void regpasses8(ull* r, int ibase, int l, int k_) {
    int half = k_ >> 1;
    if (half >= 128) slotp8<4>(r, ibase, k_);
    if (half >= 64)  slotp8<2>(r, ibase, k_);
    if (half >= 32)  slotp8<1>(r, ibase, k_);
    if (half >= 16)  shflp8<16>(r, ibase, l, k_);
    if (half >= 8)   shflp8<8>(r, ibase, l, k_);
    if (half >= 4)   shflp8<4>(r, ibase, l, k_);
    if (half >= 2)   shflp8<2>(r, ibase, l, k_);
    shflp8<1>(r, ibase, l, k_);
}
__device__ __forceinline__ void smem_pass4k(ull* s, int k_, int j_, int tid) {
#pragma unroll
    for (int p = 0; p < 4; p++) {
        int t = tid + p * 512;
        int i = ((t & ~(j_ - 1)) << 1) | (t & (j_ - 1));
        bool up = ((i & k_) == 0);
        ull a = s[i], b = s[i + j_];
        if ((a > b) == up) { s[i] = b; s[i + j_] = a; }
    }
}

__global__ void __launch_bounds__(512) k_sort_local4k(const int* __restrict__ shifts) {
    __shared__ ull s[4096];
    size_t base = (size_t)blockIdx.x * 4096;
    int tid = threadIdx.x;
    int w = tid >> 5, l = tid & 31;
    int ibase = w * 256 + l;

    bool isQ = (base < (size_t)CHN * NPTS);
    size_t hoff = isQ ? base : base - (size_t)CHN * NPTS;
    int seg = (int)(hoff >> 15);
    float hsv = decf(g_mx[seg]) - decf(g_mn[seg]);
    const float* hsrc = isQ ? g_qh : g_kh;
    ull r[8];
#pragma unroll
    for (int s_ = 0; s_ < 8; s_++) {
        size_t t = hoff + ibase + s_ * 32;
        float off = __fmul_rn((float)shifts[t], hsv);
        r[s_] = ((ull)encf(__fadd_rn(hsrc[t], off)) << 32) | (unsigned)(t & (NPTS - 1));
    }

    for (int k_ = 2; k_ <= 256; k_ <<= 1) regpasses8(r, ibase, l, k_);

    for (int k_ = 512; k_ <= 4096; k_ <<= 1) {
#pragma unroll
        for (int s_ = 0; s_ < 8; s_++) s[ibase + s_ * 32] = r[s_];
        __syncthreads();
        for (int j_ = k_ >> 1; j_ >= 256; j_ >>= 1) {
            smem_pass4k(s, k_, j_, tid);
            __syncthreads();
        }
#pragma unroll
        for (int s_ = 0; s_ < 8; s_++) r[s_] = s[ibase + s_ * 32];
        __syncthreads();
        regpasses8(r, ibase, l, k_);
    }
#pragma unroll
    for (int s_ = 0; s_ < 8; s_++) g_keys[base + ibase + s_ * 32] = r[s_];
}

// ---------------- merge-path pass with smem staging: runs of L -> 2L ----------------
__global__ void __launch_bounds__(256) k_mergepath(int L, int dir) {
    const ull* __restrict__ src = dir ? g_keys2 : g_keys;
    ull* __restrict__ dst = dir ? g_keys : g_keys2;
    __shared__ ull sA[4096];
    __shared__ int sBounds[2];
    size_t outbase = (size_t)blockIdx.x * 4096;
    size_t pairBase = outbase & ~((size_t)(2 * L) - 1);
    const ull* A = src + pairBase;
    const ull* B = A + L;
    int p0 = (int)(outbase - pairBase);
    // two block-level global merge-path searches
    if (threadIdx.x < 2) {
        int p = p0 + (int)threadIdx.x * 4096;
        int lo = p > L ? p - L : 0;
        int hi = p < L ? p : L;
        while (lo < hi) {
            int m = (lo + hi) >> 1;
            if (A[m] <= B[p - 1 - m]) lo = m + 1; else hi = m;
        }
        sBounds[threadIdx.x] = lo;
    }
    __syncthreads();
    int a0 = sBounds[0], a1 = sBounds[1];
    int aCnt = a1 - a0;
    int b0 = p0 - a0;
    int bCnt = 4096 - aCnt;
    // stage windows in smem (coalesced)
    for (int i = threadIdx.x; i < aCnt; i += 256) sA[i] = A[a0 + i];
    ull* sB = sA + aCnt;
    for (int i = threadIdx.x; i < bCnt; i += 256) sB[i] = B[b0 + i];
    __syncthreads();
    // local merge-path in smem
    int p = threadIdx.x * 16;
    int lo = p > bCnt ? p - bCnt : 0;
    int hi = p < aCnt ? p : aCnt;
    while (lo < hi) {
        int m = (lo + hi) >> 1;
        if (sA[m] <= sB[p - 1 - m]) lo = m + 1; else hi = m;
    }
    int i = lo, j = p - lo;
    ull* d = dst + outbase + p;
    ull a = (i < aCnt) ? sA[i] : ~0ull;   // keys never equal ~0 (index < 2^15)
    ull b = (j < bCnt) ? sB[j] : ~0ull;
#pragma unroll
    for (int t = 0; t < 16; t++) {
        bool takeA = (a <= b);
        d[t] = takeA ? a : b;
        if (takeA) { i++; a = (i < aCnt) ? sA[i] : ~0ull; }
        else       { j++; b = (j < bCnt) ? sB[j] : ~0ull; }
    }
}

// ---------------- kernel 5: bucketed attention (256 thr, 2 buckets, 1 q/thread, 2j unroll) ----
__global__ void __launch_bounds__(256, 2) k_attn() {
    extern __shared__ float sm[];
    float* ks = sm;                    // [2][128][36]
    float* vs = sm + 9216;             // [2][128][32]
    float* ksq = sm + 9216 + 8192;     // [2][128]
    int seg = blockIdx.y;
    int h = seg & 7;
    int t = threadIdx.x;
    int tb = t >> 7;                   // bucket half
    int tq = t & 127;                  // q/load row
    int bucket = blockIdx.x * 2 + tb;

    const ull* kkey = g_keys2 + ((size_t)(CHN + seg)) * NPTS + bucket * BSZ;
    const ull* qkey = g_keys2 + (size_t)seg * NPTS + bucket * BSZ;

    // load 1 K row + 1 V row per thread
    {
        unsigned kidx = (unsigned)kkey[tq];
        const float4* kr = (const float4*)(g_khat + ((size_t)h * NPTS + kidx) * QSTR);
        float tmp[36];
#pragma unroll
        for (int u = 0; u < 9; u++) ((float4*)tmp)[u] = kr[u];
        float s2 = 0.f;
#pragma unroll
        for (int d = 0; d < 35; d++) s2 += tmp[d] * tmp[d];
        ksq[tb * 128 + tq] = -0.5f * s2;
        float* kd = ks + (tb * 128 + tq) * 36;
#pragma unroll
        for (int u = 0; u < 9; u++) ((float4*)kd)[u] = ((float4*)tmp)[u];
        const float4* vr = (const float4*)(g_v + ((size_t)h * NPTS + kidx) * DH);
        float* vd = vs + (tb * 128 + tq) * 32;
#pragma unroll
        for (int u = 0; u < 8; u++) ((float4*)vd)[u] = vr[u];
    }

    unsigned qidx = (unsigned)qkey[tq];
    ull qp[18];
    {
        const float4* qr = (const float4*)(g_qhat + ((size_t)h * NPTS + qidx) * QSTR);
#pragma unroll
        for (int u = 0; u < 9; u++) ((float4*)qp)[u] = qr[u];
    }
    float qsq = 0.f;
#pragma unroll
    for (int d = 0; d < 35; d++) qsq += ((float*)qp)[d] * ((float*)qp)[d];
    qsq *= -0.5f;

    ull acc[16];
#pragma unroll
    for (int p = 0; p < 16; p++) acc[p] = 0ull;
    float den = 0.f;
    __syncthreads();

    const float* ksb = ks + tb * 128 * 36;
    const float* vsb = vs + tb * 128 * 32;
    const float* ksqb = ksq + tb * 128;
    for (int j = 0; j < BSZ; j += 2) {
        const float4* k0 = (const float4*)(ksb + j * 36);
        const float4* k1 = (const float4*)(ksb + j * 36 + 36);
        ull d00 = 0ull, d01 = 0ull, d10 = 0ull, d11 = 0ull;
#pragma unroll
        for (int u = 0; u < 9; u++) {
            float4 c0 = k0[u];
            float4 c1 = k1[u];
            d00 = f2fma(qp[2 * u], lo2(c0), d00);
            d01 = f2fma(qp[2 * u + 1], hi2(c0), d01);
            d10 = f2fma(qp[2 * u], lo2(c1), d10);
            d11 = f2fma(qp[2 * u + 1], hi2(c1), d11);
        }
        float a0, a1, b0, b1;
        upk(f2add(d00, d01), a0, a1);
        upk(f2add(d10, d11), b0, b1);
        float2 kq = *(const float2*)&ksqb[j];
        float s0 = a0 + a1 + qsq + kq.x;
        float s1 = b0 + b1 + qsq + kq.y;
        float e0, e1;
        fexp2p(pk2(s0, s1), e0, e1);
        den += e0 + e1;
        ull e0d = pk2(e0, e0), e1d = pk2(e1, e1);
        const float4* v0 = (const float4*)(vsb + j * 32);
        const float4* v1 = (const float4*)(vsb + j * 32 + 32);
#pragma unroll
        for (int p = 0; p < 8; p++) {
            float4 vv0 = v0[p];
            float4 vv1 = v1[p];
            acc[2 * p] = f2fma(e0d, lo2(vv0), acc[2 * p]);
            acc[2 * p + 1] = f2fma(e0d, hi2(vv0), acc[2 * p + 1]);
            acc[2 * p] = f2fma(e1d, lo2(vv1), acc[2 * p]);
            acc[2 * p + 1] = f2fma(e1d, hi2(vv1), acc[2 * p + 1]);
        }
    }
    float* od = g_oscr + ((size_t)seg * NPTS + qidx) * DH;
#pragma unroll
    for (int p = 0; p < 8; p++) {
        float o0, o1, o2, o3;
        upk(acc[2 * p], o0, o1);
        upk(acc[2 * p + 1], o2, o3);
        ((float4*)od)[p] = make_float4(o0, o1, o2, o3);
    }
    g_dscr[(size_t)seg * NPTS + qidx] = den;
}

// ---------------- kernel 7: combine + out-proj + residual + LN2 + FF + residual ----------------
__global__ void __launch_bounds__(128) k_epilogue(
    const float* __restrict__ x, const float* __restrict__ ow,
    const float* __restrict__ ob, const float* __restrict__ n2w,
    const float* __restrict__ n2b, const float* __restrict__ f1w,
    const float* __restrict__ f1b, const float* __restrict__ f2w,
    const float* __restrict__ f2b, float* __restrict__ out) {
    __shared__ float ws[256 * 32];
    __shared__ float f1sT[32 * 32];
    __shared__ float f2s[32 * 32];
    __shared__ float cs[32 * 5];
    int tid = threadIdx.x;
    for (int i = tid; i < 8192; i += 128) ws[i] = ow[i];
    for (int i = tid; i < 1024; i += 128) {
        f1sT[(i & 31) * 32 + (i >> 5)] = f1w[i];
        f2s[i] = f2w[i];
    }
    if (tid < 32) {
        cs[tid] = ob[tid]; cs[32 + tid] = n2w[tid]; cs[64 + tid] = n2b[tid];
        cs[96 + tid] = f1b[tid]; cs[128 + tid] = f2b[tid];
    }
    __syncthreads();
    int n = blockIdx.x * 128 + tid;

    ull acc2[16];
#pragma unroll
    for (int p = 0; p < 16; p++) acc2[p] = pk2(cs[2 * p], cs[2 * p + 1]);

#pragma unroll 1
    for (int h = 0; h < 8; h++) {
        float den = g_dscr[(size_t)h * NPTS + n] +
                    g_dscr[(size_t)(8 + h) * NPTS + n] +
                    g_dscr[(size_t)(16 + h) * NPTS + n] + 3e-20f;
        float inv = 1.0f / den;
        const float4* oa = (const float4*)(g_oscr + ((size_t)h * NPTS + n) * DH);
        const float4* obp = (const float4*)(g_oscr + ((size_t)(8 + h) * NPTS + n) * DH);
        const float4* oc = (const float4*)(g_oscr + ((size_t)(16 + h) * NPTS + n) * DH);
#pragma unroll
        for (int p4 = 0; p4 < 8; p4++) {
            float4 a4 = oa[p4], b4 = obp[p4], c4 = oc[p4];
            float av[4];
            av[0] = (a4.x + b4.x + c4.x) * inv;
            av[1] = (a4.y + b4.y + c4.y) * inv;
            av[2] = (a4.z + b4.z + c4.z) * inv;
            av[3] = (a4.w + b4.w + c4.w) * inv;
            int j0 = h * 32 + p4 * 4;
#pragma unroll
            for (int u = 0; u < 4; u++) {
                ull ad = pk2(av[u], av[u]);
                const float4* wr2 = (const float4*)(ws + (j0 + u) * 32);
#pragma unroll
                for (int p = 0; p < 8; p++) {
                    float4 w4 = wr2[p];
                    acc2[2 * p] = f2fma(ad, lo2(w4), acc2[2 * p]);
                    acc2[2 * p + 1] = f2fma(ad, hi2(w4), acc2[2 * p + 1]);
                }
            }
        }
    }
    float acc[32];
#pragma unroll
    for (int p = 0; p < 16; p++) upk(acc2[p], acc[2 * p], acc[2 * p + 1]);

    float x2[32];
    const float4* xr = (const float4*)(x + (size_t)n * 32);
#pragma unroll
    for (int u = 0; u < 8; u++) {
        float4 xv = xr[u];
        x2[4 * u] = xv.x + acc[4 * u];
        x2[4 * u + 1] = xv.y + acc[4 * u + 1];
        x2[4 * u + 2] = xv.z + acc[4 * u + 2];
        x2[4 * u + 3] = xv.w + acc[4 * u + 3];
    }
    float mu = 0.f;
#pragma unroll
    for (int d = 0; d < 32; d++) mu += x2[d];
    mu *= (1.0f / 32.0f);
    float var = 0.f;
#pragma unroll
    for (int d = 0; d < 32; d++) { float dd = x2[d] - mu; var += dd * dd; }
    var *= (1.0f / 32.0f);
    float rs = rsqrtf(var + 1e-5f);
    float xn2[32];
#pragma unroll
    for (int d = 0; d < 32; d++)
        xn2[d] = (x2[d] - mu) * rs * cs[32 + d] + cs[64 + d];
    ull xp[16];
#pragma unroll
    for (int u = 0; u < 16; u++) xp[u] = pk2(xn2[2 * u], xn2[2 * u + 1]);
    float h1[32];
#pragma unroll 4
    for (int jj = 0; jj < 32; jj++) {
        const float4* fr = (const float4*)(f1sT + jj * 32);
        ull a0 = 0ull, a1 = 0ull;
#pragma unroll
        for (int u = 0; u < 8; u++) {
            float4 v4 = fr[u];
            a0 = f2fma(lo2(v4), xp[2 * u], a0);
            a1 = f2fma(hi2(v4), xp[2 * u + 1], a1);
        }
        float s0, s1;
        upk(f2add(a0, a1), s0, s1);
        float t2 = cs[96 + jj] + s0 + s1;
        h1[jj] = t2 / (1.0f + fexp(-t2));
    }
    ull o2[16];
#pragma unroll
    for (int p = 0; p < 16; p++) o2[p] = pk2(cs[128 + 2 * p], cs[128 + 2 * p + 1]);
#pragma unroll 4
    for (int jj = 0; jj < 32; jj++) {
        ull hd = pk2(h1[jj], h1[jj]);
        const float4* fr = (const float4*)(f2s + jj * 32);
#pragma unroll
        for (int p = 0; p < 8; p++) {
            float4 v4 = fr[p];
            o2[2 * p] = f2fma(hd, lo2(v4), o2[2 * p]);
            o2[2 * p + 1] = f2fma(hd, hi2(v4), o2[2 * p + 1]);
        }
    }
    float o[32];
#pragma unroll
    for (int p = 0; p < 16; p++) upk(o2[p], o[2 * p], o[2 * p + 1]);
    float4* orow = (float4*)(out + (size_t)n * 32);
#pragma unroll
    for (int u = 0; u < 8; u++)
        orow[u] = make_float4(x2[4 * u] + o[4 * u], x2[4 * u + 1] + o[4 * u + 1],
                              x2[4 * u + 2] + o[4 * u + 2], x2[4 * u + 3] + o[4 * u + 3]);
}

// ---------------- launcher ----------------
extern "C" void kernel_launch(void* const* d_in, const int* in_sizes, int n_in,
                              void* d_out, int out_size) {
    const float* x = (const float*)d_in[0];
    const float* coords = (const float*)d_in[1];
    const int* shifts = (const int*)d_in[2];
    const float* n1w = (const float*)d_in[3];
    const float* n1b = (const float*)d_in[4];
    const float* wq = (const float*)d_in[5];
    const float* wk = (const float*)d_in[6];
    const float* wv = (const float*)d_in[7];
    const float* wr = (const float*)d_in[8];
    const float* alpha = (const float*)d_in[9];
    const float* ow = (const float*)d_in[10];
    const float* ob = (const float*)d_in[11];
    const float* n2w = (const float*)d_in[12];
    const float* n2b = (const float*)d_in[13];
    const float* f1w = (const float*)d_in[14];
    const float* f1b = (const float*)d_in[15];
    const float* f2w = (const float*)d_in[16];
    const float* f2b = (const float*)d_in[17];
    float* out = (float*)d_out;

    cudaFuncSetAttribute(k_attn, cudaFuncAttributeMaxDynamicSharedMemorySize, 71680);

    k_ln_qkv<<<NPTS / 128, 768>>>(x, n1w, n1b, wq, wk, wv, wr);
    k_hash<<<dim3(NPTS / 256, NH), 256>>>(coords, alpha);

    const int TOT = 2 * CHN * NPTS;
    k_sort_local4k<<<TOT / 4096, 512>>>(shifts);   // keys fused in
    k_mergepath<<<TOT / 4096, 256>>>(4096, 0);
    k_mergepath<<<TOT / 4096, 256>>>(8192, 1);
    k_mergepath<<<TOT / 4096, 256>>>(16384, 0);

    k_attn<<<dim3(NBK / 2, CHN), 256, 71680>>>();
    k_epilogue<<<NPTS / 128, 128>>>(x, ow, ob, n2w, n2b, f1w, f1b, f2w, f2b, out);
}

// round 7
// speedup vs baseline: 1.1266x; 1.0108x over previous
#include <cuda_runtime.h>
#include <cstdint>

#define NPTS 32768
#define DH 32
#define NH 8
#define NC 3
#define BSZ 128
#define NBK 256
#define CHN 24          // NC*NH
#define QSTR 36         // padded row stride for 35-dim hat vectors

typedef unsigned long long ull;

// ---------------- scratch (static device globals; no allocations) ----------------
__device__ float g_qhat[(size_t)NH * NPTS * QSTR];
__device__ float g_khat[(size_t)NH * NPTS * QSTR];
__device__ float g_v[(size_t)NH * NPTS * DH];
__device__ float g_qh[(size_t)CHN * NPTS];
__device__ float g_kh[(size_t)CHN * NPTS];
__device__ ull   g_keys[(size_t)2 * CHN * NPTS];
__device__ ull   g_keys2[(size_t)2 * CHN * NPTS];
__device__ unsigned g_pmn[CHN * 256];   // per-block min partials (encf)
__device__ unsigned g_pmx[CHN * 256];   // per-block max partials (encf)
__device__ float g_oscr[(size_t)CHN * NPTS * DH];
__device__ float g_dscr[(size_t)CHN * NPTS];

// ---------------- f32x2 packed helpers ----------------
__device__ __forceinline__ ull pk2(float a, float b) {
    ull r; asm("mov.b64 %0, {%1, %2};" : "=l"(r) : "f"(a), "f"(b)); return r;
}
__device__ __forceinline__ void upk(ull p, float& a, float& b) {
    asm("mov.b64 {%0, %1}, %2;" : "=f"(a), "=f"(b) : "l"(p));
}
__device__ __forceinline__ ull f2fma(ull a, ull b, ull c) {
    ull d; asm("fma.rn.f32x2 %0, %1, %2, %3;" : "=l"(d) : "l"(a), "l"(b), "l"(c)); return d;
}
__device__ __forceinline__ ull f2add(ull a, ull b) {
    ull d; asm("add.rn.f32x2 %0, %1, %2;" : "=l"(d) : "l"(a), "l"(b)); return d;
}
__device__ __forceinline__ ull lo2(float4 v) { return pk2(v.x, v.y); }
__device__ __forceinline__ ull hi2(float4 v) { return pk2(v.z, v.w); }

// ---------------- sort helpers ----------------
__device__ __forceinline__ unsigned encf(float f) {
    unsigned u = __float_as_uint(f);
    return (u & 0x80000000u) ? ~u : (u | 0x80000000u);
}
__device__ __forceinline__ float decf(unsigned u) {
    return (u & 0x80000000u) ? __uint_as_float(u ^ 0x80000000u)
                             : __uint_as_float(~u);
}

// scalar fast exp; clamped, rel err ~1e-7
__device__ __forceinline__ float fexp(float x) {
    x = fminf(fmaxf(x, -87.0f), 87.0f);
    float t = fmaf(x, 1.4426950408889634f, 12582912.0f);
    float j = t - 12582912.0f;
    float f = fmaf(j, -0.693145751953125f, x);
    f = fmaf(j, -1.4286067653301938e-6f, f);
    float p = 1.3888889e-3f;
    p = fmaf(p, f, 8.3333333e-3f);
    p = fmaf(p, f, 4.1666667e-2f);
    p = fmaf(p, f, 1.6666667e-1f);
    p = fmaf(p, f, 0.5f);
    p = fmaf(p, f, 1.0f);
    p = fmaf(p, f, 1.0f);
    return __int_as_float(__float_as_int(p) + (__float_as_int(t) << 23));
}

// packed exp for x <= ~0; underflow-guarded
__device__ __forceinline__ void fexp2p(ull x2, float& e0, float& e1) {
    const ull L2E = pk2(1.4426950408889634f, 1.4426950408889634f);
    const ull MAG = pk2(12582912.0f, 12582912.0f);
    const ull NMAG = pk2(-12582912.0f, -12582912.0f);
    ull t2 = f2fma(x2, L2E, MAG);
    ull j2 = f2add(t2, NMAG);
    ull f2 = f2fma(j2, pk2(-0.693145751953125f, -0.693145751953125f), x2);
    f2 = f2fma(j2, pk2(-1.4286067653301938e-6f, -1.4286067653301938e-6f), f2);
    ull p = pk2(1.3888889e-3f, 1.3888889e-3f);
    p = f2fma(p, f2, pk2(8.3333333e-3f, 8.3333333e-3f));
    p = f2fma(p, f2, pk2(4.1666667e-2f, 4.1666667e-2f));
    p = f2fma(p, f2, pk2(1.6666667e-1f, 1.6666667e-1f));
    p = f2fma(p, f2, pk2(0.5f, 0.5f));
    p = f2fma(p, f2, pk2(1.0f, 1.0f));
    p = f2fma(p, f2, pk2(1.0f, 1.0f));
    float p0, p1, t0, t1;
    upk(p, p0, p1); upk(t2, t0, t1);
    float r0 = __int_as_float(__float_as_int(p0) + (__float_as_int(t0) << 23));
    float r1 = __int_as_float(__float_as_int(p1) + (__float_as_int(t1) << 23));
    e0 = (t0 < 12582792.0f) ? 0.0f : r0;
    e1 = (t1 < 12582792.0f) ? 0.0f : r1;
}

// ---------------- kernel 1: LN + QKV + coords tails + LSH hash + minmax partials ----------------
__global__ void __launch_bounds__(768) k_ln_qkv(
    const float* __restrict__ x, const float* __restrict__ n1w,
    const float* __restrict__ n1b, const float* __restrict__ wq,
    const float* __restrict__ wk, const float* __restrict__ wv,
    const float* __restrict__ wr, const float* __restrict__ coords,
    const float* __restrict__ alpha) {
    __shared__ float xs[128 * QSTR];       // 18KB
    __shared__ float Msm0[32 * 24];        // folded Wq*alpha  [e*24+ch]
    __shared__ float Msm1[32 * 24];        // folded Wk*alpha
    __shared__ float sw[24];
    __shared__ float part_mn[24][8];
    __shared__ float part_mx[24][8];
    int base = blockIdx.x * 128;
    int tid = threadIdx.x;

    // phase 0a: sqrt weights (redundant per block; cheap)
    if (tid < CHN) {
        int h = tid / 3, r = tid % 3;
        float qw = 0.f;
        for (int k = 0; k < 8; k++) {
            float s = 0.f;
            for (int d = 0; d < 32; d++) s += wr[(h * 32 + d) * 24 + r * 8 + k];
            qw += expf(fminf(s, 50.f));
        }
        sw[tid] = sqrtf(2.f * qw);
    }
    // phase 0b: folded hash matrices M[e][ch] = sum_d W[e, h*32+d] * alpha[h,d,c]
    {
        int ch = tid >> 5, e = tid & 31;   // 24*32 = 768 exactly
        int c = ch >> 3, h = ch & 7;
        float mq = 0.f, mk = 0.f;
        const float* wqr = wq + e * 256 + h * 32;
        const float* wkr = wk + e * 256 + h * 32;
        const float* al = alpha + h * 105 + c;
#pragma unroll 8
        for (int d = 0; d < 32; d++) {
            float a = al[d * 3];
            mq += wqr[d] * a;
            mk += wkr[d] * a;
        }
        Msm0[e * 24 + ch] = mq;
        Msm1[e * 24 + ch] = mk;
    }
    __syncthreads();

    // phase 1: LayerNorm into xs
    if (tid < 128) {
        int n = base + tid;
        float r[32];
        const float4* xr = (const float4*)(x + (size_t)n * 32);
#pragma unroll
        for (int u = 0; u < 8; u++) {
            float4 v4 = xr[u];
            r[4 * u] = v4.x; r[4 * u + 1] = v4.y; r[4 * u + 2] = v4.z; r[4 * u + 3] = v4.w;
        }
        float mu = 0.f;
#pragma unroll
        for (int d = 0; d < 32; d++) mu += r[d];
        mu *= (1.0f / 32.0f);
        float var = 0.f;
#pragma unroll
        for (int d = 0; d < 32; d++) { float dd = r[d] - mu; var += dd * dd; }
        var *= (1.0f / 32.0f);
        float rs = rsqrtf(var + 1e-5f);
#pragma unroll
        for (int d = 0; d < 32; d++)
            xs[tid * QSTR + d] = (r[d] - mu) * rs * n1w[d] + n1b[d];
    }
    __syncthreads();

    // phase 2: QKV projection (column-per-thread)
    {
        int proj = tid >> 8, jj = tid & 255;
        const float* W = (proj == 0) ? wq : (proj == 1) ? wk : wv;
        ull wpk[16];
#pragma unroll
        for (int d = 0; d < 16; d++)
            wpk[d] = pk2(W[(2 * d) * 256 + jj], W[(2 * d + 1) * 256 + jj]);
        int h = jj >> 5, d0 = jj & 31;
        float* dst;
        int stride;
        if (proj == 0) { dst = g_qhat; stride = QSTR; }
        else if (proj == 1) { dst = g_khat; stride = QSTR; }
        else { dst = g_v; stride = DH; }
        for (int r = 0; r < 128; r++) {
            const float4* xr = (const float4*)(xs + r * QSTR);
            ull a0 = 0, a1 = 0;
#pragma unroll
            for (int u = 0; u < 8; u++) {
                float4 v4 = xr[u];
                a0 = f2fma(lo2(v4), wpk[2 * u], a0);
                a1 = f2fma(hi2(v4), wpk[2 * u + 1], a1);
            }
            float s0, s1;
            upk(f2add(a0, a1), s0, s1);
            dst[((size_t)h * NPTS + (base + r)) * stride + d0] = s0 + s1;
        }
    }
    // phase 2b: coords tails (positions 32..35 of qhat/khat rows)
    if (tid < 128) {
        int n = base + tid;
        float c0 = coords[n * 3], c1 = coords[n * 3 + 1], c2 = coords[n * 3 + 2];
#pragma unroll
        for (int h = 0; h < 8; h++) {
            float4 tail = make_float4(sw[h * 3] * c0, sw[h * 3 + 1] * c1,
                                      sw[h * 3 + 2] * c2, 0.f);
            *(float4*)(g_qhat + ((size_t)h * NPTS + n) * QSTR + 32) = tail;
            *(float4*)(g_khat + ((size_t)h * NPTS + n) * QSTR + 32) = tail;
        }
    }

    // phase 3: hashes. thread = (row, slot); slot<3 -> q (c=slot), else k (c=slot-3)
    {
        int row = tid & 127;
        int slot = tid >> 7;
        int half = slot >= 3;
        int c = half ? slot - 3 : slot;
        int n = base + row;
        float xr[32];
        const float4* xrow = (const float4*)(xs + row * QSTR);
#pragma unroll
        for (int u = 0; u < 8; u++) ((float4*)xr)[u] = xrow[u];
        float c0 = coords[n * 3], c1 = coords[n * 3 + 1], c2 = coords[n * 3 + 2];
        const float* M = half ? Msm1 : Msm0;
        float acc[8];
#pragma unroll
        for (int h = 0; h < 8; h++) acc[h] = 0.f;
#pragma unroll 8
        for (int e = 0; e < 32; e++) {
            float xv = xr[e];
            const float* Mr = M + e * 24 + c * 8;
#pragma unroll
            for (int h = 0; h < 8; h++) acc[h] += xv * Mr[h];
        }
        float* dst = half ? g_kh : g_qh;
#pragma unroll
        for (int h = 0; h < 8; h++) {
            float sr0 = sw[h * 3] * c0, sr1 = sw[h * 3 + 1] * c1, sr2 = sw[h * 3 + 2] * c2;
            const float* al = alpha + h * 105 + c;
            acc[h] += sr0 * al[96] + sr1 * al[99] + sr2 * al[102];
            dst[(size_t)(c * 8 + h) * NPTS + n] = acc[h];
        }
        // per-warp min/max partials (warp = 32 rows of one slot)
        int rw = row >> 5;
#pragma unroll
        for (int h = 0; h < 8; h++) {
            float mn = acc[h], mx = acc[h];
#pragma unroll
            for (int o = 16; o > 0; o >>= 1) {
                mn = fminf(mn, __shfl_xor_sync(0xFFFFFFFFu, mn, o));
                mx = fmaxf(mx, __shfl_xor_sync(0xFFFFFFFFu, mx, o));
            }
            if ((tid & 31) == 0) {
                part_mn[c * 8 + h][half * 4 + rw] = mn;
                part_mx[c * 8 + h][half * 4 + rw] = mx;
            }
        }
    }
    __syncthreads();
    if (tid < CHN) {
        float mn = part_mn[tid][0], mx = part_mx[tid][0];
#pragma unroll
        for (int i = 1; i < 8; i++) {
            mn = fminf(mn, part_mn[tid][i]);
            mx = fmaxf(mx, part_mx[tid][i]);
        }
        g_pmn[tid * 256 + blockIdx.x] = encf(mn);
        g_pmx[tid * 256 + blockIdx.x] = encf(mx);
    }
}

// ---------------- local bitonic sort of 4096-elem chunks + fused key build + minmax reduce ----
template<int J>
__device__ __forceinline__ void shflp8(ull* r, int ibase, int l, int k_) {
#pragma unroll
    for (int s = 0; s < 8; s++) {
        int i = ibase + s * 32;
        bool up = ((i & k_) == 0);
        ull o = __shfl_xor_sync(0xFFFFFFFFu, r[s], J);
        bool kmin = (((l & J) == 0) == up);
        ull lo_ = (r[s] < o) ? r[s] : o;
        ull hi_ = (r[s] < o) ? o : r[s];
        r[s] = kmin ? lo_ : hi_;
    }
}
template<int JS>   // slot-pair pass, J = JS*32
__device__ __forceinline__ void slotp8(ull* r, int ibase, int k_) {
#pragma unroll
    for (int s = 0; s < 8; s++) {
        if (!(s & JS)) {
            int sp = s | JS;
            int i = ibase + s * 32;
            bool up = ((i & k_) == 0);
            if ((r[s] > r[sp]) == up) { ull t2 = r[s]; r[s] = r[sp]; r[sp] = t2; }
        }
    }
}
__device__ __forceinline__ void regpasses8(ull* r, int ibase, int l, int k_) {
    int half = k_ >> 1;
    if (half >= 128) slotp8<4>(r, ibase, k_);
    if (half >= 64)  slotp8<2>(r, ibase, k_);
    if (half >= 32)  slotp8<1>(r, ibase, k_);
    if (half >= 16)  shflp8<16>(r, ibase, l, k_);
    if (half >= 8)   shflp8<8>(r, ibase, l, k_);
    if (half >= 4)   shflp8<4>(r, ibase, l, k_);
    if (half >= 2)   shflp8<2>(r, ibase, l, k_);
    shflp8<1>(r, ibase, l, k_);
}
__device__ __forceinline__ void smem_pass4k(ull* s, int k_, int j_, int tid) {
#pragma unroll
    for (int p = 0; p < 4; p++) {
        int t = tid + p * 512;
        int i = ((t & ~(j_ - 1)) << 1) | (t & (j_ - 1));
        bool up = ((i & k_) == 0);
        ull a = s[i], b = s[i + j_];
        if ((a > b) == up) { s[i] = b; s[i + j_] = a; }
    }
}

__global__ void __launch_bounds__(512) k_sort_local4k(const int* __restrict__ shifts) {
    __shared__ ull s[4096];
    __shared__ unsigned redn[8], redx[8];
    __shared__ float s_hsv;
    size_t base = (size_t)blockIdx.x * 4096;
    int tid = threadIdx.x;
    int w = tid >> 5, l = tid & 31;
    int ibase = w * 256 + l;

    bool isQ = (base < (size_t)CHN * NPTS);
    size_t hoff = isQ ? base : base - (size_t)CHN * NPTS;
    int seg = (int)(hoff >> 15);

    // reduce per-block minmax partials for this segment
    if (tid < 256) {
        unsigned umn = g_pmn[seg * 256 + tid];
        unsigned umx = g_pmx[seg * 256 + tid];
        unsigned a = __reduce_min_sync(0xFFFFFFFFu, umn);
        unsigned b = __reduce_max_sync(0xFFFFFFFFu, umx);
        if ((tid & 31) == 0) { redn[tid >> 5] = a; redx[tid >> 5] = b; }
    }
    __syncthreads();
    if (tid == 0) {
        unsigned a = redn[0], b = redx[0];
#pragma unroll
        for (int i = 1; i < 8; i++) {
            if (redn[i] < a) a = redn[i];
            if (redx[i] > b) b = redx[i];
        }
        s_hsv = decf(b) - decf(a);
    }
    __syncthreads();
    float hsv = s_hsv;

    const float* hsrc = isQ ? g_qh : g_kh;
    ull r[8];
#pragma unroll
    for (int s_ = 0; s_ < 8; s_++) {
        size_t t = hoff + ibase + s_ * 32;
        float off = __fmul_rn((float)shifts[t], hsv);
        r[s_] = ((ull)encf(__fadd_rn(hsrc[t], off)) << 32) | (unsigned)(t & (NPTS - 1));
    }

    for (int k_ = 2; k_ <= 256; k_ <<= 1) regpasses8(r, ibase, l, k_);

    for (int k_ = 512; k_ <= 4096; k_ <<= 1) {
#pragma unroll
        for (int s_ = 0; s_ < 8; s_++) s[ibase + s_ * 32] = r[s_];
        __syncthreads();
        for (int j_ = k_ >> 1; j_ >= 256; j_ >>= 1) {
            smem_pass4k(s, k_, j_, tid);
            __syncthreads();
        }
#pragma unroll
        for (int s_ = 0; s_ < 8; s_++) r[s_] = s[ibase + s_ * 32];
        __syncthreads();
        regpasses8(r, ibase, l, k_);
    }
#pragma unroll
    for (int s_ = 0; s_ < 8; s_++) g_keys[base + ibase + s_ * 32] = r[s_];
}

// ---------------- merge-path merge pass (global, R5 version): runs of L -> 2L ----------------
__global__ void __launch_bounds__(256) k_mergepath(int L, int dir) {
    const ull* __restrict__ src = dir ? g_keys2 : g_keys;
    ull* __restrict__ dst = dir ? g_keys : g_keys2;
    size_t outbase = (size_t)blockIdx.x * 4096 + (size_t)threadIdx.x * 16;
    size_t pairBase = outbase & ~((size_t)(2 * L) - 1);
    const ull* A = src + pairBase;
    const ull* B = A + L;
    int p0 = (int)(outbase - pairBase);
    int lo = p0 > L ? p0 - L : 0;
    int hi = p0 < L ? p0 : L;
    while (lo < hi) {
        int m = (lo + hi) >> 1;
        if (A[m] <= B[p0 - 1 - m]) lo = m + 1; else hi = m;
    }
    int i = lo, j = p0 - lo;
    ull* d = dst + pairBase + p0;
    ull a = (i < L) ? A[i] : ~0ull;     // keys never equal ~0 (index bits < 2^15)
    ull b = (j < L) ? B[j] : ~0ull;
#pragma unroll
    for (int t = 0; t < 16; t++) {
        bool takeA = (a <= b);
        d[t] = takeA ? a : b;
        if (takeA) { i++; a = (i < L) ? A[i] : ~0ull; }
        else       { j++; b = (j < L) ? B[j] : ~0ull; }
    }
}

// ---------------- kernel 5: bucketed attention (256 thr, 2 buckets, 1 q/thread, 2j unroll) ----
__global__ void __launch_bounds__(256, 2) k_attn() {
    extern __shared__ float sm[];
    float* ks = sm;                    // [2][128][36]
    float* vs = sm + 9216;             // [2][128][32]
    float* ksq = sm + 9216 + 8192;     // [2][128]
    int seg = blockIdx.y;
    int h = seg & 7;
    int t = threadIdx.x;
    int tb = t >> 7;                   // bucket half
    int tq = t & 127;                  // q/load row
    int bucket = blockIdx.x * 2 + tb;

    const ull* kkey = g_keys2 + ((size_t)(CHN + seg)) * NPTS + bucket * BSZ;
    const ull* qkey = g_keys2 + (size_t)seg * NPTS + bucket * BSZ;

    {
        unsigned kidx = (unsigned)kkey[tq];
        const float4* kr = (const float4*)(g_khat + ((size_t)h * NPTS + kidx) * QSTR);
        float tmp[36];
#pragma unroll
        for (int u = 0; u < 9; u++) ((float4*)tmp)[u] = kr[u];
        float s2 = 0.f;
#pragma unroll
        for (int d = 0; d < 35; d++) s2 += tmp[d] * tmp[d];
        ksq[tb * 128 + tq] = -0.5f * s2;
        float* kd = ks + (tb * 128 + tq) * 36;
#pragma unroll
        for (int u = 0; u < 9; u++) ((float4*)kd)[u] = ((float4*)tmp)[u];
        const float4* vr = (const float4*)(g_v + ((size_t)h * NPTS + kidx) * DH);
        float* vd = vs + (tb * 128 + tq) * 32;
#pragma unroll
        for (int u = 0; u < 8; u++) ((float4*)vd)[u] = vr[u];
    }

    unsigned qidx = (unsigned)qkey[tq];
    ull qp[18];
    {
        const float4* qr = (const float4*)(g_qhat + ((size_t)h * NPTS + qidx) * QSTR);
#pragma unroll
        for (int u = 0; u < 9; u++) ((float4*)qp)[u] = qr[u];
    }
    float qsq = 0.f;
#pragma unroll
    for (int d = 0; d < 35; d++) qsq += ((float*)qp)[d] * ((float*)qp)[d];
    qsq *= -0.5f;

    ull acc[16];
#pragma unroll
    for (int p = 0; p < 16; p++) acc[p] = 0ull;
    float den = 0.f;
    __syncthreads();

    const float* ksb = ks + tb * 128 * 36;
    const float* vsb = vs + tb * 128 * 32;
    const float* ksqb = ksq + tb * 128;
    for (int j = 0; j < BSZ; j += 2) {
        const float4* k0 = (const float4*)(ksb + j * 36);
        const float4* k1 = (const float4*)(ksb + j * 36 + 36);
        ull d00 = 0ull, d01 = 0ull, d10 = 0ull, d11 = 0ull;
#pragma unroll
        for (int u = 0; u < 9; u++) {
            float4 c0 = k0[u];
            float4 c1 = k1[u];
            d00 = f2fma(qp[2 * u], lo2(c0), d00);
            d01 = f2fma(qp[2 * u + 1], hi2(c0), d01);
            d10 = f2fma(qp[2 * u], lo2(c1), d10);
            d11 = f2fma(qp[2 * u + 1], hi2(c1), d11);
        }
        float a0, a1, b0, b1;
        upk(f2add(d00, d01), a0, a1);
        upk(f2add(d10, d11), b0, b1);
        float2 kq = *(const float2*)&ksqb[j];
        float s0 = a0 + a1 + qsq + kq.x;
        float s1 = b0 + b1 + qsq + kq.y;
        float e0, e1;
        fexp2p(pk2(s0, s1), e0, e1);
        den += e0 + e1;
        ull e0d = pk2(e0, e0), e1d = pk2(e1, e1);
        const float4* v0 = (const float4*)(vsb + j * 32);
        const float4* v1 = (const float4*)(vsb + j * 32 + 32);
#pragma unroll
        for (int p = 0; p < 8; p++) {
            float4 vv0 = v0[p];
            float4 vv1 = v1[p];
            acc[2 * p] = f2fma(e0d, lo2(vv0), acc[2 * p]);
            acc[2 * p + 1] = f2fma(e0d, hi2(vv0), acc[2 * p + 1]);
            acc[2 * p] = f2fma(e1d, lo2(vv1), acc[2 * p]);
            acc[2 * p + 1] = f2fma(e1d, hi2(vv1), acc[2 * p + 1]);
        }
    }
    float* od = g_oscr + ((size_t)seg * NPTS + qidx) * DH;
#pragma unroll
    for (int p = 0; p < 8; p++) {
        float o0, o1, o2, o3;
        upk(acc[2 * p], o0, o1);
        upk(acc[2 * p + 1], o2, o3);
        ((float4*)od)[p] = make_float4(o0, o1, o2, o3);
    }
    g_dscr[(size_t)seg * NPTS + qidx] = den;
}

// ---------------- kernel 7: combine + out-proj + residual + LN2 + FF + residual ----------------
__global__ void __launch_bounds__(128) k_epilogue(
    const float* __restrict__ x, const float* __restrict__ ow,
    const float* __restrict__ ob, const float* __restrict__ n2w,
    const float* __restrict__ n2b, const float* __restrict__ f1w,
    const float* __restrict__ f1b, const float* __restrict__ f2w,
    const float* __restrict__ f2b, float* __restrict__ out) {
    __shared__ float ws[256 * 32];
    __shared__ float f1sT[32 * 32];
    __shared__ float f2s[32 * 32];
    __shared__ float cs[32 * 5];
    int tid = threadIdx.x;
    for (int i = tid; i < 8192; i += 128) ws[i] = ow[i];
    for (int i = tid; i < 1024; i += 128) {
        f1sT[(i & 31) * 32 + (i >> 5)] = f1w[i];
        f2s[i] = f2w[i];
    }
    if (tid < 32) {
        cs[tid] = ob[tid]; cs[32 + tid] = n2w[tid]; cs[64 + tid] = n2b[tid];
        cs[96 + tid] = f1b[tid]; cs[128 + tid] = f2b[tid];
    }
    __syncthreads();
    int n = blockIdx.x * 128 + tid;

    ull acc2[16];
#pragma unroll
    for (int p = 0; p < 16; p++) acc2[p] = pk2(cs[2 * p], cs[2 * p + 1]);

#pragma unroll 1
    for (int h = 0; h < 8; h++) {
        float den = g_dscr[(size_t)h * NPTS + n] +
                    g_dscr[(size_t)(8 + h) * NPTS + n] +
                    g_dscr[(size_t)(16 + h) * NPTS + n] + 3e-20f;
        float inv = 1.0f / den;
        const float4* oa = (const float4*)(g_oscr + ((size_t)h * NPTS + n) * DH);
        const float4* obp = (const float4*)(g_oscr + ((size_t)(8 + h) * NPTS + n) * DH);
        const float4* oc = (const float4*)(g_oscr + ((size_t)(16 + h) * NPTS + n) * DH);
#pragma unroll
        for (int p4 = 0; p4 < 8; p4++) {
            float4 a4 = oa[p4], b4 = obp[p4], c4 = oc[p4];
            float av[4];
            av[0] = (a4.x + b4.x + c4.x) * inv;
            av[1] = (a4.y + b4.y + c4.y) * inv;
            av[2] = (a4.z + b4.z + c4.z) * inv;
            av[3] = (a4.w + b4.w + c4.w) * inv;
            int j0 = h * 32 + p4 * 4;
#pragma unroll
            for (int u = 0; u < 4; u++) {
                ull ad = pk2(av[u], av[u]);
                const float4* wr2 = (const float4*)(ws + (j0 + u) * 32);
#pragma unroll
                for (int p = 0; p < 8; p++) {
                    float4 w4 = wr2[p];
                    acc2[2 * p] = f2fma(ad, lo2(w4), acc2[2 * p]);
                    acc2[2 * p + 1] = f2fma(ad, hi2(w4), acc2[2 * p + 1]);
                }
            }
        }
    }
    float acc[32];
#pragma unroll
    for (int p = 0; p < 16; p++) upk(acc2[p], acc[2 * p], acc[2 * p + 1]);

    float x2[32];
    const float4* xr = (const float4*)(x + (size_t)n * 32);
#pragma unroll
    for (int u = 0; u < 8; u++) {
        float4 xv = xr[u];
        x2[4 * u] = xv.x + acc[4 * u];
        x2[4 * u + 1] = xv.y + acc[4 * u + 1];
        x2[4 * u + 2] = xv.z + acc[4 * u + 2];
        x2[4 * u + 3] = xv.w + acc[4 * u + 3];
    }
    float mu = 0.f;
#pragma unroll
    for (int d = 0; d < 32; d++) mu += x2[d];
    mu *= (1.0f / 32.0f);
    float var = 0.f;
#pragma unroll
    for (int d = 0; d < 32; d++) { float dd = x2[d] - mu; var += dd * dd; }
    var *= (1.0f / 32.0f);
    float rs = rsqrtf(var + 1e-5f);
    float xn2[32];
#pragma unroll
    for (int d = 0; d < 32; d++)
        xn2[d] = (x2[d] - mu) * rs * cs[32 + d] + cs[64 + d];
    ull xp[16];
#pragma unroll
    for (int u = 0; u < 16; u++) xp[u] = pk2(xn2[2 * u], xn2[2 * u + 1]);
    float h1[32];
#pragma unroll 4
    for (int jj = 0; jj < 32; jj++) {
        const float4* fr = (const float4*)(f1sT + jj * 32);
        ull a0 = 0ull, a1 = 0ull;
#pragma unroll
        for (int u = 0; u < 8; u++) {
            float4 v4 = fr[u];
            a0 = f2fma(lo2(v4), xp[2 * u], a0);
            a1 = f2fma(hi2(v4), xp[2 * u + 1], a1);
        }
        float s0, s1;
        upk(f2add(a0, a1), s0, s1);
        float t2 = cs[96 + jj] + s0 + s1;
        h1[jj] = t2 / (1.0f + fexp(-t2));
    }
    ull o2[16];
#pragma unroll
    for (int p = 0; p < 16; p++) o2[p] = pk2(cs[128 + 2 * p], cs[128 + 2 * p + 1]);
#pragma unroll 4
    for (int jj = 0; jj < 32; jj++) {
        ull hd = pk2(h1[jj], h1[jj]);
        const float4* fr = (const float4*)(f2s + jj * 32);
#pragma unroll
        for (int p = 0; p < 8; p++) {
            float4 v4 = fr[p];
            o2[2 * p] = f2fma(hd, lo2(v4), o2[2 * p]);
            o2[2 * p + 1] = f2fma(hd, hi2(v4), o2[2 * p + 1]);
        }
    }
    float o[32];
#pragma unroll
    for (int p = 0; p < 16; p++) upk(o2[p], o[2 * p], o[2 * p + 1]);
    float4* orow = (float4*)(out + (size_t)n * 32);
#pragma unroll
    for (int u = 0; u < 8; u++)
        orow[u] = make_float4(x2[4 * u] + o[4 * u], x2[4 * u + 1] + o[4 * u + 1],
                              x2[4 * u + 2] + o[4 * u + 2], x2[4 * u + 3] + o[4 * u + 3]);
}

// ---------------- launcher ----------------
extern "C" void kernel_launch(void* const* d_in, const int* in_sizes, int n_in,
                              void* d_out, int out_size) {
    const float* x = (const float*)d_in[0];
    const float* coords = (const float*)d_in[1];
    const int* shifts = (const int*)d_in[2];
    const float* n1w = (const float*)d_in[3];
    const float* n1b = (const float*)d_in[4];
    const float* wq = (const float*)d_in[5];
    const float* wk = (const float*)d_in[6];
    const float* wv = (const float*)d_in[7];
    const float* wr = (const float*)d_in[8];
    const float* alpha = (const float*)d_in[9];
    const float* ow = (const float*)d_in[10];
    const float* ob = (const float*)d_in[11];
    const float* n2w = (const float*)d_in[12];
    const float* n2b = (const float*)d_in[13];
    const float* f1w = (const float*)d_in[14];
    const float* f1b = (const float*)d_in[15];
    const float* f2w = (const float*)d_in[16];
    const float* f2b = (const float*)d_in[17];
    float* out = (float*)d_out;

    cudaFuncSetAttribute(k_attn, cudaFuncAttributeMaxDynamicSharedMemorySize, 71680);

    // launch 0: LN + QKV + tails + hash + minmax partials
    k_ln_qkv<<<NPTS / 128, 768>>>(x, n1w, n1b, wq, wk, wv, wr, coords, alpha);

    const int TOT = 2 * CHN * NPTS;
    // launch 1: key build + local sort (reduces minmax partials first)
    k_sort_local4k<<<TOT / 4096, 512>>>(shifts);
    // launches 2-4: merge passes
    k_mergepath<<<TOT / 4096, 256>>>(4096, 0);
    k_mergepath<<<TOT / 4096, 256>>>(8192, 1);
    k_mergepath<<<TOT / 4096, 256>>>(16384, 0);

    // launch 5 (ncu capture slot): attention
    k_attn<<<dim3(NBK / 2, CHN), 256, 71680>>>();
    // launch 6: epilogue
    k_epilogue<<<NPTS / 128, 128>>>(x, ow, ob, n2w, n2b, f1w, f1b, f2w, f2b, out);
}

// round 8
// speedup vs baseline: 1.1292x; 1.0024x over previous
#include <cuda_runtime.h>
#include <cstdint>

#define NPTS 32768
#define DH 32
#define NH 8
#define NC 3
#define BSZ 128
#define NBK 256
#define CHN 24          // NC*NH
#define QSTR 36         // padded row stride for 35-dim hat vectors

typedef unsigned long long ull;

// ---------------- scratch (static device globals; no allocations) ----------------
__device__ float g_qhat[(size_t)NH * NPTS * QSTR];
__device__ float g_khat[(size_t)NH * NPTS * QSTR];
__device__ float g_v[(size_t)NH * NPTS * DH];
__device__ float g_qh[(size_t)CHN * NPTS];
__device__ float g_kh[(size_t)CHN * NPTS];
__device__ ull   g_keys[(size_t)2 * CHN * NPTS];
__device__ ull   g_keys2[(size_t)2 * CHN * NPTS];
__device__ unsigned g_pmn[CHN * 256];   // per-block min partials (encf)
__device__ unsigned g_pmx[CHN * 256];   // per-block max partials (encf)
__device__ float g_oscr[(size_t)CHN * NPTS * DH];
__device__ float g_dscr[(size_t)CHN * NPTS];

// ---------------- f32x2 packed helpers ----------------
__device__ __forceinline__ ull pk2(float a, float b) {
    ull r; asm("mov.b64 %0, {%1, %2};" : "=l"(r) : "f"(a), "f"(b)); return r;
}
__device__ __forceinline__ void upk(ull p, float& a, float& b) {
    asm("mov.b64 {%0, %1}, %2;" : "=f"(a), "=f"(b) : "l"(p));
}
__device__ __forceinline__ ull f2fma(ull a, ull b, ull c) {
    ull d; asm("fma.rn.f32x2 %0, %1, %2, %3;" : "=l"(d) : "l"(a), "l"(b), "l"(c)); return d;
}
__device__ __forceinline__ ull f2add(ull a, ull b) {
    ull d; asm("add.rn.f32x2 %0, %1, %2;" : "=l"(d) : "l"(a), "l"(b)); return d;
}
__device__ __forceinline__ ull lo2(float4 v) { return pk2(v.x, v.y); }
__device__ __forceinline__ ull hi2(float4 v) { return pk2(v.z, v.w); }

// ---------------- sort helpers ----------------
__device__ __forceinline__ unsigned encf(float f) {
    unsigned u = __float_as_uint(f);
    return (u & 0x80000000u) ? ~u : (u | 0x80000000u);
}
__device__ __forceinline__ float decf(unsigned u) {
    return (u & 0x80000000u) ? __uint_as_float(u ^ 0x80000000u)
                             : __uint_as_float(~u);
}

// scalar fast exp; clamped, rel err ~1e-7
__device__ __forceinline__ float fexp(float x) {
    x = fminf(fmaxf(x, -87.0f), 87.0f);
    float t = fmaf(x, 1.4426950408889634f, 12582912.0f);
    float j = t - 12582912.0f;
    float f = fmaf(j, -0.693145751953125f, x);
    f = fmaf(j, -1.4286067653301938e-6f, f);
    float p = 1.3888889e-3f;
    p = fmaf(p, f, 8.3333333e-3f);
    p = fmaf(p, f, 4.1666667e-2f);
    p = fmaf(p, f, 1.6666667e-1f);
    p = fmaf(p, f, 0.5f);
    p = fmaf(p, f, 1.0f);
    p = fmaf(p, f, 1.0f);
    return __int_as_float(__float_as_int(p) + (__float_as_int(t) << 23));
}

// packed exp for x <= ~0; underflow-guarded
__device__ __forceinline__ void fexp2p(ull x2, float& e0, float& e1) {
    const ull L2E = pk2(1.4426950408889634f, 1.4426950408889634f);
    const ull MAG = pk2(12582912.0f, 12582912.0f);
    const ull NMAG = pk2(-12582912.0f, -12582912.0f);
    ull t2 = f2fma(x2, L2E, MAG);
    ull j2 = f2add(t2, NMAG);
    ull f2 = f2fma(j2, pk2(-0.693145751953125f, -0.693145751953125f), x2);
    f2 = f2fma(j2, pk2(-1.4286067653301938e-6f, -1.4286067653301938e-6f), f2);
    ull p = pk2(1.3888889e-3f, 1.3888889e-3f);
    p = f2fma(p, f2, pk2(8.3333333e-3f, 8.3333333e-3f));
    p = f2fma(p, f2, pk2(4.1666667e-2f, 4.1666667e-2f));
    p = f2fma(p, f2, pk2(1.6666667e-1f, 1.6666667e-1f));
    p = f2fma(p, f2, pk2(0.5f, 0.5f));
    p = f2fma(p, f2, pk2(1.0f, 1.0f));
    p = f2fma(p, f2, pk2(1.0f, 1.0f));
    float p0, p1, t0, t1;
    upk(p, p0, p1); upk(t2, t0, t1);
    float r0 = __int_as_float(__float_as_int(p0) + (__float_as_int(t0) << 23));
    float r1 = __int_as_float(__float_as_int(p1) + (__float_as_int(t1) << 23));
    e0 = (t0 < 12582792.0f) ? 0.0f : r0;
    e1 = (t1 < 12582792.0f) ? 0.0f : r1;
}

// ---------------- kernel 1: LN + QKV + coords tails + LSH hash + minmax partials ----------------
__global__ void __launch_bounds__(768) k_ln_qkv(
    const float* __restrict__ x, const float* __restrict__ n1w,
    const float* __restrict__ n1b, const float* __restrict__ wq,
    const float* __restrict__ wk, const float* __restrict__ wv,
    const float* __restrict__ wr, const float* __restrict__ coords,
    const float* __restrict__ alpha) {
    __shared__ float xs[128 * QSTR];       // 18KB
    __shared__ float Msm0[32 * 24];        // folded Wq*alpha  [e*24+ch]
    __shared__ float Msm1[32 * 24];        // folded Wk*alpha
    __shared__ float sw[24];
    __shared__ float part_mn[24][8];
    __shared__ float part_mx[24][8];
    int base = blockIdx.x * 128;
    int tid = threadIdx.x;

    // phase 0a: sqrt weights (redundant per block; cheap)
    if (tid < CHN) {
        int h = tid / 3, r = tid % 3;
        float qw = 0.f;
        for (int k = 0; k < 8; k++) {
            float s = 0.f;
            for (int d = 0; d < 32; d++) s += wr[(h * 32 + d) * 24 + r * 8 + k];
            qw += expf(fminf(s, 50.f));
        }
        sw[tid] = sqrtf(2.f * qw);
    }
    // phase 0b: folded hash matrices M[e][ch] = sum_d W[e, h*32+d] * alpha[h,d,c]
    {
        int ch = tid >> 5, e = tid & 31;   // 24*32 = 768 exactly
        int c = ch >> 3, h = ch & 7;
        float mq = 0.f, mk = 0.f;
        const float* wqr = wq + e * 256 + h * 32;
        const float* wkr = wk + e * 256 + h * 32;
        const float* al = alpha + h * 105 + c;
#pragma unroll 8
        for (int d = 0; d < 32; d++) {
            float a = al[d * 3];
            mq += wqr[d] * a;
            mk += wkr[d] * a;
        }
        Msm0[e * 24 + ch] = mq;
        Msm1[e * 24 + ch] = mk;
    }
    __syncthreads();

    // phase 1: LayerNorm into xs
    if (tid < 128) {
        int n = base + tid;
        float r[32];
        const float4* xr = (const float4*)(x + (size_t)n * 32);
#pragma unroll
        for (int u = 0; u < 8; u++) {
            float4 v4 = xr[u];
            r[4 * u] = v4.x; r[4 * u + 1] = v4.y; r[4 * u + 2] = v4.z; r[4 * u + 3] = v4.w;
        }
        float mu = 0.f;
#pragma unroll
        for (int d = 0; d < 32; d++) mu += r[d];
        mu *= (1.0f / 32.0f);
        float var = 0.f;
#pragma unroll
        for (int d = 0; d < 32; d++) { float dd = r[d] - mu; var += dd * dd; }
        var *= (1.0f / 32.0f);
        float rs = rsqrtf(var + 1e-5f);
#pragma unroll
        for (int d = 0; d < 32; d++)
            xs[tid * QSTR + d] = (r[d] - mu) * rs * n1w[d] + n1b[d];
    }
    __syncthreads();

    // phase 2: QKV projection (column-per-thread)
    {
        int proj = tid >> 8, jj = tid & 255;
        const float* W = (proj == 0) ? wq : (proj == 1) ? wk : wv;
        ull wpk[16];
#pragma unroll
        for (int d = 0; d < 16; d++)
            wpk[d] = pk2(W[(2 * d) * 256 + jj], W[(2 * d + 1) * 256 + jj]);
        int h = jj >> 5, d0 = jj & 31;
        float* dst;
        int stride;
        if (proj == 0) { dst = g_qhat; stride = QSTR; }
        else if (proj == 1) { dst = g_khat; stride = QSTR; }
        else { dst = g_v; stride = DH; }
        for (int r = 0; r < 128; r++) {
            const float4* xr = (const float4*)(xs + r * QSTR);
            ull a0 = 0, a1 = 0;
#pragma unroll
            for (int u = 0; u < 8; u++) {
                float4 v4 = xr[u];
                a0 = f2fma(lo2(v4), wpk[2 * u], a0);
                a1 = f2fma(hi2(v4), wpk[2 * u + 1], a1);
            }
            float s0, s1;
            upk(f2add(a0, a1), s0, s1);
            dst[((size_t)h * NPTS + (base + r)) * stride + d0] = s0 + s1;
        }
    }
    // phase 2b: coords tails (positions 32..35 of qhat/khat rows)
    if (tid < 128) {
        int n = base + tid;
        float c0 = coords[n * 3], c1 = coords[n * 3 + 1], c2 = coords[n * 3 + 2];
#pragma unroll
        for (int h = 0; h < 8; h++) {
            float4 tail = make_float4(sw[h * 3] * c0, sw[h * 3 + 1] * c1,
                                      sw[h * 3 + 2] * c2, 0.f);
            *(float4*)(g_qhat + ((size_t)h * NPTS + n) * QSTR + 32) = tail;
            *(float4*)(g_khat + ((size_t)h * NPTS + n) * QSTR + 32) = tail;
        }
    }

    // phase 3: hashes. thread = (row, slot); slot<3 -> q (c=slot), else k (c=slot-3)
    {
        int row = tid & 127;
        int slot = tid >> 7;
        int half = slot >= 3;
        int c = half ? slot - 3 : slot;
        int n = base + row;
        float xr[32];
        const float4* xrow = (const float4*)(xs + row * QSTR);
#pragma unroll
        for (int u = 0; u < 8; u++) ((float4*)xr)[u] = xrow[u];
        float c0 = coords[n * 3], c1 = coords[n * 3 + 1], c2 = coords[n * 3 + 2];
        const float* M = half ? Msm1 : Msm0;
        float acc[8];
#pragma unroll
        for (int h = 0; h < 8; h++) acc[h] = 0.f;
#pragma unroll 8
        for (int e = 0; e < 32; e++) {
            float xv = xr[e];
            const float* Mr = M + e * 24 + c * 8;
#pragma unroll
            for (int h = 0; h < 8; h++) acc[h] += xv * Mr[h];
        }
        float* dst = half ? g_kh : g_qh;
#pragma unroll
        for (int h = 0; h < 8; h++) {
            float sr0 = sw[h * 3] * c0, sr1 = sw[h * 3 + 1] * c1, sr2 = sw[h * 3 + 2] * c2;
            const float* al = alpha + h * 105 + c;
            acc[h] += sr0 * al[96] + sr1 * al[99] + sr2 * al[102];
            dst[(size_t)(c * 8 + h) * NPTS + n] = acc[h];
        }
        // per-warp min/max partials (warp = 32 rows of one slot)
        int rw = row >> 5;
#pragma unroll
        for (int h = 0; h < 8; h++) {
            float mn = acc[h], mx = acc[h];
#pragma unroll
            for (int o = 16; o > 0; o >>= 1) {
                mn = fminf(mn, __shfl_xor_sync(0xFFFFFFFFu, mn, o));
                mx = fmaxf(mx, __shfl_xor_sync(0xFFFFFFFFu, mx, o));
            }
            if ((tid & 31) == 0) {
                part_mn[c * 8 + h][half * 4 + rw] = mn;
                part_mx[c * 8 + h][half * 4 + rw] = mx;
            }
        }
    }
    __syncthreads();
    if (tid < CHN) {
        float mn = part_mn[tid][0], mx = part_mx[tid][0];
#pragma unroll
        for (int i = 1; i < 8; i++) {
            mn = fminf(mn, part_mn[tid][i]);
            mx = fmaxf(mx, part_mx[tid][i]);
        }
        g_pmn[tid * 256 + blockIdx.x] = encf(mn);
        g_pmx[tid * 256 + blockIdx.x] = encf(mx);
    }
}

// ---------------- local bitonic sort of 4096-elem chunks + fused key build + minmax reduce ----
template<int J>
__device__ __forceinline__ void shflp8(ull* r, int ibase, int l, int k_) {
#pragma unroll
    for (int s = 0; s < 8; s++) {
        int i = ibase + s * 32;
        bool up = ((i & k_) == 0);
        ull o = __shfl_xor_sync(0xFFFFFFFFu, r[s], J);
        bool kmin = (((l & J) == 0) == up);
        ull lo_ = (r[s] < o) ? r[s] : o;
        ull hi_ = (r[s] < o) ? o : r[s];
        r[s] = kmin ? lo_ : hi_;
    }
}
template<int JS>   // slot-pair pass, J = JS*32
__device__ __forceinline__ void slotp8(ull* r, int ibase, int k_) {
#pragma unroll
    for (int s = 0; s < 8; s++) {
        if (!(s & JS)) {
            int sp = s | JS;
            int i = ibase + s * 32;
            bool up = ((i & k_) == 0);
            if ((r[s] > r[sp]) == up) { ull t2 = r[s]; r[s] = r[sp]; r[sp] = t2; }
        }
    }
}
__device__ __forceinline__ void regpasses8(ull* r, int ibase, int l, int k_) {
    int half = k_ >> 1;
    if (half >= 128) slotp8<4>(r, ibase, k_);
    if (half >= 64)  slotp8<2>(r, ibase, k_);
    if (half >= 32)  slotp8<1>(r, ibase, k_);
    if (half >= 16)  shflp8<16>(r, ibase, l, k_);
    if (half >= 8)   shflp8<8>(r, ibase, l, k_);
    if (half >= 4)   shflp8<4>(r, ibase, l, k_);
    if (half >= 2)   shflp8<2>(r, ibase, l, k_);
    shflp8<1>(r, ibase, l, k_);
}
__device__ __forceinline__ void smem_pass4k(ull* s, int k_, int j_, int tid) {
#pragma unroll
    for (int p = 0; p < 4; p++) {
        int t = tid + p * 512;
        int i = ((t & ~(j_ - 1)) << 1) | (t & (j_ - 1));
        bool up = ((i & k_) == 0);
        ull a = s[i], b = s[i + j_];
        if ((a > b) == up) { s[i] = b; s[i + j_] = a; }
    }
}

__global__ void __launch_bounds__(512) k_sort_local4k(const int* __restrict__ shifts) {
    __shared__ ull s[4096];
    __shared__ unsigned redn[8], redx[8];
    __shared__ float s_hsv;
    size_t base = (size_t)blockIdx.x * 4096;
    int tid = threadIdx.x;
    int w = tid >> 5, l = tid & 31;
    int ibase = w * 256 + l;

    bool isQ = (base < (size_t)CHN * NPTS);
    size_t hoff = isQ ? base : base - (size_t)CHN * NPTS;
    int seg = (int)(hoff >> 15);

    // reduce per-block minmax partials for this segment
    if (tid < 256) {
        unsigned umn = g_pmn[seg * 256 + tid];
        unsigned umx = g_pmx[seg * 256 + tid];
        unsigned a = __reduce_min_sync(0xFFFFFFFFu, umn);
        unsigned b = __reduce_max_sync(0xFFFFFFFFu, umx);
        if ((tid & 31) == 0) { redn[tid >> 5] = a; redx[tid >> 5] = b; }
    }
    __syncthreads();
    if (tid == 0) {
        unsigned a = redn[0], b = redx[0];
#pragma unroll
        for (int i = 1; i < 8; i++) {
            if (redn[i] < a) a = redn[i];
            if (redx[i] > b) b = redx[i];
        }
        s_hsv = decf(b) - decf(a);
    }
    __syncthreads();
    float hsv = s_hsv;

    const float* hsrc = isQ ? g_qh : g_kh;
    ull r[8];
#pragma unroll
    for (int s_ = 0; s_ < 8; s_++) {
        size_t t = hoff + ibase + s_ * 32;
        float off = __fmul_rn((float)shifts[t], hsv);
        r[s_] = ((ull)encf(__fadd_rn(hsrc[t], off)) << 32) | (unsigned)(t & (NPTS - 1));
    }

    for (int k_ = 2; k_ <= 256; k_ <<= 1) regpasses8(r, ibase, l, k_);

    for (int k_ = 512; k_ <= 4096; k_ <<= 1) {
#pragma unroll
        for (int s_ = 0; s_ < 8; s_++) s[ibase + s_ * 32] = r[s_];
        __syncthreads();
        for (int j_ = k_ >> 1; j_ >= 256; j_ >>= 1) {
            smem_pass4k(s, k_, j_, tid);
            __syncthreads();
        }
#pragma unroll
        for (int s_ = 0; s_ < 8; s_++) r[s_] = s[ibase + s_ * 32];
        __syncthreads();
        regpasses8(r, ibase, l, k_);
    }
#pragma unroll
    for (int s_ = 0; s_ < 8; s_++) g_keys[base + ibase + s_ * 32] = r[s_];
}

// ---------------- merge-path merge pass (global, R5 version): runs of L -> 2L ----------------
__global__ void __launch_bounds__(256) k_mergepath(int L, int dir) {
    const ull* __restrict__ src = dir ? g_keys2 : g_keys;
    ull* __restrict__ dst = dir ? g_keys : g_keys2;
    size_t outbase = (size_t)blockIdx.x * 4096 + (size_t)threadIdx.x * 16;
    size_t pairBase = outbase & ~((size_t)(2 * L) - 1);
    const ull* A = src + pairBase;
    const ull* B = A + L;
    int p0 = (int)(outbase - pairBase);
    int lo = p0 > L ? p0 - L : 0;
    int hi = p0 < L ? p0 : L;
    while (lo < hi) {
        int m = (lo + hi) >> 1;
        if (A[m] <= B[p0 - 1 - m]) lo = m + 1; else hi = m;
    }
    int i = lo, j = p0 - lo;
    ull* d = dst + pairBase + p0;
    ull a = (i < L) ? A[i] : ~0ull;     // keys never equal ~0 (index bits < 2^15)
    ull b = (j < L) ? B[j] : ~0ull;
#pragma unroll
    for (int t = 0; t < 16; t++) {
        bool takeA = (a <= b);
        d[t] = takeA ? a : b;
        if (takeA) { i++; a = (i < L) ? A[i] : ~0ull; }
        else       { j++; b = (j < L) ? B[j] : ~0ull; }
    }
}

// ---------------- kernel 5: bucketed attention (256 thr, 2 buckets, 1 q/thread, 2j unroll) ----
__global__ void __launch_bounds__(256, 2) k_attn() {
    extern __shared__ float sm[];
    float* ks = sm;                    // [2][128][36]
    float* vs = sm + 9216;             // [2][128][32]
    float* ksq = sm + 9216 + 8192;     // [2][128]
    int seg = blockIdx.y;
    int h = seg & 7;
    int t = threadIdx.x;
    int tb = t >> 7;                   // bucket half
    int tq = t & 127;                  // q/load row
    int bucket = blockIdx.x * 2 + tb;

    const ull* kkey = g_keys2 + ((size_t)(CHN + seg)) * NPTS + bucket * BSZ;
    const ull* qkey = g_keys2 + (size_t)seg * NPTS + bucket * BSZ;

    {
        unsigned kidx = (unsigned)kkey[tq];
        const float4* kr = (const float4*)(g_khat + ((size_t)h * NPTS + kidx) * QSTR);
        float tmp[36];
#pragma unroll
        for (int u = 0; u < 9; u++) ((float4*)tmp)[u] = kr[u];
        float s2 = 0.f;
#pragma unroll
        for (int d = 0; d < 35; d++) s2 += tmp[d] * tmp[d];
        ksq[tb * 128 + tq] = -0.5f * s2;
        float* kd = ks + (tb * 128 + tq) * 36;
#pragma unroll
        for (int u = 0; u < 9; u++) ((float4*)kd)[u] = ((float4*)tmp)[u];
        const float4* vr = (const float4*)(g_v + ((size_t)h * NPTS + kidx) * DH);
        float* vd = vs + (tb * 128 + tq) * 32;
#pragma unroll
        for (int u = 0; u < 8; u++) ((float4*)vd)[u] = vr[u];
    }

    unsigned qidx = (unsigned)qkey[tq];
    ull qp[18];
    {
        const float4* qr = (const float4*)(g_qhat + ((size_t)h * NPTS + qidx) * QSTR);
#pragma unroll
        for (int u = 0; u < 9; u++) ((float4*)qp)[u] = qr[u];
    }
    float qsq = 0.f;
#pragma unroll
    for (int d = 0; d < 35; d++) qsq += ((float*)qp)[d] * ((float*)qp)[d];
    qsq *= -0.5f;

    ull acc[16];
#pragma unroll
    for (int p = 0; p < 16; p++) acc[p] = 0ull;
    float den = 0.f;
    __syncthreads();

    const float* ksb = ks + tb * 128 * 36;
    const float* vsb = vs + tb * 128 * 32;
    const float* ksqb = ksq + tb * 128;
    for (int j = 0; j < BSZ; j += 2) {
        const float4* k0 = (const float4*)(ksb + j * 36);
        const float4* k1 = (const float4*)(ksb + j * 36 + 36);
        ull d00 = 0ull, d01 = 0ull, d10 = 0ull, d11 = 0ull;
#pragma unroll
        for (int u = 0; u < 9; u++) {
            float4 c0 = k0[u];
            float4 c1 = k1[u];
            d00 = f2fma(qp[2 * u], lo2(c0), d00);
            d01 = f2fma(qp[2 * u + 1], hi2(c0), d01);
            d10 = f2fma(qp[2 * u], lo2(c1), d10);
            d11 = f2fma(qp[2 * u + 1], hi2(c1), d11);
        }
        float a0, a1, b0, b1;
        upk(f2add(d00, d01), a0, a1);
        upk(f2add(d10, d11), b0, b1);
        float2 kq = *(const float2*)&ksqb[j];
        float s0 = a0 + a1 + qsq + kq.x;
        float s1 = b0 + b1 + qsq + kq.y;
        float e0, e1;
        fexp2p(pk2(s0, s1), e0, e1);
        den += e0 + e1;
        ull e0d = pk2(e0, e0), e1d = pk2(e1, e1);
        const float4* v0 = (const float4*)(vsb + j * 32);
        const float4* v1 = (const float4*)(vsb + j * 32 + 32);
#pragma unroll
        for (int p = 0; p < 8; p++) {
            float4 vv0 = v0[p];
            float4 vv1 = v1[p];
            acc[2 * p] = f2fma(e0d, lo2(vv0), acc[2 * p]);
            acc[2 * p + 1] = f2fma(e0d, hi2(vv0), acc[2 * p + 1]);
            acc[2 * p] = f2fma(e1d, lo2(vv1), acc[2 * p]);
            acc[2 * p + 1] = f2fma(e1d, hi2(vv1), acc[2 * p + 1]);
        }
    }
    float* od = g_oscr + ((size_t)seg * NPTS + qidx) * DH;
#pragma unroll
    for (int p = 0; p < 8; p++) {
        float o0, o1, o2, o3;
        upk(acc[2 * p], o0, o1);
        upk(acc[2 * p + 1], o2, o3);
        ((float4*)od)[p] = make_float4(o0, o1, o2, o3);
    }
    g_dscr[(size_t)seg * NPTS + qidx] = den;
}

// ---------------- kernel 7: combine + out-proj + residual + LN2 + FF + residual ----------------
__global__ void __launch_bounds__(128) k_epilogue(
    const float* __restrict__ x, const float* __restrict__ ow,
    const float* __restrict__ ob, const float* __restrict__ n2w,
    const float* __restrict__ n2b, const float* __restrict__ f1w,
    const float* __restrict__ f1b, const float* __restrict__ f2w,
    const float* __restrict__ f2b, float* __restrict__ out) {
    __shared__ float ws[256 * 32];
    __shared__ float f1sT[32 * 32];
    __shared__ float f2s[32 * 32];
    __shared__ float cs[32 * 5];
    int tid = threadIdx.x;
    for (int i = tid; i < 8192; i += 128) ws[i] = ow[i];
    for (int i = tid; i < 1024; i += 128) {
        f1sT[(i & 31) * 32 + (i >> 5)] = f1w[i];
        f2s[i] = f2w[i];
    }
    if (tid < 32) {
        cs[tid] = ob[tid]; cs[32 + tid] = n2w[tid]; cs[64 + tid] = n2b[tid];
        cs[96 + tid] = f1b[tid]; cs[128 + tid] = f2b[tid];
    }
    __syncthreads();
    int n = blockIdx.x * 128 + tid;

    ull acc2[16];
#pragma unroll
    for (int p = 0; p < 16; p++) acc2[p] = pk2(cs[2 * p], cs[2 * p + 1]);

#pragma unroll 1
    for (int h = 0; h < 8; h++) {
        float den = g_dscr[(size_t)h * NPTS + n] +
                    g_dscr[(size_t)(8 + h) * NPTS + n] +
                    g_dscr[(size_t)(16 + h) * NPTS + n] + 3e-20f;
        float inv = 1.0f / den;
        const float4* oa = (const float4*)(g_oscr + ((size_t)h * NPTS + n) * DH);
        const float4* obp = (const float4*)(g_oscr + ((size_t)(8 + h) * NPTS + n) * DH);
        const float4* oc = (const float4*)(g_oscr + ((size_t)(16 + h) * NPTS + n) * DH);
#pragma unroll
        for (int p4 = 0; p4 < 8; p4++) {
            float4 a4 = oa[p4], b4 = obp[p4], c4 = oc[p4];
            float av[4];
            av[0] = (a4.x + b4.x + c4.x) * inv;
            av[1] = (a4.y + b4.y + c4.y) * inv;
            av[2] = (a4.z + b4.z + c4.z) * inv;
            av[3] = (a4.w + b4.w + c4.w) * inv;
            int j0 = h * 32 + p4 * 4;
#pragma unroll
            for (int u = 0; u < 4; u++) {
                ull ad = pk2(av[u], av[u]);
                const float4* wr2 = (const float4*)(ws + (j0 + u) * 32);
#pragma unroll
                for (int p = 0; p < 8; p++) {
                    float4 w4 = wr2[p];
                    acc2[2 * p] = f2fma(ad, lo2(w4), acc2[2 * p]);
                    acc2[2 * p + 1] = f2fma(ad, hi2(w4), acc2[2 * p + 1]);
                }
            }
        }
    }
    float acc[32];
#pragma unroll
    for (int p = 0; p < 16; p++) upk(acc2[p], acc[2 * p], acc[2 * p + 1]);

    float x2[32];
    const float4* xr = (const float4*)(x + (size_t)n * 32);
#pragma unroll
    for (int u = 0; u < 8; u++) {
        float4 xv = xr[u];
        x2[4 * u] = xv.x + acc[4 * u];
        x2[4 * u + 1] = xv.y + acc[4 * u + 1];
        x2[4 * u + 2] = xv.z + acc[4 * u + 2];
        x2[4 * u + 3] = xv.w + acc[4 * u + 3];
    }
    float mu = 0.f;
#pragma unroll
    for (int d = 0; d < 32; d++) mu += x2[d];
    mu *= (1.0f / 32.0f);
    float var = 0.f;
#pragma unroll
    for (int d = 0; d < 32; d++) { float dd = x2[d] - mu; var += dd * dd; }
    var *= (1.0f / 32.0f);
    float rs = rsqrtf(var + 1e-5f);
    float xn2[32];
#pragma unroll
    for (int d = 0; d < 32; d++)
        xn2[d] = (x2[d] - mu) * rs * cs[32 + d] + cs[64 + d];
    ull xp[16];
#pragma unroll
    for (int u = 0; u < 16; u++) xp[u] = pk2(xn2[2 * u], xn2[2 * u + 1]);
    float h1[32];
#pragma unroll 4
    for (int jj = 0; jj < 32; jj++) {
        const float4* fr = (const float4*)(f1sT + jj * 32);
        ull a0 = 0ull, a1 = 0ull;
#pragma unroll
        for (int u = 0; u < 8; u++) {
            float4 v4 = fr[u];
            a0 = f2fma(lo2(v4), xp[2 * u], a0);
            a1 = f2fma(hi2(v4), xp[2 * u + 1], a1);
        }
        float s0, s1;
        upk(f2add(a0, a1), s0, s1);
        float t2 = cs[96 + jj] + s0 + s1;
        h1[jj] = t2 / (1.0f + fexp(-t2));
    }
    ull o2[16];
#pragma unroll
    for (int p = 0; p < 16; p++) o2[p] = pk2(cs[128 + 2 * p], cs[128 + 2 * p + 1]);
#pragma unroll 4
    for (int jj = 0; jj < 32; jj++) {
        ull hd = pk2(h1[jj], h1[jj]);
        const float4* fr = (const float4*)(f2s + jj * 32);
#pragma unroll
        for (int p = 0; p < 8; p++) {
            float4 v4 = fr[p];
            o2[2 * p] = f2fma(hd, lo2(v4), o2[2 * p]);
            o2[2 * p + 1] = f2fma(hd, hi2(v4), o2[2 * p + 1]);
        }
    }
    float o[32];
#pragma unroll
    for (int p = 0; p < 16; p++) upk(o2[p], o[2 * p], o[2 * p + 1]);
    float4* orow = (float4*)(out + (size_t)n * 32);
#pragma unroll
    for (int u = 0; u < 8; u++)
        orow[u] = make_float4(x2[4 * u] + o[4 * u], x2[4 * u + 1] + o[4 * u + 1],
                              x2[4 * u + 2] + o[4 * u + 2], x2[4 * u + 3] + o[4 * u + 3]);
}

// ---------------- launcher ----------------
extern "C" void kernel_launch(void* const* d_in, const int* in_sizes, int n_in,
                              void* d_out, int out_size) {
    const float* x = (const float*)d_in[0];
    const float* coords = (const float*)d_in[1];
    const int* shifts = (const int*)d_in[2];
    const float* n1w = (const float*)d_in[3];
    const float* n1b = (const float*)d_in[4];
    const float* wq = (const float*)d_in[5];
    const float* wk = (const float*)d_in[6];
    const float* wv = (const float*)d_in[7];
    const float* wr = (const float*)d_in[8];
    const float* alpha = (const float*)d_in[9];
    const float* ow = (const float*)d_in[10];
    const float* ob = (const float*)d_in[11];
    const float* n2w = (const float*)d_in[12];
    const float* n2b = (const float*)d_in[13];
    const float* f1w = (const float*)d_in[14];
    const float* f1b = (const float*)d_in[15];
    const float* f2w = (const float*)d_in[16];
    const float* f2b = (const float*)d_in[17];
    float* out = (float*)d_out;

    cudaFuncSetAttribute(k_attn, cudaFuncAttributeMaxDynamicSharedMemorySize, 71680);

    // launch 0: LN + QKV + tails + hash + minmax partials
    k_ln_qkv<<<NPTS / 128, 768>>>(x, n1w, n1b, wq, wk, wv, wr, coords, alpha);

    const int TOT = 2 * CHN * NPTS;
    // launch 1: key build + local sort (reduces minmax partials first)
    k_sort_local4k<<<TOT / 4096, 512>>>(shifts);
    // launches 2-4: merge passes
    k_mergepath<<<TOT / 4096, 256>>>(4096, 0);
    k_mergepath<<<TOT / 4096, 256>>>(8192, 1);
    k_mergepath<<<TOT / 4096, 256>>>(16384, 0);

    // launch 5 (ncu capture slot): attention
    k_attn<<<dim3(NBK / 2, CHN), 256, 71680>>>();
    // launch 6: epilogue
    k_epilogue<<<NPTS / 128, 128>>>(x, ow, ob, n2w, n2b, f1w, f1b, f2w, f2b, out);
}

// round 9
// speedup vs baseline: 1.1316x; 1.0021x over previous
#include <cuda_runtime.h>
#include <cstdint>

#define NPTS 32768
#define DH 32
#define NH 8
#define NC 3
#define BSZ 128
#define NBK 256
#define CHN 24          // NC*NH
#define QSTR 36         // padded row stride for 35-dim hat vectors

typedef unsigned long long ull;

// ---------------- scratch (static device globals; no allocations) ----------------
__device__ float g_qhat[(size_t)NH * NPTS * QSTR];
__device__ float g_khat[(size_t)NH * NPTS * QSTR];
__device__ float g_v[(size_t)NH * NPTS * DH];
__device__ float g_qh[(size_t)CHN * NPTS];
__device__ float g_kh[(size_t)CHN * NPTS];
__device__ ull   g_keys[(size_t)2 * CHN * NPTS];
__device__ ull   g_keys2[(size_t)2 * CHN * NPTS];
__device__ unsigned g_pmn[CHN * 256];   // per-block min partials (encf)
__device__ unsigned g_pmx[CHN * 256];   // per-block max partials (encf)
__device__ float g_oscr[(size_t)CHN * NPTS * DH];
__device__ float g_dscr[(size_t)CHN * NPTS];

// ---------------- f32x2 packed helpers ----------------
__device__ __forceinline__ ull pk2(float a, float b) {
    ull r; asm("mov.b64 %0, {%1, %2};" : "=l"(r) : "f"(a), "f"(b)); return r;
}
__device__ __forceinline__ void upk(ull p, float& a, float& b) {
    asm("mov.b64 {%0, %1}, %2;" : "=f"(a), "=f"(b) : "l"(p));
}
__device__ __forceinline__ ull f2fma(ull a, ull b, ull c) {
    ull d; asm("fma.rn.f32x2 %0, %1, %2, %3;" : "=l"(d) : "l"(a), "l"(b), "l"(c)); return d;
}
__device__ __forceinline__ ull f2add(ull a, ull b) {
    ull d; asm("add.rn.f32x2 %0, %1, %2;" : "=l"(d) : "l"(a), "l"(b)); return d;
}
__device__ __forceinline__ ull lo2(float4 v) { return pk2(v.x, v.y); }
__device__ __forceinline__ ull hi2(float4 v) { return pk2(v.z, v.w); }

// ---------------- sort helpers ----------------
__device__ __forceinline__ unsigned encf(float f) {
    unsigned u = __float_as_uint(f);
    return (u & 0x80000000u) ? ~u : (u | 0x80000000u);
}
__device__ __forceinline__ float decf(unsigned u) {
    return (u & 0x80000000u) ? __uint_as_float(u ^ 0x80000000u)
                             : __uint_as_float(~u);
}

// ---------------- kernel 1: LN + QKV + coords tails + LSH hash + minmax partials ----------------
__global__ void __launch_bounds__(768) k_ln_qkv(
    const float* __restrict__ x, const float* __restrict__ n1w,
    const float* __restrict__ n1b, const float* __restrict__ wq,
    const float* __restrict__ wk, const float* __restrict__ wv,
    const float* __restrict__ wr, const float* __restrict__ coords,
    const float* __restrict__ alpha) {
    __shared__ float xs[128 * QSTR];
    __shared__ float Msm0[32 * 24];
    __shared__ float Msm1[32 * 24];
    __shared__ float sw[24];
    __shared__ float part_mn[24][8];
    __shared__ float part_mx[24][8];
    int base = blockIdx.x * 128;
    int tid = threadIdx.x;

    if (tid < CHN) {
        int h = tid / 3, r = tid % 3;
        float qw = 0.f;
        for (int k = 0; k < 8; k++) {
            float s = 0.f;
            for (int d = 0; d < 32; d++) s += wr[(h * 32 + d) * 24 + r * 8 + k];
            qw += expf(fminf(s, 50.f));
        }
        sw[tid] = sqrtf(2.f * qw);
    }
    {
        int ch = tid >> 5, e = tid & 31;
        int c = ch >> 3, h = ch & 7;
        float mq = 0.f, mk = 0.f;
        const float* wqr = wq + e * 256 + h * 32;
        const float* wkr = wk + e * 256 + h * 32;
        const float* al = alpha + h * 105 + c;
#pragma unroll 8
        for (int d = 0; d < 32; d++) {
            float a = al[d * 3];
            mq += wqr[d] * a;
            mk += wkr[d] * a;
        }
        Msm0[e * 24 + ch] = mq;
        Msm1[e * 24 + ch] = mk;
    }
    __syncthreads();

    if (tid < 128) {
        int n = base + tid;
        float r[32];
        const float4* xr = (const float4*)(x + (size_t)n * 32);
#pragma unroll
        for (int u = 0; u < 8; u++) {
            float4 v4 = xr[u];
            r[4 * u] = v4.x; r[4 * u + 1] = v4.y; r[4 * u + 2] = v4.z; r[4 * u + 3] = v4.w;
        }
        float mu = 0.f;
#pragma unroll
        for (int d = 0; d < 32; d++) mu += r[d];
        mu *= (1.0f / 32.0f);
        float var = 0.f;
#pragma unroll
        for (int d = 0; d < 32; d++) { float dd = r[d] - mu; var += dd * dd; }
        var *= (1.0f / 32.0f);
        float rs = rsqrtf(var + 1e-5f);
#pragma unroll
        for (int d = 0; d < 32; d++)
            xs[tid * QSTR + d] = (r[d] - mu) * rs * n1w[d] + n1b[d];
    }
    __syncthreads();

    {
        int proj = tid >> 8, jj = tid & 255;
        const float* W = (proj == 0) ? wq : (proj == 1) ? wk : wv;
        ull wpk[16];
#pragma unroll
        for (int d = 0; d < 16; d++)
            wpk[d] = pk2(W[(2 * d) * 256 + jj], W[(2 * d + 1) * 256 + jj]);
        int h = jj >> 5, d0 = jj & 31;
        float* dst;
        int stride;
        if (proj == 0) { dst = g_qhat; stride = QSTR; }
        else if (proj == 1) { dst = g_khat; stride = QSTR; }
        else { dst = g_v; stride = DH; }
        for (int r = 0; r < 128; r++) {
            const float4* xr = (const float4*)(xs + r * QSTR);
            ull a0 = 0, a1 = 0;
#pragma unroll
            for (int u = 0; u < 8; u++) {
                float4 v4 = xr[u];
                a0 = f2fma(lo2(v4), wpk[2 * u], a0);
                a1 = f2fma(hi2(v4), wpk[2 * u + 1], a1);
            }
            float s0, s1;
            upk(f2add(a0, a1), s0, s1);
            dst[((size_t)h * NPTS + (base + r)) * stride + d0] = s0 + s1;
        }
    }
    if (tid < 128) {
        int n = base + tid;
        float c0 = coords[n * 3], c1 = coords[n * 3 + 1], c2 = coords[n * 3 + 2];
#pragma unroll
        for (int h = 0; h < 8; h++) {
            float4 tail = make_float4(sw[h * 3] * c0, sw[h * 3 + 1] * c1,
                                      sw[h * 3 + 2] * c2, 0.f);
            *(float4*)(g_qhat + ((size_t)h * NPTS + n) * QSTR + 32) = tail;
            *(float4*)(g_khat + ((size_t)h * NPTS + n) * QSTR + 32) = tail;
        }
    }

    {
        int row = tid & 127;
        int slot = tid >> 7;
        int half = slot >= 3;
        int c = half ? slot - 3 : slot;
        int n = base + row;
        float xr[32];
        const float4* xrow = (const float4*)(xs + row * QSTR);
#pragma unroll
        for (int u = 0; u < 8; u++) ((float4*)xr)[u] = xrow[u];
        float c0 = coords[n * 3], c1 = coords[n * 3 + 1], c2 = coords[n * 3 + 2];
        const float* M = half ? Msm1 : Msm0;
        float acc[8];
#pragma unroll
        for (int h = 0; h < 8; h++) acc[h] = 0.f;
#pragma unroll 8
        for (int e = 0; e < 32; e++) {
            float xv = xr[e];
            const float* Mr = M + e * 24 + c * 8;
#pragma unroll
            for (int h = 0; h < 8; h++) acc[h] += xv * Mr[h];
        }
        float* dst = half ? g_kh : g_qh;
#pragma unroll
        for (int h = 0; h < 8; h++) {
            float sr0 = sw[h * 3] * c0, sr1 = sw[h * 3 + 1] * c1, sr2 = sw[h * 3 + 2] * c2;
            const float* al = alpha + h * 105 + c;
            acc[h] += sr0 * al[96] + sr1 * al[99] + sr2 * al[102];
            dst[(size_t)(c * 8 + h) * NPTS + n] = acc[h];
        }
        int rw = row >> 5;
#pragma unroll
        for (int h = 0; h < 8; h++) {
            float mn = acc[h], mx = acc[h];
#pragma unroll
            for (int o = 16; o > 0; o >>= 1) {
                mn = fminf(mn, __shfl_xor_sync(0xFFFFFFFFu, mn, o));
                mx = fmaxf(mx, __shfl_xor_sync(0xFFFFFFFFu, mx, o));
            }
            if ((tid & 31) == 0) {
                part_mn[c * 8 + h][half * 4 + rw] = mn;
                part_mx[c * 8 + h][half * 4 + rw] = mx;
            }
        }
    }
    __syncthreads();
    if (tid < CHN) {
        float mn = part_mn[tid][0], mx = part_mx[tid][0];
#pragma unroll
        for (int i = 1; i < 8; i++) {
            mn = fminf(mn, part_mn[tid][i]);
            mx = fmaxf(mx, part_mx[tid][i]);
        }
        g_pmn[tid * 256 + blockIdx.x] = encf(mn);
        g_pmx[tid * 256 + blockIdx.x] = encf(mx);
    }
}

// ---------------- local bitonic sort of 4096-elem chunks + fused key build + minmax reduce ----
template<int J>
__device__ __forceinline__ void shflp8(ull* r, int ibase, int l, int k_) {
#pragma unroll
    for (int s = 0; s < 8; s++) {
        int i = ibase + s * 32;
        bool up = ((i & k_) == 0);
        ull o = __shfl_xor_sync(0xFFFFFFFFu, r[s], J);
        bool kmin = (((l & J) == 0) == up);
        ull lo_ = (r[s] < o) ? r[s] : o;
        ull hi_ = (r[s] < o) ? o : r[s];
        r[s] = kmin ? lo_ : hi_;
    }
}
template<int JS>   // slot-pair pass, J = JS*32
__device__ __forceinline__ void slotp8(ull* r, int ibase, int k_) {
#pragma unroll
    for (int s = 0; s < 8; s++) {
        if (!(s & JS)) {
            int sp = s | JS;
            int i = ibase + s * 32;
            bool up = ((i & k_) == 0);
            if ((r[s] > r[sp]) == up) { ull t2 = r[s]; r[s] = r[sp]; r[sp] = t2; }
        }
    }
}
__device__ __forceinline__ void regpasses8(ull* r, int ibase, int l, int k_) {
    int half = k_ >> 1;
    if (half >= 128) slotp8<4>(r, ibase, k_);
    if (half >= 64)  slotp8<2>(r, ibase, k_);
    if (half >= 32)  slotp8<1>(r, ibase, k_);
    if (half >= 16)  shflp8<16>(r, ibase, l, k_);
    if (half >= 8)   shflp8<8>(r, ibase, l, k_);
    if (half >= 4)   shflp8<4>(r, ibase, l, k_);
    if (half >= 2)   shflp8<2>(r, ibase, l, k_);
    shflp8<1>(r, ibase, l, k_);
}
__device__ __forceinline__ void smem_pass4k(ull* s, int k_, int j_, int tid) {
#pragma unroll
    for (int p = 0; p < 4; p++) {
        int t = tid + p * 512;
        int i = ((t & ~(j_ - 1)) << 1) | (t & (j_ - 1));
        bool up = ((i & k_) == 0);
        ull a = s[i], b = s[i + j_];
        if ((a > b) == up) { s[i] = b; s[i + j_] = a; }
    }
}

__global__ void __launch_bounds__(512) k_sort_local4k(const int* __restrict__ shifts) {
    __shared__ ull s[4096];
    __shared__ unsigned redn[8], redx[8];
    __shared__ float s_hsv;
    size_t base = (size_t)blockIdx.x * 4096;
    int tid = threadIdx.x;
    int w = tid >> 5, l = tid & 31;
    int ibase = w * 256 + l;

    bool isQ = (base < (size_t)CHN * NPTS);
    size_t hoff = isQ ? base : base - (size_t)CHN * NPTS;
    int seg = (int)(hoff >> 15);

    if (tid < 256) {
        unsigned umn = g_pmn[seg * 256 + tid];
        unsigned umx = g_pmx[seg * 256 + tid];
        unsigned a = __reduce_min_sync(0xFFFFFFFFu, umn);
        unsigned b = __reduce_max_sync(0xFFFFFFFFu, umx);
        if ((tid & 31) == 0) { redn[tid >> 5] = a; redx[tid >> 5] = b; }
    }
    __syncthreads();
    if (tid == 0) {
        unsigned a = redn[0], b = redx[0];
#pragma unroll
        for (int i = 1; i < 8; i++) {
            if (redn[i] < a) a = redn[i];
            if (redx[i] > b) b = redx[i];
        }
        s_hsv = decf(b) - decf(a);
    }
    __syncthreads();
    float hsv = s_hsv;

    const float* hsrc = isQ ? g_qh : g_kh;
    ull r[8];
#pragma unroll
    for (int s_ = 0; s_ < 8; s_++) {
        size_t t = hoff + ibase + s_ * 32;
        float off = __fmul_rn((float)shifts[t], hsv);
        r[s_] = ((ull)encf(__fadd_rn(hsrc[t], off)) << 32) | (unsigned)(t & (NPTS - 1));
    }

    for (int k_ = 2; k_ <= 256; k_ <<= 1) regpasses8(r, ibase, l, k_);

    for (int k_ = 512; k_ <= 4096; k_ <<= 1) {
#pragma unroll
        for (int s_ = 0; s_ < 8; s_++) s[ibase + s_ * 32] = r[s_];
        __syncthreads();
        for (int j_ = k_ >> 1; j_ >= 256; j_ >>= 1) {
            smem_pass4k(s, k_, j_, tid);
            __syncthreads();
        }
#pragma unroll
        for (int s_ = 0; s_ < 8; s_++) r[s_] = s[ibase + s_ * 32];
        __syncthreads();
        regpasses8(r, ibase, l, k_);
    }
#pragma unroll
    for (int s_ = 0; s_ < 8; s_++) g_keys[base + ibase + s_ * 32] = r[s_];
}

// ---------------- merge-path merge pass (global): runs of L -> 2L ----------------
__global__ void __launch_bounds__(256) k_mergepath(int L, int dir) {
    const ull* __restrict__ src = dir ? g_keys2 : g_keys;
    ull* __restrict__ dst = dir ? g_keys : g_keys2;
    size_t outbase = (size_t)blockIdx.x * 4096 + (size_t)threadIdx.x * 16;
    size_t pairBase = outbase & ~((size_t)(2 * L) - 1);
    const ull* A = src + pairBase;
    const ull* B = A + L;
    int p0 = (int)(outbase - pairBase);
    int lo = p0 > L ? p0 - L : 0;
    int hi = p0 < L ? p0 : L;
    while (lo < hi) {
        int m = (lo + hi) >> 1;
        if (A[m] <= B[p0 - 1 - m]) lo = m + 1; else hi = m;
    }
    int i = lo, j = p0 - lo;
    ull* d = dst + pairBase + p0;
    ull a = (i < L) ? A[i] : ~0ull;
    ull b = (j < L) ? B[j] : ~0ull;
#pragma unroll
    for (int t = 0; t < 16; t++) {
        bool takeA = (a <= b);
        d[t] = takeA ? a : b;
        if (takeA) { i++; a = (i < L) ? A[i] : ~0ull; }
        else       { j++; b = (j < L) ? B[j] : ~0ull; }
    }
}

// ---------------- kernel 5: bucketed attention (256 thr, 2 buckets, 1 q/thread, 2j unroll) ----
// exp now via MUFU (__expf): removes the 11-deep FMA chain from the critical path.
__global__ void __launch_bounds__(256, 2) k_attn() {
    extern __shared__ float sm[];
    float* ks = sm;                    // [2][128][36]
    float* vs = sm + 9216;             // [2][128][32]
    float* ksq = sm + 9216 + 8192;     // [2][128]
    int seg = blockIdx.y;
    int h = seg & 7;
    int t = threadIdx.x;
    int tb = t >> 7;                   // bucket half
    int tq = t & 127;                  // q/load row
    int bucket = blockIdx.x * 2 + tb;

    const ull* kkey = g_keys2 + ((size_t)(CHN + seg)) * NPTS + bucket * BSZ;
    const ull* qkey = g_keys2 + (size_t)seg * NPTS + bucket * BSZ;

    {
        unsigned kidx = (unsigned)kkey[tq];
        const float4* kr = (const float4*)(g_khat + ((size_t)h * NPTS + kidx) * QSTR);
        float tmp[36];
#pragma unroll
        for (int u = 0; u < 9; u++) ((float4*)tmp)[u] = kr[u];
        float s2 = 0.f;
#pragma unroll
        for (int d = 0; d < 35; d++) s2 += tmp[d] * tmp[d];
        ksq[tb * 128 + tq] = -0.5f * s2;
        float* kd = ks + (tb * 128 + tq) * 36;
#pragma unroll
        for (int u = 0; u < 9; u++) ((float4*)kd)[u] = ((float4*)tmp)[u];
        const float4* vr = (const float4*)(g_v + ((size_t)h * NPTS + kidx) * DH);
        float* vd = vs + (tb * 128 + tq) * 32;
#pragma unroll
        for (int u = 0; u < 8; u++) ((float4*)vd)[u] = vr[u];
    }

    unsigned qidx = (unsigned)qkey[tq];
    ull qp[18];
    {
        const float4* qr = (const float4*)(g_qhat + ((size_t)h * NPTS + qidx) * QSTR);
#pragma unroll
        for (int u = 0; u < 9; u++) ((float4*)qp)[u] = qr[u];
    }
    float qsq = 0.f;
#pragma unroll
    for (int d = 0; d < 35; d++) qsq += ((float*)qp)[d] * ((float*)qp)[d];
    qsq *= -0.5f;

    ull acc[16];
#pragma unroll
    for (int p = 0; p < 16; p++) acc[p] = 0ull;
    float den = 0.f;
    __syncthreads();

    const float* ksb = ks + tb * 128 * 36;
    const float* vsb = vs + tb * 128 * 32;
    const float* ksqb = ksq + tb * 128;
    for (int j = 0; j < BSZ; j += 2) {
        const float4* k0 = (const float4*)(ksb + j * 36);
        const float4* k1 = (const float4*)(ksb + j * 36 + 36);
        ull d00 = 0ull, d01 = 0ull, d10 = 0ull, d11 = 0ull;
#pragma unroll
        for (int u = 0; u < 9; u++) {
            float4 c0 = k0[u];
            float4 c1 = k1[u];
            d00 = f2fma(qp[2 * u], lo2(c0), d00);
            d01 = f2fma(qp[2 * u + 1], hi2(c0), d01);
            d10 = f2fma(qp[2 * u], lo2(c1), d10);
            d11 = f2fma(qp[2 * u + 1], hi2(c1), d11);
        }
        float a0, a1, b0, b1;
        upk(f2add(d00, d01), a0, a1);
        upk(f2add(d10, d11), b0, b1);
        float2 kq = *(const float2*)&ksqb[j];
        float s0 = fminf(a0 + a1 + qsq + kq.x, 0.f);
        float s1 = fminf(b0 + b1 + qsq + kq.y, 0.f);
        float e0 = __expf(s0);
        float e1 = __expf(s1);
        den += e0 + e1;
        ull e0d = pk2(e0, e0), e1d = pk2(e1, e1);
        const float4* v0 = (const float4*)(vsb + j * 32);
        const float4* v1 = (const float4*)(vsb + j * 32 + 32);
#pragma unroll
        for (int p = 0; p < 8; p++) {
            float4 vv0 = v0[p];
            float4 vv1 = v1[p];
            acc[2 * p] = f2fma(e0d, lo2(vv0), acc[2 * p]);
            acc[2 * p + 1] = f2fma(e0d, hi2(vv0), acc[2 * p + 1]);
            acc[2 * p] = f2fma(e1d, lo2(vv1), acc[2 * p]);
            acc[2 * p + 1] = f2fma(e1d, hi2(vv1), acc[2 * p + 1]);
        }
    }
    float* od = g_oscr + ((size_t)seg * NPTS + qidx) * DH;
#pragma unroll
    for (int p = 0; p < 8; p++) {
        float o0, o1, o2, o3;
        upk(acc[2 * p], o0, o1);
        upk(acc[2 * p + 1], o2, o3);
        ((float4*)od)[p] = make_float4(o0, o1, o2, o3);
    }
    g_dscr[(size_t)seg * NPTS + qidx] = den;
}

// ---------------- kernel 7: combine + out-proj + residual + LN2 + FF + residual ----------------
__global__ void __launch_bounds__(128) k_epilogue(
    const float* __restrict__ x, const float* __restrict__ ow,
    const float* __restrict__ ob, const float* __restrict__ n2w,
    const float* __restrict__ n2b, const float* __restrict__ f1w,
    const float* __restrict__ f1b, const float* __restrict__ f2w,
    const float* __restrict__ f2b, float* __restrict__ out) {
    __shared__ float ws[256 * 32];
    __shared__ float f1sT[32 * 32];
    __shared__ float f2s[32 * 32];
    __shared__ float cs[32 * 5];
    int tid = threadIdx.x;
    for (int i = tid; i < 8192; i += 128) ws[i] = ow[i];
    for (int i = tid; i < 1024; i += 128) {
        f1sT[(i & 31) * 32 + (i >> 5)] = f1w[i];
        f2s[i] = f2w[i];
    }
    if (tid < 32) {
        cs[tid] = ob[tid]; cs[32 + tid] = n2w[tid]; cs[64 + tid] = n2b[tid];
        cs[96 + tid] = f1b[tid]; cs[128 + tid] = f2b[tid];
    }
    __syncthreads();
    int n = blockIdx.x * 128 + tid;

    ull acc2[16];
#pragma unroll
    for (int p = 0; p < 16; p++) acc2[p] = pk2(cs[2 * p], cs[2 * p + 1]);

#pragma unroll 1
    for (int h = 0; h < 8; h++) {
        float den = g_dscr[(size_t)h * NPTS + n] +
                    g_dscr[(size_t)(8 + h) * NPTS + n] +
                    g_dscr[(size_t)(16 + h) * NPTS + n] + 3e-20f;
        float inv = 1.0f / den;
        const float4* oa = (const float4*)(g_oscr + ((size_t)h * NPTS + n) * DH);
        const float4* obp = (const float4*)(g_oscr + ((size_t)(8 + h) * NPTS + n) * DH);
        const float4* oc = (const float4*)(g_oscr + ((size_t)(16 + h) * NPTS + n) * DH);
#pragma unroll
        for (int p4 = 0; p4 < 8; p4++) {
            float4 a4 = oa[p4], b4 = obp[p4], c4 = oc[p4];
            float av[4];
            av[0] = (a4.x + b4.x + c4.x) * inv;
            av[1] = (a4.y + b4.y + c4.y) * inv;
            av[2] = (a4.z + b4.z + c4.z) * inv;
            av[3] = (a4.w + b4.w + c4.w) * inv;
            int j0 = h * 32 + p4 * 4;
#pragma unroll
            for (int u = 0; u < 4; u++) {
                ull ad = pk2(av[u], av[u]);
                const float4* wr2 = (const float4*)(ws + (j0 + u) * 32);
#pragma unroll
                for (int p = 0; p < 8; p++) {
                    float4 w4 = wr2[p];
                    acc2[2 * p] = f2fma(ad, lo2(w4), acc2[2 * p]);
                    acc2[2 * p + 1] = f2fma(ad, hi2(w4), acc2[2 * p + 1]);
                }
            }
        }
    }
    float acc[32];
#pragma unroll
    for (int p = 0; p < 16; p++) upk(acc2[p], acc[2 * p], acc[2 * p + 1]);

    float x2[32];
    const float4* xr = (const float4*)(x + (size_t)n * 32);
#pragma unroll
    for (int u = 0; u < 8; u++) {
        float4 xv = xr[u];
        x2[4 * u] = xv.x + acc[4 * u];
        x2[4 * u + 1] = xv.y + acc[4 * u + 1];
        x2[4 * u + 2] = xv.z + acc[4 * u + 2];
        x2[4 * u + 3] = xv.w + acc[4 * u + 3];
    }
    float mu = 0.f;
#pragma unroll
    for (int d = 0; d < 32; d++) mu += x2[d];
    mu *= (1.0f / 32.0f);
    float var = 0.f;
#pragma unroll
    for (int d = 0; d < 32; d++) { float dd = x2[d] - mu; var += dd * dd; }
    var *= (1.0f / 32.0f);
    float rs = rsqrtf(var + 1e-5f);
    float xn2[32];
#pragma unroll
    for (int d = 0; d < 32; d++)
        xn2[d] = (x2[d] - mu) * rs * cs[32 + d] + cs[64 + d];
    ull xp[16];
#pragma unroll
    for (int u = 0; u < 16; u++) xp[u] = pk2(xn2[2 * u], xn2[2 * u + 1]);
    float h1[32];
#pragma unroll 4
    for (int jj = 0; jj < 32; jj++) {
        const float4* fr = (const float4*)(f1sT + jj * 32);
        ull a0 = 0ull, a1 = 0ull;
#pragma unroll
        for (int u = 0; u < 8; u++) {
            float4 v4 = fr[u];
            a0 = f2fma(lo2(v4), xp[2 * u], a0);
            a1 = f2fma(hi2(v4), xp[2 * u + 1], a1);
        }
        float s0, s1;
        upk(f2add(a0, a1), s0, s1);
        float t2 = cs[96 + jj] + s0 + s1;
        h1[jj] = t2 / (1.0f + __expf(-t2));
    }
    ull o2[16];
#pragma unroll
    for (int p = 0; p < 16; p++) o2[p] = pk2(cs[128 + 2 * p], cs[128 + 2 * p + 1]);
#pragma unroll 4
    for (int jj = 0; jj < 32; jj++) {
        ull hd = pk2(h1[jj], h1[jj]);
        const float4* fr = (const float4*)(f2s + jj * 32);
#pragma unroll
        for (int p = 0; p < 8; p++) {
            float4 v4 = fr[p];
            o2[2 * p] = f2fma(hd, lo2(v4), o2[2 * p]);
            o2[2 * p + 1] = f2fma(hd, hi2(v4), o2[2 * p + 1]);
        }
    }
    float o[32];
#pragma unroll
    for (int p = 0; p < 16; p++) upk(o2[p], o[2 * p], o[2 * p + 1]);
    float4* orow = (float4*)(out + (size_t)n * 32);
#pragma unroll
    for (int u = 0; u < 8; u++)
        orow[u] = make_float4(x2[4 * u] + o[4 * u], x2[4 * u + 1] + o[4 * u + 1],
                              x2[4 * u + 2] + o[4 * u + 2], x2[4 * u + 3] + o[4 * u + 3]);
}

// ---------------- launcher ----------------
extern "C" void kernel_launch(void* const* d_in, const int* in_sizes, int n_in,
                              void* d_out, int out_size) {
    const float* x = (const float*)d_in[0];
    const float* coords = (const float*)d_in[1];
    const int* shifts = (const int*)d_in[2];
    const float* n1w = (const float*)d_in[3];
    const float* n1b = (const float*)d_in[4];
    const float* wq = (const float*)d_in[5];
    const float* wk = (const float*)d_in[6];
    const float* wv = (const float*)d_in[7];
    const float* wr = (const float*)d_in[8];
    const float* alpha = (const float*)d_in[9];
    const float* ow = (const float*)d_in[10];
    const float* ob = (const float*)d_in[11];
    const float* n2w = (const float*)d_in[12];
    const float* n2b = (const float*)d_in[13];
    const float* f1w = (const float*)d_in[14];
    const float* f1b = (const float*)d_in[15];
    const float* f2w = (const float*)d_in[16];
    const float* f2b = (const float*)d_in[17];
    float* out = (float*)d_out;

    cudaFuncSetAttribute(k_attn, cudaFuncAttributeMaxDynamicSharedMemorySize, 71680);

    k_ln_qkv<<<NPTS / 128, 768>>>(x, n1w, n1b, wq, wk, wv, wr, coords, alpha);

    const int TOT = 2 * CHN * NPTS;
    k_sort_local4k<<<TOT / 4096, 512>>>(shifts);
    k_mergepath<<<TOT / 4096, 256>>>(4096, 0);
    k_mergepath<<<TOT / 4096, 256>>>(8192, 1);
    k_mergepath<<<TOT / 4096, 256>>>(16384, 0);

    k_attn<<<dim3(NBK / 2, CHN), 256, 71680>>>();
    k_epilogue<<<NPTS / 128, 128>>>(x, ow, ob, n2w, n2b, f1w, f1b, f2w, f2b, out);
}

// round 12
// speedup vs baseline: 1.4613x; 1.2915x over previous
#include <cuda_runtime.h>
#include <cstdint>

#define NPTS 32768
#define DH 32
#define NH 8
#define BSZ 128
#define NBK 256
#define CHN 24
#define QSTR 36

typedef unsigned long long ull;

__device__ float g_qhat[(size_t)NH * NPTS * QSTR];
__device__ float g_khat[(size_t)NH * NPTS * QSTR];
__device__ float g_v[(size_t)NH * NPTS * DH];
__device__ float g_qh[(size_t)CHN * NPTS];
__device__ float g_kh[(size_t)CHN * NPTS];
__device__ ull   g_keys[(size_t)2 * CHN * NPTS];
__device__ ull   g_keys2[(size_t)2 * CHN * NPTS];
__device__ unsigned g_pmn[CHN * 256];
__device__ unsigned g_pmx[CHN * 256];
__device__ float g_oscr[(size_t)CHN * NPTS * DH];
__device__ float g_dscr[(size_t)CHN * NPTS];

// ---------------- f32x2 helpers ----------------
__device__ __forceinline__ ull pk2(float a, float b) {
    ull r; asm("mov.b64 %0, {%1, %2};" : "=l"(r) : "f"(a), "f"(b)); return r;
}
__device__ __forceinline__ void upk(ull p, float& a, float& b) {
    asm("mov.b64 {%0, %1}, %2;" : "=f"(a), "=f"(b) : "l"(p));
}
__device__ __forceinline__ ull f2fma(ull a, ull b, ull c) {
    ull d; asm("fma.rn.f32x2 %0, %1, %2, %3;" : "=l"(d) : "l"(a), "l"(b), "l"(c)); return d;
}
__device__ __forceinline__ ull f2add(ull a, ull b) {
    ull d; asm("add.rn.f32x2 %0, %1, %2;" : "=l"(d) : "l"(a), "l"(b)); return d;
}
__device__ __forceinline__ ull lo2(float4 v) { return pk2(v.x, v.y); }
__device__ __forceinline__ ull hi2(float4 v) { return pk2(v.z, v.w); }

__device__ __forceinline__ unsigned encf(float f) {
    unsigned u = __float_as_uint(f);
    return (u & 0x80000000u) ? ~u : (u | 0x80000000u);
}
__device__ __forceinline__ float decf(unsigned u) {
    return (u & 0x80000000u) ? __uint_as_float(u ^ 0x80000000u)
                             : __uint_as_float(~u);
}
__device__ __forceinline__ float tf32r(float x) {
    uint32_t u; asm("cvt.rna.tf32.f32 %0, %1;" : "=r"(u) : "f"(x));
    return __uint_as_float(u);
}
#define MMA_TF32(c, a0, a1, a2, a3, b0, b1) \
    asm volatile("mma.sync.aligned.m16n8k8.row.col.f32.tf32.tf32.f32 " \
        "{%0,%1,%2,%3}, {%4,%5,%6,%7}, {%8,%9}, {%0,%1,%2,%3};" \
        : "+f"((c)[0]), "+f"((c)[1]), "+f"((c)[2]), "+f"((c)[3]) \
        : "r"(a0), "r"(a1), "r"(a2), "r"(a3), "r"(b0), "r"(b1))

// ---------------- kernel 1: LN + QKV + tails + hash + minmax partials ----------
__global__ void __launch_bounds__(768) k_ln_qkv(
    const float* __restrict__ x, const float* __restrict__ n1w,
    const float* __restrict__ n1b, const float* __restrict__ wq,
    const float* __restrict__ wk, const float* __restrict__ wv,
    const float* __restrict__ wr, const float* __restrict__ coords,
    const float* __restrict__ alpha) {
    __shared__ float xs[128 * QSTR];
    __shared__ float Msm0[32 * 24];
    __shared__ float Msm1[32 * 24];
    __shared__ float sw[24];
    __shared__ float part_mn[24][8];
    __shared__ float part_mx[24][8];
    int base = blockIdx.x * 128;
    int tid = threadIdx.x;

    if (tid < CHN) {
        int h = tid / 3, r = tid % 3;
        float qw = 0.f;
        for (int k = 0; k < 8; k++) {
            float s = 0.f;
            for (int d = 0; d < 32; d++) s += wr[(h * 32 + d) * 24 + r * 8 + k];
            qw += expf(fminf(s, 50.f));
        }
        sw[tid] = sqrtf(2.f * qw);
    }
    {
        int ch = tid >> 5, e = tid & 31;
        int c = ch >> 3, h = ch & 7;
        float mq = 0.f, mk = 0.f;
        const float* wqr = wq + e * 256 + h * 32;
        const float* wkr = wk + e * 256 + h * 32;
        const float* al = alpha + h * 105 + c;
#pragma unroll 8
        for (int d = 0; d < 32; d++) {
            float a = al[d * 3];
            mq += wqr[d] * a;
            mk += wkr[d] * a;
        }
        Msm0[e * 24 + ch] = mq;
        Msm1[e * 24 + ch] = mk;
    }
    __syncthreads();

    if (tid < 128) {
        int n = base + tid;
        float r[32];
        const float4* xr = (const float4*)(x + (size_t)n * 32);
#pragma unroll
        for (int u = 0; u < 8; u++) {
            float4 v4 = xr[u];
            r[4 * u] = v4.x; r[4 * u + 1] = v4.y; r[4 * u + 2] = v4.z; r[4 * u + 3] = v4.w;
        }
        float mu = 0.f;
#pragma unroll
        for (int d = 0; d < 32; d++) mu += r[d];
        mu *= (1.0f / 32.0f);
        float var = 0.f;
#pragma unroll
        for (int d = 0; d < 32; d++) { float dd = r[d] - mu; var += dd * dd; }
        var *= (1.0f / 32.0f);
        float rs = rsqrtf(var + 1e-5f);
#pragma unroll
        for (int d = 0; d < 32; d++)
            xs[tid * QSTR + d] = (r[d] - mu) * rs * n1w[d] + n1b[d];
    }
    __syncthreads();

    {
        int proj = tid >> 8, jj = tid & 255;
        const float* W = (proj == 0) ? wq : (proj == 1) ? wk : wv;
        ull wpk[16];
#pragma unroll
        for (int d = 0; d < 16; d++)
            wpk[d] = pk2(W[(2 * d) * 256 + jj], W[(2 * d + 1) * 256 + jj]);
        int h = jj >> 5, d0 = jj & 31;
        float* dst;
        int stride;
        if (proj == 0) { dst = g_qhat; stride = QSTR; }
        else if (proj == 1) { dst = g_khat; stride = QSTR; }
        else { dst = g_v; stride = DH; }
        for (int r = 0; r < 128; r++) {
            const float4* xr = (const float4*)(xs + r * QSTR);
            ull a0 = 0, a1 = 0;
#pragma unroll
            for (int u = 0; u < 8; u++) {
                float4 v4 = xr[u];
                a0 = f2fma(lo2(v4), wpk[2 * u], a0);
                a1 = f2fma(hi2(v4), wpk[2 * u + 1], a1);
            }
            float s0, s1;
            upk(f2add(a0, a1), s0, s1);
            dst[((size_t)h * NPTS + (base + r)) * stride + d0] = s0 + s1;
        }
    }
    if (tid < 128) {
        int n = base + tid;
        float c0 = coords[n * 3], c1 = coords[n * 3 + 1], c2 = coords[n * 3 + 2];
#pragma unroll
        for (int h = 0; h < 8; h++) {
            float4 tail = make_float4(sw[h * 3] * c0, sw[h * 3 + 1] * c1,
                                      sw[h * 3 + 2] * c2, 0.f);
            *(float4*)(g_qhat + ((size_t)h * NPTS + n) * QSTR + 32) = tail;
            *(float4*)(g_khat + ((size_t)h * NPTS + n) * QSTR + 32) = tail;
        }
    }
    {
        int row = tid & 127;
        int slot = tid >> 7;
        int half = slot >= 3;
        int c = half ? slot - 3 : slot;
        int n = base + row;
        float xr[32];
        const float4* xrow = (const float4*)(xs + row * QSTR);
#pragma unroll
        for (int u = 0; u < 8; u++) ((float4*)xr)[u] = xrow[u];
        float c0 = coords[n * 3], c1 = coords[n * 3 + 1], c2 = coords[n * 3 + 2];
        const float* M = half ? Msm1 : Msm0;
        float acc[8];
#pragma unroll
        for (int h = 0; h < 8; h++) acc[h] = 0.f;
#pragma unroll 8
        for (int e = 0; e < 32; e++) {
            float xv = xr[e];
            const float* Mr = M + e * 24 + c * 8;
#pragma unroll
            for (int h = 0; h < 8; h++) acc[h] += xv * Mr[h];
        }
        float* dst = half ? g_kh : g_qh;
#pragma unroll
        for (int h = 0; h < 8; h++) {
            float sr0 = sw[h * 3] * c0, sr1 = sw[h * 3 + 1] * c1, sr2 = sw[h * 3 + 2] * c2;
            const float* al = alpha + h * 105 + c;
            acc[h] += sr0 * al[96] + sr1 * al[99] + sr2 * al[102];
            dst[(size_t)(c * 8 + h) * NPTS + n] = acc[h];
        }
        int rw = row >> 5;
#pragma unroll
        for (int h = 0; h < 8; h++) {
            float mn = acc[h], mx = acc[h];
#pragma unroll
            for (int o = 16; o > 0; o >>= 1) {
                mn = fminf(mn, __shfl_xor_sync(0xFFFFFFFFu, mn, o));
                mx = fmaxf(mx, __shfl_xor_sync(0xFFFFFFFFu, mx, o));
            }
            if ((tid & 31) == 0) {
                part_mn[c * 8 + h][half * 4 + rw] = mn;
                part_mx[c * 8 + h][half * 4 + rw] = mx;
            }
        }
    }
    __syncthreads();
    if (tid < CHN) {
        float mn = part_mn[tid][0], mx = part_mx[tid][0];
#pragma unroll
        for (int i = 1; i < 8; i++) {
            mn = fminf(mn, part_mn[tid][i]);
            mx = fmaxf(mx, part_mx[tid][i]);
        }
        g_pmn[tid * 256 + blockIdx.x] = encf(mn);
        g_pmx[tid * 256 + blockIdx.x] = encf(mx);
    }
}

// ---------------- bitonic sort primitives ----------------
template<int J>
__device__ __forceinline__ void shflp8(ull* r, int ibase, int l, int k_) {
#pragma unroll
    for (int s = 0; s < 8; s++) {
        int i = ibase + s * 32;
        bool up = ((i & k_) == 0);
        ull o = __shfl_xor_sync(0xFFFFFFFFu, r[s], J);
        bool kmin = (((l & J) == 0) == up);
        ull lo_ = (r[s] < o) ? r[s] : o;
        ull hi_ = (r[s] < o) ? o : r[s];
        r[s] = kmin ? lo_ : hi_;
    }
}
template<int JS>
__device__ __forceinline__ void slotp8(ull* r, int ibase, int k_) {
#pragma unroll
    for (int s = 0; s < 8; s++) {
        if (!(s & JS)) {
            int sp = s | JS;
            int i = ibase + s * 32;
            bool up = ((i & k_) == 0);
            if ((r[s] > r[sp]) == up) { ull t2 = r[s]; r[s] = r[sp]; r[sp] = t2; }
        }
    }
}
__device__ __forceinline__ void regpasses8(ull* r, int ibase, int l, int k_) {
    int half = k_ >> 1;
    if (half >= 128) slotp8<4>(r, ibase, k_);
    if (half >= 64)  slotp8<2>(r, ibase, k_);
    if (half >= 32)  slotp8<1>(r, ibase, k_);
    if (half >= 16)  shflp8<16>(r, ibase, l, k_);
    if (half >= 8)   shflp8<8>(r, ibase, l, k_);
    if (half >= 4)   shflp8<4>(r, ibase, l, k_);
    if (half >= 2)   shflp8<2>(r, ibase, l, k_);
    shflp8<1>(r, ibase, l, k_);
}
__device__ __forceinline__ void smem_pass8k(ull* s, int k_, int j_, int tid) {
#pragma unroll
    for (int p = 0; p < 4; p++) {
        int t = tid + p * 1024;
        int i = ((t & ~(j_ - 1)) << 1) | (t & (j_ - 1));
        bool up = ((i & k_) == 0);
        ull a = s[i], b = s[i + j_];
        if ((a > b) == up) { s[i] = b; s[i + j_] = a; }
    }
}

__global__ void __launch_bounds__(1024) k_sort8k(const int* __restrict__ shifts) {
    extern __shared__ ull s8[];
    __shared__ unsigned redn[8], redx[8];
    __shared__ float s_hsv;
    size_t base = (size_t)blockIdx.x * 8192;
    int tid = threadIdx.x;
    int w = tid >> 5, l = tid & 31;
    int ibase = w * 256 + l;

    bool isQ = (base < (size_t)CHN * NPTS);
    size_t hoff = isQ ? base : base - (size_t)CHN * NPTS;
    int seg = (int)(hoff >> 15);

    if (tid < 256) {
        unsigned umn = g_pmn[seg * 256 + tid];
        unsigned umx = g_pmx[seg * 256 + tid];
        unsigned a = __reduce_min_sync(0xFFFFFFFFu, umn);
        unsigned b = __reduce_max_sync(0xFFFFFFFFu, umx);
        if ((tid & 31) == 0) { redn[tid >> 5] = a; redx[tid >> 5] = b; }
    }
    __syncthreads();
    if (tid == 0) {
        unsigned a = redn[0], b = redx[0];
#pragma unroll
        for (int i = 1; i < 8; i++) {
            if (redn[i] < a) a = redn[i];
            if (redx[i] > b) b = redx[i];
        }
        s_hsv = decf(b) - decf(a);
    }
    __syncthreads();
    float hsv = s_hsv;
    const float* hsrc = isQ ? g_qh : g_kh;
    ull r[8];
#pragma unroll
    for (int s_ = 0; s_ < 8; s_++) {
        size_t t = hoff + ibase + s_ * 32;
        float off = __fmul_rn((float)shifts[t], hsv);
        r[s_] = ((ull)encf(__fadd_rn(hsrc[t], off)) << 32) | (unsigned)(t & (NPTS - 1));
    }
    for (int k_ = 2; k_ <= 256; k_ <<= 1) regpasses8(r, ibase, l, k_);
    for (int k_ = 512; k_ <= 8192; k_ <<= 1) {
#pragma unroll
        for (int s_ = 0; s_ < 8; s_++) s8[ibase + s_ * 32] = r[s_];
        __syncthreads();
        for (int j_ = k_ >> 1; j_ >= 256; j_ >>= 1) {
            smem_pass8k(s8, k_, j_, tid);
            __syncthreads();
        }
#pragma unroll
        for (int s_ = 0; s_ < 8; s_++) r[s_] = s8[ibase + s_ * 32];
        __syncthreads();
        regpasses8(r, ibase, l, k_);
    }
#pragma unroll
    for (int s_ = 0; s_ < 8; s_++) g_keys[base + ibase + s_ * 32] = r[s_];
}

__global__ void __launch_bounds__(256) k_mergepath(int L, int dir) {
    const ull* __restrict__ src = dir ? g_keys2 : g_keys;
    ull* __restrict__ dst = dir ? g_keys : g_keys2;
    size_t outbase = (size_t)blockIdx.x * 4096 + (size_t)threadIdx.x * 16;
    size_t pairBase = outbase & ~((size_t)(2 * L) - 1);
    const ull* A = src + pairBase;
    const ull* B = A + L;
    int p0 = (int)(outbase - pairBase);
    int lo = p0 > L ? p0 - L : 0;
    int hi = p0 < L ? p0 : L;
    while (lo < hi) {
        int m = (lo + hi) >> 1;
        if (A[m] <= B[p0 - 1 - m]) lo = m + 1; else hi = m;
    }
    int i = lo, j = p0 - lo;
    ull* d = dst + pairBase + p0;
    ull a = (i < L) ? A[i] : ~0ull;
    ull b = (j < L) ? B[j] : ~0ull;
#pragma unroll
    for (int t = 0; t < 16; t++) {
        bool takeA = (a <= b);
        d[t] = takeA ? a : b;
        if (takeA) { i++; a = (i < L) ? A[i] : ~0ull; }
        else       { j++; b = (j < L) ? B[j] : ~0ull; }
    }
}

// ---------------- attention via mma.sync tf32 (1 bucket/block, 8 warps) ----------------
// smem float offsets
#define OF_Q 0                      // [128][44]
#define OF_K 5632                   // [40][136]
#define OF_V 11072                  // [128][40]
#define OF_QSQ 16192                // [128]
#define OF_KSQ 16320                // [128]
#define OF_QIX 16448                // [128] unsigned
#define SMEM_ATTN ((16576) * 4)

__global__ void __launch_bounds__(256) k_attn() {
    extern __shared__ float sm[];
    int seg = blockIdx.y;
    int h = seg & 7;
    int bucket = blockIdx.x;
    int tid = threadIdx.x;

    const ull* kkey = g_keys + ((size_t)(CHN + seg)) * NPTS + bucket * BSZ;
    const ull* qkey = g_keys + (size_t)seg * NPTS + bucket * BSZ;

    if (tid < 128) {
        int r = tid;
        unsigned kidx = (unsigned)kkey[r];
        float tmp[36];
        const float4* kr = (const float4*)(g_khat + ((size_t)h * NPTS + kidx) * QSTR);
#pragma unroll
        for (int u = 0; u < 9; u++) ((float4*)tmp)[u] = kr[u];
        float s2 = 0.f;
#pragma unroll
        for (int d = 0; d < 35; d++) s2 += tmp[d] * tmp[d];
        sm[OF_KSQ + r] = -0.5f * s2;
#pragma unroll
        for (int d = 0; d < 36; d++) sm[OF_K + d * 136 + r] = tmp[d];
#pragma unroll
        for (int d = 36; d < 40; d++) sm[OF_K + d * 136 + r] = 0.f;
        float vv[32];
        const float4* vr = (const float4*)(g_v + ((size_t)h * NPTS + kidx) * DH);
#pragma unroll
        for (int u = 0; u < 8; u++) ((float4*)vv)[u] = vr[u];
#pragma unroll
        for (int d = 0; d < 32; d++) sm[OF_V + r * 40 + d] = vv[d];
    } else {
        int r = tid - 128;
        unsigned qidx = (unsigned)qkey[r];
        ((unsigned*)(sm + OF_QIX))[r] = qidx;
        float tmp[36];
        const float4* qr = (const float4*)(g_qhat + ((size_t)h * NPTS + qidx) * QSTR);
#pragma unroll
        for (int u = 0; u < 9; u++) ((float4*)tmp)[u] = qr[u];
        float s2 = 0.f;
#pragma unroll
        for (int d = 0; d < 35; d++) s2 += tmp[d] * tmp[d];
        sm[OF_QSQ + r] = -0.5f * s2;
#pragma unroll
        for (int d = 0; d < 36; d++) sm[OF_Q + r * 44 + d] = tmp[d];
#pragma unroll
        for (int d = 36; d < 40; d++) sm[OF_Q + r * 44 + d] = 0.f;
    }
    __syncthreads();

    int w = tid >> 5, lane = tid & 31;
    int g = lane >> 2, t = lane & 3;
    int rA = w * 16 + g, rB = rA + 8;

    float cc[16][4];
#pragma unroll
    for (int nt = 0; nt < 16; nt++) {
        cc[nt][0] = 0.f; cc[nt][1] = 0.f; cc[nt][2] = 0.f; cc[nt][3] = 0.f;
    }

    // S = Q K^T via 3xTF32
#pragma unroll
    for (int kt = 0; kt < 5; kt++) {
        float a0f = sm[OF_Q + rA * 44 + kt * 8 + t];
        float a1f = sm[OF_Q + rB * 44 + kt * 8 + t];
        float a2f = sm[OF_Q + rA * 44 + kt * 8 + t + 4];
        float a3f = sm[OF_Q + rB * 44 + kt * 8 + t + 4];
        float h0 = tf32r(a0f), h1 = tf32r(a1f), h2 = tf32r(a2f), h3 = tf32r(a3f);
        uint32_t ah0 = __float_as_uint(h0), ah1 = __float_as_uint(h1);
        uint32_t ah2 = __float_as_uint(h2), ah3 = __float_as_uint(h3);
        uint32_t al0 = __float_as_uint(a0f - h0), al1 = __float_as_uint(a1f - h1);
        uint32_t al2 = __float_as_uint(a2f - h2), al3 = __float_as_uint(a3f - h3);
#pragma unroll
        for (int nt = 0; nt < 16; nt++) {
            float b0f = sm[OF_K + (kt * 8 + t) * 136 + nt * 8 + g];
            float b1f = sm[OF_K + (kt * 8 + t + 4) * 136 + nt * 8 + g];
            float bh0f = tf32r(b0f), bh1f = tf32r(b1f);
            uint32_t bh0 = __float_as_uint(bh0f), bh1 = __float_as_uint(bh1f);
            uint32_t bl0 = __float_as_uint(b0f - bh0f), bl1 = __float_as_uint(b1f - bh1f);
            MMA_TF32(cc[nt], ah0, ah1, ah2, ah3, bh0, bh1);
            MMA_TF32(cc[nt], ah0, ah1, ah2, ah3, bl0, bl1);
            MMA_TF32(cc[nt], al0, al1, al2, al3, bh0, bh1);
        }
    }

    // exp + den, P (tf32-rounded) kept in cc
    float qsqA = sm[OF_QSQ + rA], qsqB = sm[OF_QSQ + rB];
    float denA = 0.f, denB = 0.f;
#pragma unroll
    for (int nt = 0; nt < 16; nt++) {
        int c0 = nt * 8 + 2 * t;
        float k0 = sm[OF_KSQ + c0], k1 = sm[OF_KSQ + c0 + 1];
        float e0 = __expf(fminf(cc[nt][0] + qsqA + k0, 0.f));
        float e1 = __expf(fminf(cc[nt][1] + qsqA + k1, 0.f));
        float e2 = __expf(fminf(cc[nt][2] + qsqB + k0, 0.f));
        float e3 = __expf(fminf(cc[nt][3] + qsqB + k1, 0.f));
        denA += e0 + e1;
        denB += e2 + e3;
        cc[nt][0] = tf32r(e0); cc[nt][1] = tf32r(e1);
        cc[nt][2] = tf32r(e2); cc[nt][3] = tf32r(e3);
    }
    denA += __shfl_xor_sync(0xFFFFFFFFu, denA, 1);
    denA += __shfl_xor_sync(0xFFFFFFFFu, denA, 2);
    denB += __shfl_xor_sync(0xFFFFFFFFu, denB, 1);
    denB += __shfl_xor_sync(0xFFFFFFFFu, denB, 2);

    // D = P V (V hi/lo, 2 passes)
    float dd[4][4];
#pragma unroll
    for (int nv = 0; nv < 4; nv++) {
        dd[nv][0] = 0.f; dd[nv][1] = 0.f; dd[nv][2] = 0.f; dd[nv][3] = 0.f;
    }
    int src1 = (lane & ~3) | (t >> 1);
    int src2 = src1 + 2;
    bool odd = (t & 1);
#pragma unroll
    for (int kt = 0; kt < 16; kt++) {
        float v00 = __shfl_sync(0xFFFFFFFFu, cc[kt][0], src1);
        float v01 = __shfl_sync(0xFFFFFFFFu, cc[kt][1], src1);
        float v02 = __shfl_sync(0xFFFFFFFFu, cc[kt][2], src1);
        float v03 = __shfl_sync(0xFFFFFFFFu, cc[kt][3], src1);
        float v10 = __shfl_sync(0xFFFFFFFFu, cc[kt][0], src2);
        float v11 = __shfl_sync(0xFFFFFFFFu, cc[kt][1], src2);
        float v12 = __shfl_sync(0xFFFFFFFFu, cc[kt][2], src2);
        float v13 = __shfl_sync(0xFFFFFFFFu, cc[kt][3], src2);
        uint32_t a0 = __float_as_uint(odd ? v01 : v00);
        uint32_t a1 = __float_as_uint(odd ? v03 : v02);
        uint32_t a2 = __float_as_uint(odd ? v11 : v10);
        uint32_t a3 = __float_as_uint(odd ? v13 : v12);
#pragma unroll
        for (int nv = 0; nv < 4; nv++) {
            float b0f = sm[OF_V + (kt * 8 + t) * 40 + nv * 8 + g];
            float b1f = sm[OF_V + (kt * 8 + t + 4) * 40 + nv * 8 + g];
            float bh0f = tf32r(b0f), bh1f = tf32r(b1f);
            uint32_t bh0 = __float_as_uint(bh0f), bh1 = __float_as_uint(bh1f);
            uint32_t bl0 = __float_as_uint(b0f - bh0f), bl1 = __float_as_uint(b1f - bh1f);
            MMA_TF32(dd[nv], a0, a1, a2, a3, bh0, bh1);
            MMA_TF32(dd[nv], a0, a1, a2, a3, bl0, bl1);
        }
    }

    // write results
    unsigned qA = ((unsigned*)(sm + OF_QIX))[rA];
    unsigned qB = ((unsigned*)(sm + OF_QIX))[rB];
    if (t == 0) {
        g_dscr[(size_t)seg * NPTS + qA] = denA;
        g_dscr[(size_t)seg * NPTS + qB] = denB;
    }
    float* odA = g_oscr + ((size_t)seg * NPTS + qA) * DH;
    float* odB = g_oscr + ((size_t)seg * NPTS + qB) * DH;
#pragma unroll
    for (int nv = 0; nv < 4; nv++) {
        int col = nv * 8 + 2 * t;
        *(float2*)(odA + col) = make_float2(dd[nv][0], dd[nv][1]);
        *(float2*)(odB + col) = make_float2(dd[nv][2], dd[nv][3]);
    }
}

// ---------------- epilogue: combine + out-proj + residual + LN2 + FF + residual ----------
__global__ void __launch_bounds__(128) k_epilogue(
    const float* __restrict__ x, const float* __restrict__ ow,
    const float* __restrict__ ob, const float* __restrict__ n2w,
    const float* __restrict__ n2b, const float* __restrict__ f1w,
    const float* __restrict__ f1b, const float* __restrict__ f2w,
    const float* __restrict__ f2b, float* __restrict__ out) {
    __shared__ float ws[256 * 32];
    __shared__ float f1sT[32 * 32];
    __shared__ float f2s[32 * 32];
    __shared__ float cs[32 * 5];
    int tid = threadIdx.x;
    for (int i = tid; i < 8192; i += 128) ws[i] = ow[i];
    for (int i = tid; i < 1024; i += 128) {
        f1sT[(i & 31) * 32 + (i >> 5)] = f1w[i];
        f2s[i] = f2w[i];
    }
    if (tid < 32) {
        cs[tid] = ob[tid]; cs[32 + tid] = n2w[tid]; cs[64 + tid] = n2b[tid];
        cs[96 + tid] = f1b[tid]; cs[128 + tid] = f2b[tid];
    }
    __syncthreads();
    int n = blockIdx.x * 128 + tid;

    ull acc2[16];
#pragma unroll
    for (int p = 0; p < 16; p++) acc2[p] = pk2(cs[2 * p], cs[2 * p + 1]);

#pragma unroll 1
    for (int h = 0; h < 8; h++) {
        float den = g_dscr[(size_t)h * NPTS + n] +
                    g_dscr[(size_t)(8 + h) * NPTS + n] +
                    g_dscr[(size_t)(16 + h) * NPTS + n] + 3e-20f;
        float inv = 1.0f / den;
        const float4* oa = (const float4*)(g_oscr + ((size_t)h * NPTS + n) * DH);
        const float4* obp = (const float4*)(g_oscr + ((size_t)(8 + h) * NPTS + n) * DH);
        const float4* oc = (const float4*)(g_oscr + ((size_t)(16 + h) * NPTS + n) * DH);
#pragma unroll
        for (int p4 = 0; p4 < 8; p4++) {
            float4 a4 = oa[p4], b4 = obp[p4], c4 = oc[p4];
            float av[4];
            av[0] = (a4.x + b4.x + c4.x) * inv;
            av[1] = (a4.y + b4.y + c4.y) * inv;
            av[2] = (a4.z + b4.z + c4.z) * inv;
            av[3] = (a4.w + b4.w + c4.w) * inv;
            int j0 = h * 32 + p4 * 4;
#pragma unroll
            for (int u = 0; u < 4; u++) {
                ull ad = pk2(av[u], av[u]);
                const float4* wr2 = (const float4*)(ws + (j0 + u) * 32);
#pragma unroll
                for (int p = 0; p < 8; p++) {
                    float4 w4 = wr2[p];
                    acc2[2 * p] = f2fma(ad, lo2(w4), acc2[2 * p]);
                    acc2[2 * p + 1] = f2fma(ad, hi2(w4), acc2[2 * p + 1]);
                }
            }
        }
    }
    float acc[32];
#pragma unroll
    for (int p = 0; p < 16; p++) upk(acc2[p], acc[2 * p], acc[2 * p + 1]);

    float x2[32];
    const float4* xr = (const float4*)(x + (size_t)n * 32);
#pragma unroll
    for (int u = 0; u < 8; u++) {
        float4 xv = xr[u];
        x2[4 * u] = xv.x + acc[4 * u];
        x2[4 * u + 1] = xv.y + acc[4 * u + 1];
        x2[4 * u + 2] = xv.z + acc[4 * u + 2];
        x2[4 * u + 3] = xv.w + acc[4 * u + 3];
    }
    float mu = 0.f;
#pragma unroll
    for (int d = 0; d < 32; d++) mu += x2[d];
    mu *= (1.0f / 32.0f);
    float var = 0.f;
#pragma unroll
    for (int d = 0; d < 32; d++) { float dd = x2[d] - mu; var += dd * dd; }
    var *= (1.0f / 32.0f);
    float rs = rsqrtf(var + 1e-5f);
    float xn2[32];
#pragma unroll
    for (int d = 0; d < 32; d++)
        xn2[d] = (x2[d] - mu) * rs * cs[32 + d] + cs[64 + d];
    ull xp[16];
#pragma unroll
    for (int u = 0; u < 16; u++) xp[u] = pk2(xn2[2 * u], xn2[2 * u + 1]);
    float h1[32];
#pragma unroll 4
    for (int jj = 0; jj < 32; jj++) {
        const float4* fr = (const float4*)(f1sT + jj * 32);
        ull a0 = 0ull, a1 = 0ull;
#pragma unroll
        for (int u = 0; u < 8; u++) {
            float4 v4 = fr[u];
            a0 = f2fma(lo2(v4), xp[2 * u], a0);
            a1 = f2fma(hi2(v4), xp[2 * u + 1], a1);
        }
        float s0, s1;
        upk(f2add(a0, a1), s0, s1);
        float t2 = cs[96 + jj] + s0 + s1;
        h1[jj] = t2 / (1.0f + __expf(-t2));
    }
    ull o2[16];
#pragma unroll
    for (int p = 0; p < 16; p++) o2[p] = pk2(cs[128 + 2 * p], cs[128 + 2 * p + 1]);
#pragma unroll 4
    for (int jj = 0; jj < 32; jj++) {
        ull hd = pk2(h1[jj], h1[jj]);
        const float4* fr = (const float4*)(f2s + jj * 32);
#pragma unroll
        for (int p = 0; p < 8; p++) {
            float4 v4 = fr[p];
            o2[2 * p] = f2fma(hd, lo2(v4), o2[2 * p]);
            o2[2 * p + 1] = f2fma(hd, hi2(v4), o2[2 * p + 1]);
        }
    }
    float o[32];
#pragma unroll
    for (int p = 0; p < 16; p++) upk(o2[p], o[2 * p], o[2 * p + 1]);
    float4* orow = (float4*)(out + (size_t)n * 32);
#pragma unroll
    for (int u = 0; u < 8; u++)
        orow[u] = make_float4(x2[4 * u] + o[4 * u], x2[4 * u + 1] + o[4 * u + 1],
                              x2[4 * u + 2] + o[4 * u + 2], x2[4 * u + 3] + o[4 * u + 3]);
}

// ---------------- launcher ----------------
extern "C" void kernel_launch(void* const* d_in, const int* in_sizes, int n_in,
                              void* d_out, int out_size) {
    const float* x = (const float*)d_in[0];
    const float* coords = (const float*)d_in[1];
    const int* shifts = (const int*)d_in[2];
    const float* n1w = (const float*)d_in[3];
    const float* n1b = (const float*)d_in[4];
    const float* wq = (const float*)d_in[5];
    const float* wk = (const float*)d_in[6];
    const float* wv = (const float*)d_in[7];
    const float* wr = (const float*)d_in[8];
    const float* alpha = (const float*)d_in[9];
    const float* ow = (const float*)d_in[10];
    const float* ob = (const float*)d_in[11];
    const float* n2w = (const float*)d_in[12];
    const float* n2b = (const float*)d_in[13];
    const float* f1w = (const float*)d_in[14];
    const float* f1b = (const float*)d_in[15];
    const float* f2w = (const float*)d_in[16];
    const float* f2b = (const float*)d_in[17];
    float* out = (float*)d_out;

    cudaFuncSetAttribute(k_sort8k, cudaFuncAttributeMaxDynamicSharedMemorySize, 65536);
    cudaFuncSetAttribute(k_attn, cudaFuncAttributeMaxDynamicSharedMemorySize, SMEM_ATTN);

    k_ln_qkv<<<NPTS / 128, 768>>>(x, n1w, n1b, wq, wk, wv, wr, coords, alpha);

    const int TOT = 2 * CHN * NPTS;
    k_sort8k<<<TOT / 8192, 1024, 65536>>>(shifts);
    k_mergepath<<<TOT / 4096, 256>>>(8192, 0);    // keys  -> keys2 (16384 runs)
    k_mergepath<<<TOT / 4096, 256>>>(16384, 1);   // keys2 -> keys  (32768 runs)

    // launch 4 (ncu capture slot): mma.sync attention
    k_attn<<<dim3(NBK, CHN), 256, SMEM_ATTN>>>();
    k_epilogue<<<NPTS / 128, 128>>>(x, ow, ob, n2w, n2b, f1w, f1b, f2w, f2b, out);
}

// round 13
// speedup vs baseline: 1.4985x; 1.0254x over previous
#include <cuda_runtime.h>
#include <cstdint>

#define NPTS 32768
#define DH 32
#define NH 8
#define BSZ 128
#define NBK 256
#define CHN 24
#define QSTR 36

typedef unsigned long long ull;

__device__ float g_qhat[(size_t)NH * NPTS * QSTR];
__device__ float g_khat[(size_t)NH * NPTS * QSTR];
__device__ float g_v[(size_t)NH * NPTS * DH];
__device__ float g_qh[(size_t)CHN * NPTS];
__device__ float g_kh[(size_t)CHN * NPTS];
__device__ ull   g_keys[(size_t)2 * CHN * NPTS];
__device__ ull   g_keys2[(size_t)2 * CHN * NPTS];
__device__ unsigned g_pmn[CHN * 256];
__device__ unsigned g_pmx[CHN * 256];
__device__ float g_oscr[(size_t)CHN * NPTS * DH];
__device__ float g_dscr[(size_t)CHN * NPTS];

// ---------------- f32x2 helpers ----------------
__device__ __forceinline__ ull pk2(float a, float b) {
    ull r; asm("mov.b64 %0, {%1, %2};" : "=l"(r) : "f"(a), "f"(b)); return r;
}
__device__ __forceinline__ void upk(ull p, float& a, float& b) {
    asm("mov.b64 {%0, %1}, %2;" : "=f"(a), "=f"(b) : "l"(p));
}
__device__ __forceinline__ ull f2fma(ull a, ull b, ull c) {
    ull d; asm("fma.rn.f32x2 %0, %1, %2, %3;" : "=l"(d) : "l"(a), "l"(b), "l"(c)); return d;
}
__device__ __forceinline__ ull f2add(ull a, ull b) {
    ull d; asm("add.rn.f32x2 %0, %1, %2;" : "=l"(d) : "l"(a), "l"(b)); return d;
}
__device__ __forceinline__ ull lo2(float4 v) { return pk2(v.x, v.y); }
__device__ __forceinline__ ull hi2(float4 v) { return pk2(v.z, v.w); }

__device__ __forceinline__ unsigned encf(float f) {
    unsigned u = __float_as_uint(f);
    return (u & 0x80000000u) ? ~u : (u | 0x80000000u);
}
__device__ __forceinline__ float decf(unsigned u) {
    return (u & 0x80000000u) ? __uint_as_float(u ^ 0x80000000u)
                             : __uint_as_float(~u);
}
__device__ __forceinline__ float tf32r(float x) {
    uint32_t u; asm("cvt.rna.tf32.f32 %0, %1;" : "=r"(u) : "f"(x));
    return __uint_as_float(u);
}
#define MMA_TF32(c, a0, a1, a2, a3, b0, b1) \
    asm volatile("mma.sync.aligned.m16n8k8.row.col.f32.tf32.tf32.f32 " \
        "{%0,%1,%2,%3}, {%4,%5,%6,%7}, {%8,%9}, {%0,%1,%2,%3};" \
        : "+f"((c)[0]), "+f"((c)[1]), "+f"((c)[2]), "+f"((c)[3]) \
        : "r"(a0), "r"(a1), "r"(a2), "r"(a3), "r"(b0), "r"(b1))

// ---------------- kernel 1: LN + QKV + tails + hash + minmax partials ----------
__global__ void __launch_bounds__(768) k_ln_qkv(
    const float* __restrict__ x, const float* __restrict__ n1w,
    const float* __restrict__ n1b, const float* __restrict__ wq,
    const float* __restrict__ wk, const float* __restrict__ wv,
    const float* __restrict__ wr, const float* __restrict__ coords,
    const float* __restrict__ alpha) {
    __shared__ float xs[128 * QSTR];
    __shared__ float Msm0[32 * 24];
    __shared__ float Msm1[32 * 24];
    __shared__ float sw[24];
    __shared__ float part_mn[24][8];
    __shared__ float part_mx[24][8];
    int base = blockIdx.x * 128;
    int tid = threadIdx.x;

    if (tid < CHN) {
        int h = tid / 3, r = tid % 3;
        float qw = 0.f;
        for (int k = 0; k < 8; k++) {
            float s = 0.f;
            for (int d = 0; d < 32; d++) s += wr[(h * 32 + d) * 24 + r * 8 + k];
            qw += expf(fminf(s, 50.f));
        }
        sw[tid] = sqrtf(2.f * qw);
    }
    {
        int ch = tid >> 5, e = tid & 31;
        int c = ch >> 3, h = ch & 7;
        float mq = 0.f, mk = 0.f;
        const float* wqr = wq + e * 256 + h * 32;
        const float* wkr = wk + e * 256 + h * 32;
        const float* al = alpha + h * 105 + c;
#pragma unroll 8
        for (int d = 0; d < 32; d++) {
            float a = al[d * 3];
            mq += wqr[d] * a;
            mk += wkr[d] * a;
        }
        Msm0[e * 24 + ch] = mq;
        Msm1[e * 24 + ch] = mk;
    }
    __syncthreads();

    if (tid < 128) {
        int n = base + tid;
        float r[32];
        const float4* xr = (const float4*)(x + (size_t)n * 32);
#pragma unroll
        for (int u = 0; u < 8; u++) {
            float4 v4 = xr[u];
            r[4 * u] = v4.x; r[4 * u + 1] = v4.y; r[4 * u + 2] = v4.z; r[4 * u + 3] = v4.w;
        }
        float mu = 0.f;
#pragma unroll
        for (int d = 0; d < 32; d++) mu += r[d];
        mu *= (1.0f / 32.0f);
        float var = 0.f;
#pragma unroll
        for (int d = 0; d < 32; d++) { float dd = r[d] - mu; var += dd * dd; }
        var *= (1.0f / 32.0f);
        float rs = rsqrtf(var + 1e-5f);
#pragma unroll
        for (int d = 0; d < 32; d++)
            xs[tid * QSTR + d] = (r[d] - mu) * rs * n1w[d] + n1b[d];
    }
    __syncthreads();

    {
        int proj = tid >> 8, jj = tid & 255;
        const float* W = (proj == 0) ? wq : (proj == 1) ? wk : wv;
        ull wpk[16];
#pragma unroll
        for (int d = 0; d < 16; d++)
            wpk[d] = pk2(W[(2 * d) * 256 + jj], W[(2 * d + 1) * 256 + jj]);
        int h = jj >> 5, d0 = jj & 31;
        float* dst;
        int stride;
        if (proj == 0) { dst = g_qhat; stride = QSTR; }
        else if (proj == 1) { dst = g_khat; stride = QSTR; }
        else { dst = g_v; stride = DH; }
        for (int r = 0; r < 128; r++) {
            const float4* xr = (const float4*)(xs + r * QSTR);
            ull a0 = 0, a1 = 0;
#pragma unroll
            for (int u = 0; u < 8; u++) {
                float4 v4 = xr[u];
                a0 = f2fma(lo2(v4), wpk[2 * u], a0);
                a1 = f2fma(hi2(v4), wpk[2 * u + 1], a1);
            }
            float s0, s1;
            upk(f2add(a0, a1), s0, s1);
            dst[((size_t)h * NPTS + (base + r)) * stride + d0] = s0 + s1;
        }
    }
    if (tid < 128) {
        int n = base + tid;
        float c0 = coords[n * 3], c1 = coords[n * 3 + 1], c2 = coords[n * 3 + 2];
#pragma unroll
        for (int h = 0; h < 8; h++) {
            float4 tail = make_float4(sw[h * 3] * c0, sw[h * 3 + 1] * c1,
                                      sw[h * 3 + 2] * c2, 0.f);
            *(float4*)(g_qhat + ((size_t)h * NPTS + n) * QSTR + 32) = tail;
            *(float4*)(g_khat + ((size_t)h * NPTS + n) * QSTR + 32) = tail;
        }
    }
    {
        int row = tid & 127;
        int slot = tid >> 7;
        int half = slot >= 3;
        int c = half ? slot - 3 : slot;
        int n = base + row;
        float xr[32];
        const float4* xrow = (const float4*)(xs + row * QSTR);
#pragma unroll
        for (int u = 0; u < 8; u++) ((float4*)xr)[u] = xrow[u];
        float c0 = coords[n * 3], c1 = coords[n * 3 + 1], c2 = coords[n * 3 + 2];
        const float* M = half ? Msm1 : Msm0;
        float acc[8];
#pragma unroll
        for (int h = 0; h < 8; h++) acc[h] = 0.f;
#pragma unroll 8
        for (int e = 0; e < 32; e++) {
            float xv = xr[e];
            const float* Mr = M + e * 24 + c * 8;
#pragma unroll
            for (int h = 0; h < 8; h++) acc[h] += xv * Mr[h];
        }
        float* dst = half ? g_kh : g_qh;
#pragma unroll
        for (int h = 0; h < 8; h++) {
            float sr0 = sw[h * 3] * c0, sr1 = sw[h * 3 + 1] * c1, sr2 = sw[h * 3 + 2] * c2;
            const float* al = alpha + h * 105 + c;
            acc[h] += sr0 * al[96] + sr1 * al[99] + sr2 * al[102];
            dst[(size_t)(c * 8 + h) * NPTS + n] = acc[h];
        }
        int rw = row >> 5;
#pragma unroll
        for (int h = 0; h < 8; h++) {
            float mn = acc[h], mx = acc[h];
#pragma unroll
            for (int o = 16; o > 0; o >>= 1) {
                mn = fminf(mn, __shfl_xor_sync(0xFFFFFFFFu, mn, o));
                mx = fmaxf(mx, __shfl_xor_sync(0xFFFFFFFFu, mx, o));
            }
            if ((tid & 31) == 0) {
                part_mn[c * 8 + h][half * 4 + rw] = mn;
                part_mx[c * 8 + h][half * 4 + rw] = mx;
            }
        }
    }
    __syncthreads();
    if (tid < CHN) {
        float mn = part_mn[tid][0], mx = part_mx[tid][0];
#pragma unroll
        for (int i = 1; i < 8; i++) {
            mn = fminf(mn, part_mn[tid][i]);
            mx = fmaxf(mx, part_mx[tid][i]);
        }
        g_pmn[tid * 256 + blockIdx.x] = encf(mn);
        g_pmx[tid * 256 + blockIdx.x] = encf(mx);
    }
}

// ---------------- bitonic sort primitives ----------------
template<int J>
__device__ __forceinline__ void shflp8(ull* r, int ibase, int l, int k_) {
#pragma unroll
    for (int s = 0; s < 8; s++) {
        int i = ibase + s * 32;
        bool up = ((i & k_) == 0);
        ull o = __shfl_xor_sync(0xFFFFFFFFu, r[s], J);
        bool kmin = (((l & J) == 0) == up);
        ull lo_ = (r[s] < o) ? r[s] : o;
        ull hi_ = (r[s] < o) ? o : r[s];
        r[s] = kmin ? lo_ : hi_;
    }
}
template<int JS>
__device__ __forceinline__ void slotp8(ull* r, int ibase, int k_) {
#pragma unroll
    for (int s = 0; s < 8; s++) {
        if (!(s & JS)) {
            int sp = s | JS;
            int i = ibase + s * 32;
            bool up = ((i & k_) == 0);
            if ((r[s] > r[sp]) == up) { ull t2 = r[s]; r[s] = r[sp]; r[sp] = t2; }
        }
    }
}
__device__ __forceinline__ void regpasses8(ull* r, int ibase, int l, int k_) {
    int half = k_ >> 1;
    if (half >= 128) slotp8<4>(r, ibase, k_);
    if (half >= 64)  slotp8<2>(r, ibase, k_);
    if (half >= 32)  slotp8<1>(r, ibase, k_);
    if (half >= 16)  shflp8<16>(r, ibase, l, k_);
    if (half >= 8)   shflp8<8>(r, ibase, l, k_);
    if (half >= 4)   shflp8<4>(r, ibase, l, k_);
    if (half >= 2)   shflp8<2>(r, ibase, l, k_);
    shflp8<1>(r, ibase, l, k_);
}
__device__ __forceinline__ void smem_pass8k(ull* s, int k_, int j_, int tid) {
#pragma unroll
    for (int p = 0; p < 4; p++) {
        int t = tid + p * 1024;
        int i = ((t & ~(j_ - 1)) << 1) | (t & (j_ - 1));
        bool up = ((i & k_) == 0);
        ull a = s[i], b = s[i + j_];
        if ((a > b) == up) { s[i] = b; s[i + j_] = a; }
    }
}

__global__ void __launch_bounds__(1024) k_sort8k(const int* __restrict__ shifts) {
    extern __shared__ ull s8[];
    __shared__ unsigned redn[8], redx[8];
    __shared__ float s_hsv;
    size_t base = (size_t)blockIdx.x * 8192;
    int tid = threadIdx.x;
    int w = tid >> 5, l = tid & 31;
    int ibase = w * 256 + l;

    bool isQ = (base < (size_t)CHN * NPTS);
    size_t hoff = isQ ? base : base - (size_t)CHN * NPTS;
    int seg = (int)(hoff >> 15);

    if (tid < 256) {
        unsigned umn = g_pmn[seg * 256 + tid];
        unsigned umx = g_pmx[seg * 256 + tid];
        unsigned a = __reduce_min_sync(0xFFFFFFFFu, umn);
        unsigned b = __reduce_max_sync(0xFFFFFFFFu, umx);
        if ((tid & 31) == 0) { redn[tid >> 5] = a; redx[tid >> 5] = b; }
    }
    __syncthreads();
    if (tid == 0) {
        unsigned a = redn[0], b = redx[0];
#pragma unroll
        for (int i = 1; i < 8; i++) {
            if (redn[i] < a) a = redn[i];
            if (redx[i] > b) b = redx[i];
        }
        s_hsv = decf(b) - decf(a);
    }
    __syncthreads();
    float hsv = s_hsv;
    const float* hsrc = isQ ? g_qh : g_kh;
    ull r[8];
#pragma unroll
    for (int s_ = 0; s_ < 8; s_++) {
        size_t t = hoff + ibase + s_ * 32;
        float off = __fmul_rn((float)shifts[t], hsv);
        r[s_] = ((ull)encf(__fadd_rn(hsrc[t], off)) << 32) | (unsigned)(t & (NPTS - 1));
    }
    for (int k_ = 2; k_ <= 256; k_ <<= 1) regpasses8(r, ibase, l, k_);
    for (int k_ = 512; k_ <= 8192; k_ <<= 1) {
#pragma unroll
        for (int s_ = 0; s_ < 8; s_++) s8[ibase + s_ * 32] = r[s_];
        __syncthreads();
        for (int j_ = k_ >> 1; j_ >= 256; j_ >>= 1) {
            smem_pass8k(s8, k_, j_, tid);
            __syncthreads();
        }
#pragma unroll
        for (int s_ = 0; s_ < 8; s_++) r[s_] = s8[ibase + s_ * 32];
        __syncthreads();
        regpasses8(r, ibase, l, k_);
    }
#pragma unroll
    for (int s_ = 0; s_ < 8; s_++) g_keys[base + ibase + s_ * 32] = r[s_];
}

__global__ void __launch_bounds__(256) k_mergepath(int L, int dir) {
    const ull* __restrict__ src = dir ? g_keys2 : g_keys;
    ull* __restrict__ dst = dir ? g_keys : g_keys2;
    size_t outbase = (size_t)blockIdx.x * 4096 + (size_t)threadIdx.x * 16;
    size_t pairBase = outbase & ~((size_t)(2 * L) - 1);
    const ull* A = src + pairBase;
    const ull* B = A + L;
    int p0 = (int)(outbase - pairBase);
    int lo = p0 > L ? p0 - L : 0;
    int hi = p0 < L ? p0 : L;
    while (lo < hi) {
        int m = (lo + hi) >> 1;
        if (A[m] <= B[p0 - 1 - m]) lo = m + 1; else hi = m;
    }
    int i = lo, j = p0 - lo;
    ull* d = dst + pairBase + p0;
    ull a = (i < L) ? A[i] : ~0ull;
    ull b = (j < L) ? B[j] : ~0ull;
#pragma unroll
    for (int t = 0; t < 16; t++) {
        bool takeA = (a <= b);
        d[t] = takeA ? a : b;
        if (takeA) { i++; a = (i < L) ? A[i] : ~0ull; }
        else       { j++; b = (j < L) ? B[j] : ~0ull; }
    }
}

// ---------------- attention via mma.sync tf32 (1 bucket/block, 8 warps) ----------------
// K pre-split hi/lo at staging; V staged tf32-rounded (single PV pass).
// smem float offsets
#define OF_Q 0                      // [128][44]
#define OF_KH 5632                  // [40][136] tf32 hi
#define OF_KL 11072                 // [40][136] residual lo
#define OF_V 16512                  // [128][40] tf32
#define OF_QSQ 21632                // [128]
#define OF_KSQ 21760                // [128]
#define OF_QIX 21888                // [128] unsigned
#define SMEM_ATTN ((22016) * 4)

__global__ void __launch_bounds__(256) k_attn() {
    extern __shared__ float sm[];
    int seg = blockIdx.y;
    int h = seg & 7;
    int bucket = blockIdx.x;
    int tid = threadIdx.x;

    const ull* kkey = g_keys + ((size_t)(CHN + seg)) * NPTS + bucket * BSZ;
    const ull* qkey = g_keys + (size_t)seg * NPTS + bucket * BSZ;

    if (tid < 128) {
        int r = tid;
        unsigned kidx = (unsigned)kkey[r];
        float tmp[36];
        const float4* kr = (const float4*)(g_khat + ((size_t)h * NPTS + kidx) * QSTR);
#pragma unroll
        for (int u = 0; u < 9; u++) ((float4*)tmp)[u] = kr[u];
        float s2 = 0.f;
#pragma unroll
        for (int d = 0; d < 35; d++) s2 += tmp[d] * tmp[d];
        sm[OF_KSQ + r] = -0.5f * s2;
#pragma unroll
        for (int d = 0; d < 36; d++) {
            float hi_ = tf32r(tmp[d]);
            sm[OF_KH + d * 136 + r] = hi_;
            sm[OF_KL + d * 136 + r] = tmp[d] - hi_;
        }
#pragma unroll
        for (int d = 36; d < 40; d++) {
            sm[OF_KH + d * 136 + r] = 0.f;
            sm[OF_KL + d * 136 + r] = 0.f;
        }
        float vv[32];
        const float4* vr = (const float4*)(g_v + ((size_t)h * NPTS + kidx) * DH);
#pragma unroll
        for (int u = 0; u < 8; u++) ((float4*)vv)[u] = vr[u];
#pragma unroll
        for (int d = 0; d < 32; d++) sm[OF_V + r * 40 + d] = tf32r(vv[d]);
    } else {
        int r = tid - 128;
        unsigned qidx = (unsigned)qkey[r];
        ((unsigned*)(sm + OF_QIX))[r] = qidx;
        float tmp[36];
        const float4* qr = (const float4*)(g_qhat + ((size_t)h * NPTS + qidx) * QSTR);
#pragma unroll
        for (int u = 0; u < 9; u++) ((float4*)tmp)[u] = qr[u];
        float s2 = 0.f;
#pragma unroll
        for (int d = 0; d < 35; d++) s2 += tmp[d] * tmp[d];
        sm[OF_QSQ + r] = -0.5f * s2;
#pragma unroll
        for (int d = 0; d < 36; d++) sm[OF_Q + r * 44 + d] = tmp[d];
#pragma unroll
        for (int d = 36; d < 40; d++) sm[OF_Q + r * 44 + d] = 0.f;
    }
    __syncthreads();

    int w = tid >> 5, lane = tid & 31;
    int g = lane >> 2, t = lane & 3;
    int rA = w * 16 + g, rB = rA + 8;

    float cc[16][4];
#pragma unroll
    for (int nt = 0; nt < 16; nt++) {
        cc[nt][0] = 0.f; cc[nt][1] = 0.f; cc[nt][2] = 0.f; cc[nt][3] = 0.f;
    }

    // S = Q K^T via 3xTF32 (K pre-split in smem)
#pragma unroll
    for (int kt = 0; kt < 5; kt++) {
        float a0f = sm[OF_Q + rA * 44 + kt * 8 + t];
        float a1f = sm[OF_Q + rB * 44 + kt * 8 + t];
        float a2f = sm[OF_Q + rA * 44 + kt * 8 + t + 4];
        float a3f = sm[OF_Q + rB * 44 + kt * 8 + t + 4];
        float h0 = tf32r(a0f), h1 = tf32r(a1f), h2 = tf32r(a2f), h3 = tf32r(a3f);
        uint32_t ah0 = __float_as_uint(h0), ah1 = __float_as_uint(h1);
        uint32_t ah2 = __float_as_uint(h2), ah3 = __float_as_uint(h3);
        uint32_t al0 = __float_as_uint(a0f - h0), al1 = __float_as_uint(a1f - h1);
        uint32_t al2 = __float_as_uint(a2f - h2), al3 = __float_as_uint(a3f - h3);
#pragma unroll
        for (int nt = 0; nt < 16; nt++) {
            uint32_t bh0 = __float_as_uint(sm[OF_KH + (kt * 8 + t) * 136 + nt * 8 + g]);
            uint32_t bh1 = __float_as_uint(sm[OF_KH + (kt * 8 + t + 4) * 136 + nt * 8 + g]);
            uint32_t bl0 = __float_as_uint(sm[OF_KL + (kt * 8 + t) * 136 + nt * 8 + g]);
            uint32_t bl1 = __float_as_uint(sm[OF_KL + (kt * 8 + t + 4) * 136 + nt * 8 + g]);
            MMA_TF32(cc[nt], ah0, ah1, ah2, ah3, bh0, bh1);
            MMA_TF32(cc[nt], ah0, ah1, ah2, ah3, bl0, bl1);
            MMA_TF32(cc[nt], al0, al1, al2, al3, bh0, bh1);
        }
    }

    // exp + den, P (tf32-rounded) kept in cc
    float qsqA = sm[OF_QSQ + rA], qsqB = sm[OF_QSQ + rB];
    float denA = 0.f, denB = 0.f;
#pragma unroll
    for (int nt = 0; nt < 16; nt++) {
        int c0 = nt * 8 + 2 * t;
        float k0 = sm[OF_KSQ + c0], k1 = sm[OF_KSQ + c0 + 1];
        float e0 = __expf(fminf(cc[nt][0] + qsqA + k0, 0.f));
        float e1 = __expf(fminf(cc[nt][1] + qsqA + k1, 0.f));
        float e2 = __expf(fminf(cc[nt][2] + qsqB + k0, 0.f));
        float e3 = __expf(fminf(cc[nt][3] + qsqB + k1, 0.f));
        denA += e0 + e1;
        denB += e2 + e3;
        cc[nt][0] = tf32r(e0); cc[nt][1] = tf32r(e1);
        cc[nt][2] = tf32r(e2); cc[nt][3] = tf32r(e3);
    }
    denA += __shfl_xor_sync(0xFFFFFFFFu, denA, 1);
    denA += __shfl_xor_sync(0xFFFFFFFFu, denA, 2);
    denB += __shfl_xor_sync(0xFFFFFFFFu, denB, 1);
    denB += __shfl_xor_sync(0xFFFFFFFFu, denB, 2);

    // D = P V (V already tf32; single pass)
    float dd[4][4];
#pragma unroll
    for (int nv = 0; nv < 4; nv++) {
        dd[nv][0] = 0.f; dd[nv][1] = 0.f; dd[nv][2] = 0.f; dd[nv][3] = 0.f;
    }
    int src1 = (lane & ~3) | (t >> 1);
    int src2 = src1 + 2;
    bool odd = (t & 1);
#pragma unroll
    for (int kt = 0; kt < 16; kt++) {
        float v00 = __shfl_sync(0xFFFFFFFFu, cc[kt][0], src1);
        float v01 = __shfl_sync(0xFFFFFFFFu, cc[kt][1], src1);
        float v02 = __shfl_sync(0xFFFFFFFFu, cc[kt][2], src1);
        float v03 = __shfl_sync(0xFFFFFFFFu, cc[kt][3], src1);
        float v10 = __shfl_sync(0xFFFFFFFFu, cc[kt][0], src2);
        float v11 = __shfl_sync(0xFFFFFFFFu, cc[kt][1], src2);
        float v12 = __shfl_sync(0xFFFFFFFFu, cc[kt][2], src2);
        float v13 = __shfl_sync(0xFFFFFFFFu, cc[kt][3], src2);
        uint32_t a0 = __float_as_uint(odd ? v01 : v00);
        uint32_t a1 = __float_as_uint(odd ? v03 : v02);
        uint32_t a2 = __float_as_uint(odd ? v11 : v10);
        uint32_t a3 = __float_as_uint(odd ? v13 : v12);
#pragma unroll
        for (int nv = 0; nv < 4; nv++) {
            uint32_t bh0 = __float_as_uint(sm[OF_V + (kt * 8 + t) * 40 + nv * 8 + g]);
            uint32_t bh1 = __float_as_uint(sm[OF_V + (kt * 8 + t + 4) * 40 + nv * 8 + g]);
            MMA_TF32(dd[nv], a0, a1, a2, a3, bh0, bh1);
        }
    }

    // write results
    unsigned qA = ((unsigned*)(sm + OF_QIX))[rA];
    unsigned qB = ((unsigned*)(sm + OF_QIX))[rB];
    if (t == 0) {
        g_dscr[(size_t)seg * NPTS + qA] = denA;
        g_dscr[(size_t)seg * NPTS + qB] = denB;
    }
    float* odA = g_oscr + ((size_t)seg * NPTS + qA) * DH;
    float* odB = g_oscr + ((size_t)seg * NPTS + qB) * DH;
#pragma unroll
    for (int nv = 0; nv < 4; nv++) {
        int col = nv * 8 + 2 * t;
        *(float2*)(odA + col) = make_float2(dd[nv][0], dd[nv][1]);
        *(float2*)(odB + col) = make_float2(dd[nv][2], dd[nv][3]);
    }
}

// ---------------- epilogue: combine + out-proj + residual + LN2 + FF + residual ----------
__global__ void __launch_bounds__(128) k_epilogue(
    const float* __restrict__ x, const float* __restrict__ ow,
    const float* __restrict__ ob, const float* __restrict__ n2w,
    const float* __restrict__ n2b, const float* __restrict__ f1w,
    const float* __restrict__ f1b, const float* __restrict__ f2w,
    const float* __restrict__ f2b, float* __restrict__ out) {
    __shared__ float ws[256 * 32];
    __shared__ float f1sT[32 * 32];
    __shared__ float f2s[32 * 32];
    __shared__ float cs[32 * 5];
    int tid = threadIdx.x;
    for (int i = tid; i < 8192; i += 128) ws[i] = ow[i];
    for (int i = tid; i < 1024; i += 128) {
        f1sT[(i & 31) * 32 + (i >> 5)] = f1w[i];
        f2s[i] = f2w[i];
    }
    if (tid < 32) {
        cs[tid] = ob[tid]; cs[32 + tid] = n2w[tid]; cs[64 + tid] = n2b[tid];
        cs[96 + tid] = f1b[tid]; cs[128 + tid] = f2b[tid];
    }
    __syncthreads();
    int n = blockIdx.x * 128 + tid;

    ull acc2[16];
#pragma unroll
    for (int p = 0; p < 16; p++) acc2[p] = pk2(cs[2 * p], cs[2 * p + 1]);

#pragma unroll 1
    for (int h = 0; h < 8; h++) {
        float den = g_dscr[(size_t)h * NPTS + n] +
                    g_dscr[(size_t)(8 + h) * NPTS + n] +
                    g_dscr[(size_t)(16 + h) * NPTS + n] + 3e-20f;
        float inv = 1.0f / den;
        const float4* oa = (const float4*)(g_oscr + ((size_t)h * NPTS + n) * DH);
        const float4* obp = (const float4*)(g_oscr + ((size_t)(8 + h) * NPTS + n) * DH);
        const float4* oc = (const float4*)(g_oscr + ((size_t)(16 + h) * NPTS + n) * DH);
#pragma unroll
        for (int p4 = 0; p4 < 8; p4++) {
            float4 a4 = oa[p4], b4 = obp[p4], c4 = oc[p4];
            float av[4];
            av[0] = (a4.x + b4.x + c4.x) * inv;
            av[1] = (a4.y + b4.y + c4.y) * inv;
            av[2] = (a4.z + b4.z + c4.z) * inv;
            av[3] = (a4.w + b4.w + c4.w) * inv;
            int j0 = h * 32 + p4 * 4;
#pragma unroll
            for (int u = 0; u < 4; u++) {
                ull ad = pk2(av[u], av[u]);
                const float4* wr2 = (const float4*)(ws + (j0 + u) * 32);
#pragma unroll
                for (int p = 0; p < 8; p++) {
                    float4 w4 = wr2[p];
                    acc2[2 * p] = f2fma(ad, lo2(w4), acc2[2 * p]);
                    acc2[2 * p + 1] = f2fma(ad, hi2(w4), acc2[2 * p + 1]);
                }
            }
        }
    }
    float acc[32];
#pragma unroll
    for (int p = 0; p < 16; p++) upk(acc2[p], acc[2 * p], acc[2 * p + 1]);

    float x2[32];
    const float4* xr = (const float4*)(x + (size_t)n * 32);
#pragma unroll
    for (int u = 0; u < 8; u++) {
        float4 xv = xr[u];
        x2[4 * u] = xv.x + acc[4 * u];
        x2[4 * u + 1] = xv.y + acc[4 * u + 1];
        x2[4 * u + 2] = xv.z + acc[4 * u + 2];
        x2[4 * u + 3] = xv.w + acc[4 * u + 3];
    }
    float mu = 0.f;
#pragma unroll
    for (int d = 0; d < 32; d++) mu += x2[d];
    mu *= (1.0f / 32.0f);
    float var = 0.f;
#pragma unroll
    for (int d = 0; d < 32; d++) { float dd = x2[d] - mu; var += dd * dd; }
    var *= (1.0f / 32.0f);
    float rs = rsqrtf(var + 1e-5f);
    float xn2[32];
#pragma unroll
    for (int d = 0; d < 32; d++)
        xn2[d] = (x2[d] - mu) * rs * cs[32 + d] + cs[64 + d];
    ull xp[16];
#pragma unroll
    for (int u = 0; u < 16; u++) xp[u] = pk2(xn2[2 * u], xn2[2 * u + 1]);
    float h1[32];
#pragma unroll 4
    for (int jj = 0; jj < 32; jj++) {
        const float4* fr = (const float4*)(f1sT + jj * 32);
        ull a0 = 0ull, a1 = 0ull;
#pragma unroll
        for (int u = 0; u < 8; u++) {
            float4 v4 = fr[u];
            a0 = f2fma(lo2(v4), xp[2 * u], a0);
            a1 = f2fma(hi2(v4), xp[2 * u + 1], a1);
        }
        float s0, s1;
        upk(f2add(a0, a1), s0, s1);
        float t2 = cs[96 + jj] + s0 + s1;
        h1[jj] = t2 / (1.0f + __expf(-t2));
    }
    ull o2[16];
#pragma unroll
    for (int p = 0; p < 16; p++) o2[p] = pk2(cs[128 + 2 * p], cs[128 + 2 * p + 1]);
#pragma unroll 4
    for (int jj = 0; jj < 32; jj++) {
        ull hd = pk2(h1[jj], h1[jj]);
        const float4* fr = (const float4*)(f2s + jj * 32);
#pragma unroll
        for (int p = 0; p < 8; p++) {
            float4 v4 = fr[p];
            o2[2 * p] = f2fma(hd, lo2(v4), o2[2 * p]);
            o2[2 * p + 1] = f2fma(hd, hi2(v4), o2[2 * p + 1]);
        }
    }
    float o[32];
#pragma unroll
    for (int p = 0; p < 16; p++) upk(o2[p], o[2 * p], o[2 * p + 1]);
    float4* orow = (float4*)(out + (size_t)n * 32);
#pragma unroll
    for (int u = 0; u < 8; u++)
        orow[u] = make_float4(x2[4 * u] + o[4 * u], x2[4 * u + 1] + o[4 * u + 1],
                              x2[4 * u + 2] + o[4 * u + 2], x2[4 * u + 3] + o[4 * u + 3]);
}

// ---------------- launcher ----------------
extern "C" void kernel_launch(void* const* d_in, const int* in_sizes, int n_in,
                              void* d_out, int out_size) {
    const float* x = (const float*)d_in[0];
    const float* coords = (const float*)d_in[1];
    const int* shifts = (const int*)d_in[2];
    const float* n1w = (const float*)d_in[3];
    const float* n1b = (const float*)d_in[4];
    const float* wq = (const float*)d_in[5];
    const float* wk = (const float*)d_in[6];
    const float* wv = (const float*)d_in[7];
    const float* wr = (const float*)d_in[8];
    const float* alpha = (const float*)d_in[9];
    const float* ow = (const float*)d_in[10];
    const float* ob = (const float*)d_in[11];
    const float* n2w = (const float*)d_in[12];
    const float* n2b = (const float*)d_in[13];
    const float* f1w = (const float*)d_in[14];
    const float* f1b = (const float*)d_in[15];
    const float* f2w = (const float*)d_in[16];
    const float* f2b = (const float*)d_in[17];
    float* out = (float*)d_out;

    cudaFuncSetAttribute(k_sort8k, cudaFuncAttributeMaxDynamicSharedMemorySize, 65536);
    cudaFuncSetAttribute(k_attn, cudaFuncAttributeMaxDynamicSharedMemorySize, SMEM_ATTN);

    k_ln_qkv<<<NPTS / 128, 768>>>(x, n1w, n1b, wq, wk, wv, wr, coords, alpha);

    const int TOT = 2 * CHN * NPTS;
    k_sort8k<<<TOT / 8192, 1024, 65536>>>(shifts);
    k_mergepath<<<TOT / 4096, 256>>>(8192, 0);    // keys  -> keys2 (16384 runs)
    k_mergepath<<<TOT / 4096, 256>>>(16384, 1);   // keys2 -> keys  (32768 runs)

    k_attn<<<dim3(NBK, CHN), 256, SMEM_ATTN>>>();
    k_epilogue<<<NPTS / 128, 128>>>(x, ow, ob, n2w, n2b, f1w, f1b, f2w, f2b, out);
}